// round 8
// baseline (speedup 1.0000x reference)
#include <cuda_runtime.h>
#include <cuda_fp16.h>
#include <math.h>
#include <stdint.h>

#define SEQ      4096
#define DMODEL   256
#define DINNER   512
#define DSTATE   64
#define NHEADS   8
#define HEADDIM  64
#define CONVDIM  640
#define DPROJ    1160
#define MTOT     32768          // 8 * 4096 rows (concat of both batch stacks)

// ---------------- scratch (static device globals; no allocations allowed) ----
__device__ float g_zx   [(size_t)MTOT * DPROJ];
__device__ float g_yraw [(size_t)MTOT * DINNER];
__device__ float g_sp   [(size_t)MTOT * DMODEL];
__device__ float g_u    [(size_t)MTOT * DMODEL];

// fp16 activations
__device__ __half g_xnh[(size_t)MTOT * DMODEL];
__device__ __half g_ynh[(size_t)MTOT * DINNER];
__device__ __half g_sph[(size_t)MTOT * DMODEL];
__device__ __half g_hmh[(size_t)MTOT * DMODEL];

// fp16 weights (in-proj keeps hi/lo split; others hi only)
__device__ __half g_Winh[DPROJ * DMODEL], g_Winl[DPROJ * DMODEL];
__device__ __half g_Wouth[DMODEL * DINNER];
__device__ __half g_w1h[DMODEL * DINNER];
__device__ __half g_w2h[DMODEL * DMODEL];

__device__ __forceinline__ float siluf(float x) {
    return x / (1.f + expf(-x));
}

// ---------------- merged weight convert --------------------------------------
__global__ void wcvt_kernel(const float* __restrict__ W_in, const float* __restrict__ W_out,
                            const float* __restrict__ w1,  const float* __restrict__ w2)
{
    int i = blockIdx.x * blockDim.x + threadIdx.x;
    if (i < DPROJ * DMODEL) {
        float v = W_in[i];
        __half h = __float2half(v);
        g_Winh[i] = h;
        g_Winl[i] = __float2half(v - __half2float(h));
    }
    if (i < DMODEL * DINNER) {
        g_Wouth[i] = __float2half(W_out[i]);
        g_w1h[i]   = __float2half(w1[i]);
    }
    if (i < DMODEL * DMODEL) {
        g_w2h[i] = __float2half(w2[i]);
    }
}

// ---------------- LayerNorm of concatenated input -> fp16 -------------------
__global__ void ln_s_kernel(const float* __restrict__ x0, const float* __restrict__ x1,
                            const float* __restrict__ w,  const float* __restrict__ bias)
{
    int m = blockIdx.x;
    int b = m >> 12;
    int t = m & 4095;
    const float* src = (b < 4) ? (x0 + ((size_t)(b * SEQ + t)) * DMODEL)
                               : (x1 + ((size_t)((b - 4) * SEQ + t)) * DMODEL);
    int n = threadIdx.x;
    float v = src[n];
    float s = v, s2 = v * v;
    #pragma unroll
    for (int o = 16; o; o >>= 1) {
        s  += __shfl_xor_sync(0xffffffffu, s,  o);
        s2 += __shfl_xor_sync(0xffffffffu, s2, o);
    }
    __shared__ float rs[8], rs2[8];
    int wid = n >> 5, lid = n & 31;
    if (lid == 0) { rs[wid] = s; rs2[wid] = s2; }
    __syncthreads();
    float ts = 0.f, ts2 = 0.f;
    #pragma unroll
    for (int i = 0; i < 8; i++) { ts += rs[i]; ts2 += rs2[i]; }
    float mu  = ts  * (1.f / 256.f);
    float var = ts2 * (1.f / 256.f) - mu * mu;
    float r = rsqrtf(var + 1e-5f);
    float o = (v - mu) * r * w[n] + bias[n];
    g_xnh[(size_t)m * DMODEL + n] = __float2half(o);
}

// ---------------- final LayerNorm: g_u -> d_out ------------------------------
__global__ void ln_t_kernel(const float* __restrict__ w, const float* __restrict__ bias,
                            float* __restrict__ out)
{
    int m = blockIdx.x;
    int n = threadIdx.x;
    float v = g_u[(size_t)m * DMODEL + n];
    float s = v, s2 = v * v;
    #pragma unroll
    for (int o = 16; o; o >>= 1) {
        s  += __shfl_xor_sync(0xffffffffu, s,  o);
        s2 += __shfl_xor_sync(0xffffffffu, s2, o);
    }
    __shared__ float rs[8], rs2[8];
    int wid = n >> 5, lid = n & 31;
    if (lid == 0) { rs[wid] = s; rs2[wid] = s2; }
    __syncthreads();
    float ts = 0.f, ts2 = 0.f;
    #pragma unroll
    for (int i = 0; i < 8; i++) { ts += rs[i]; ts2 += rs2[i]; }
    float mu  = ts  * (1.f / 256.f);
    float var = ts2 * (1.f / 256.f) - mu * mu;
    float r = rsqrtf(var + 1e-5f);
    out[(size_t)m * DMODEL + n] = (v - mu) * r * w[n] + bias[n];
}

// ====== fused selective scan: conv+SiLU + dt/dA + scan, deferred reduction ====
// grid = 128: blockIdx = b*16 + h*2 + ps; block = 256: tid = pl*8 + nq
#define SCHUNK 32
// smem float offsets
#define OF_RAWX 0                       // [35][32]
#define OF_RAWB 1120                    // [35][64]
#define OF_RAWC 3360                    // [35][64]
#define OF_SX   5600                    // [32][32]
#define OF_SB   6624                    // [32][64]
#define OF_SC   8672                    // [32][64]
#define OF_SY   10720                   // [32][32][8]
#define OF_SDT  18912                   // [32]
#define OF_SDA  18944                   // [32]
#define SCAN_SMEM_FLOATS 18976
#define SCAN_SMEM_BYTES  (SCAN_SMEM_FLOATS * 4)   // 75904

__global__ void __launch_bounds__(256) scan_kernel(
    const float* __restrict__ dt_bias, const float* __restrict__ A_log,
    const float* __restrict__ D_param,
    const float* __restrict__ conv_w,  const float* __restrict__ conv_b)
{
    extern __shared__ float sm[];
    float* rawx = sm + OF_RAWX;
    float* rawB = sm + OF_RAWB;
    float* rawC = sm + OF_RAWC;
    float* sx   = sm + OF_SX;
    float* sB   = sm + OF_SB;
    float* sC   = sm + OF_SC;
    float* sy   = sm + OF_SY;
    float* sdt  = sm + OF_SDT;
    float* sdA  = sm + OF_SDA;

    int blk = blockIdx.x;
    int ps  = blk & 1;
    int h   = (blk >> 1) & 7;
    int b   = blk >> 4;
    int tid = threadIdx.x;
    int pl  = tid >> 3;
    int nq  = tid & 7;
    int pofs = h * 64 + ps * 32;

    float Dh  = D_param[h];
    float eA  = expf(A_log[h]);
    float dtb = dt_bias[h];

    float hs[8];
    #pragma unroll
    for (int j = 0; j < 8; j++) hs[j] = 0.f;

    const float* zrow = g_zx + (size_t)(b * SEQ) * DPROJ;

    for (int c0 = 0; c0 < SEQ; c0 += SCHUNK) {
        // ---- load raw xBC rows [c0-3, c0+32) : 35 rows x 40 float4 ----
        for (int i = tid; i < 35 * 40; i += 256) {
            int r = i / 40, c4 = i % 40;
            int t = c0 - 3 + r;
            float4 v = make_float4(0.f, 0.f, 0.f, 0.f);
            if (t >= 0) {
                const float* rowp = zrow + (size_t)t * DPROJ;
                int col = (c4 < 8)  ? (512 + pofs + c4 * 4)
                        : (c4 < 24) ? (1024 + (c4 - 8) * 4)
                                    : (1088 + (c4 - 24) * 4);
                v = *(const float4*)(rowp + col);
            }
            float* dst = (c4 < 8)  ? (rawx + r * 32 + c4 * 4)
                       : (c4 < 24) ? (rawB + r * 64 + (c4 - 8) * 4)
                                   : (rawC + r * 64 + (c4 - 24) * 4);
            *(float4*)dst = v;
        }
        // ---- dt / dA for this chunk ----
        if (tid < SCHUNK) {
            float raw = zrow[(size_t)(c0 + tid) * DPROJ + (DPROJ - NHEADS) + h] + dtb;
            float dt = (raw > 20.f) ? raw : log1pf(expf(raw));
            sdt[tid] = dt;
            sdA[tid] = expf(-eA * dt);
        }
        __syncthreads();

        // ---- conv(k=4) + SiLU into sx/sB/sC ----
        for (int i = tid; i < 32 * 160; i += 256) {
            int t = i / 160, c = i % 160;
            const float* rp; int wch; float* dst; int wd;
            if (c < 32)      { rp = rawx + c;        wch = pofs + c;       dst = sx + t * 32 + c;        wd = 32; }
            else if (c < 96) { rp = rawB + (c - 32); wch = 512 + (c - 32); dst = sB + t * 64 + (c - 32); wd = 64; }
            else             { rp = rawC + (c - 96); wch = 576 + (c - 96); dst = sC + t * 64 + (c - 96); wd = 64; }
            float4 w4 = *(const float4*)(conv_w + wch * 4);
            float acc = conv_b[wch];
            acc = fmaf(rp[(t + 0) * wd], w4.x, acc);
            acc = fmaf(rp[(t + 1) * wd], w4.y, acc);
            acc = fmaf(rp[(t + 2) * wd], w4.z, acc);
            acc = fmaf(rp[(t + 3) * wd], w4.w, acc);
            *dst = siluf(acc);
        }
        __syncthreads();

        // ---- sequential scan: partials to smem, no shuffles ----
        #pragma unroll 4
        for (int t = 0; t < SCHUNK; t++) {
            float dAv = sdA[t];
            float xv  = sx[t * 32 + pl];
            float dtx = sdt[t] * xv;
            float4 B0 = *(const float4*)(sB + t * 64 + nq * 8);
            float4 B1 = *(const float4*)(sB + t * 64 + nq * 8 + 4);
            float4 C0 = *(const float4*)(sC + t * 64 + nq * 8);
            float4 C1 = *(const float4*)(sC + t * 64 + nq * 8 + 4);
            hs[0] = fmaf(dAv, hs[0], dtx * B0.x);
            hs[1] = fmaf(dAv, hs[1], dtx * B0.y);
            hs[2] = fmaf(dAv, hs[2], dtx * B0.z);
            hs[3] = fmaf(dAv, hs[3], dtx * B0.w);
            hs[4] = fmaf(dAv, hs[4], dtx * B1.x);
            hs[5] = fmaf(dAv, hs[5], dtx * B1.y);
            hs[6] = fmaf(dAv, hs[6], dtx * B1.z);
            hs[7] = fmaf(dAv, hs[7], dtx * B1.w);
            float p0 = fmaf(hs[1], C0.y, hs[0] * C0.x);
            float p1 = fmaf(hs[3], C0.w, hs[2] * C0.z);
            float p2 = fmaf(hs[5], C1.y, hs[4] * C1.x);
            float p3 = fmaf(hs[7], C1.w, hs[6] * C1.z);
            sy[t * 256 + pl * 8 + nq] = (p0 + p1) + (p2 + p3);
        }
        __syncthreads();

        // ---- reduce partials + D*x skip, write out ----
        #pragma unroll
        for (int k = 0; k < 4; k++) {
            int idx = tid + k * 256;          // 1024 outputs
            int t = idx >> 5, p = idx & 31;
            float4 a = *(float4*)(sy + t * 256 + p * 8);
            float4 c = *(float4*)(sy + t * 256 + p * 8 + 4);
            float ysum = ((a.x + a.y) + (a.z + a.w)) + ((c.x + c.y) + (c.z + c.w));
            g_yraw[(size_t)(b * SEQ + c0 + t) * DINNER + pofs + p] =
                fmaf(Dh, sx[t * 32 + p], ysum);
        }
        __syncthreads();
    }
}

// ---------------- gate with silu(z) + RMSNorm -> fp16 ------------------------
__global__ void gate_rms_kernel(const float* __restrict__ rms_w)
{
    int m = blockIdx.x;
    int tid = threadIdx.x;
    float yg[2];
    float s2 = 0.f;
    #pragma unroll
    for (int e = 0; e < 2; e++) {
        int i = tid + e * 256;
        float z = g_zx[(size_t)m * DPROJ + i];
        float y = g_yraw[(size_t)m * DINNER + i];
        float g = y * siluf(z);
        yg[e] = g;
        s2 += g * g;
    }
    #pragma unroll
    for (int o = 16; o; o >>= 1) s2 += __shfl_xor_sync(0xffffffffu, s2, o);
    __shared__ float rs[8];
    int wid = tid >> 5, lid = tid & 31;
    if (lid == 0) rs[wid] = s2;
    __syncthreads();
    float tot = 0.f;
    #pragma unroll
    for (int i = 0; i < 8; i++) tot += rs[i];
    float r = rsqrtf(tot * (1.f / 512.f) + 1e-5f);
    #pragma unroll
    for (int e = 0; e < 2; e++) {
        int i = tid + e * 256;
        g_ynh[(size_t)m * DINNER + i] = __float2half(yg[e] * r * rms_w[i]);
    }
}

// ======== pipelined fp16 mma.sync GEMM: C = A * (Bh [+ Bl])^T ================
__device__ __forceinline__ uint32_t smem_u32(const void* p) {
    uint32_t a;
    asm("{ .reg .u64 t; cvta.to.shared.u64 t, %1; cvt.u32.u64 %0, t; }" : "=r"(a) : "l"(p));
    return a;
}

#define CP16(dst, src, sz) \
    asm volatile("cp.async.cg.shared.global [%0], [%1], 16, %2;" \
                 :: "r"(dst), "l"(src), "r"(sz))
#define CP_COMMIT() asm volatile("cp.async.commit_group;" ::: "memory")
#define CP_WAIT1()  asm volatile("cp.async.wait_group 1;" ::: "memory")

#define LDSM4(d0, d1, d2, d3, a) \
    asm volatile("ldmatrix.sync.aligned.m8n8.x4.shared.b16 {%0,%1,%2,%3}, [%4];" \
                 : "=r"(d0), "=r"(d1), "=r"(d2), "=r"(d3) : "r"(a))

__device__ __forceinline__ void mma_fp16(float* d, const uint32_t* a, const uint32_t* b) {
    asm volatile(
        "mma.sync.aligned.m16n8k16.row.col.f32.f16.f16.f32 "
        "{%0,%1,%2,%3}, {%4,%5,%6,%7}, {%8,%9}, {%0,%1,%2,%3};"
        : "+f"(d[0]), "+f"(d[1]), "+f"(d[2]), "+f"(d[3])
        : "r"(a[0]), "r"(a[1]), "r"(a[2]), "r"(a[3]), "r"(b[0]), "r"(b[1]));
}

#define ROWB     80
#define MATB     (128 * ROWB)        // 10240
#define NSTAGE   3

template <int MODE, int NPROD>
__global__ void __launch_bounds__(256, 2) gemm_mma(
    const __half* __restrict__ Ah,
    const __half* __restrict__ Bh, const __half* __restrict__ Bl,
    float* __restrict__ C, int N, int K,
    const float* __restrict__ e0, const float* __restrict__ e1)
{
    constexpr int STAGEB = (1 + NPROD) * MATB;
    extern __shared__ char smem[];
    uint32_t sb = smem_u32(smem);
    int tid  = threadIdx.x;
    int wid  = tid >> 5, lane = tid & 31;
    int wm   = wid >> 2, wn = wid & 3;
    int bm   = blockIdx.y * 128;
    int bn   = blockIdx.x * 128;
    int gq   = lane >> 2;
    int tq   = lane & 3;

    float acc[4][4][4];
    #pragma unroll
    for (int mi = 0; mi < 4; mi++)
        #pragma unroll
        for (int ni = 0; ni < 4; ni++)
            #pragma unroll
            for (int r = 0; r < 4; r++) acc[mi][ni][r] = 0.f;

    auto fill_stage = [&](int s, int k0) {
        uint32_t st = sb + s * STAGEB;
        #pragma unroll
        for (int j = 0; j < 2; j++) {
            int idx = j * 256 + tid;
            int row = idx >> 2, seg = idx & 3;
            const __half* sh;
            if (MODE == 2) {
                int gr = bm + row;
                int vv = gr >> 14;
                int base = gr & 16383;
                int kk = k0 + seg * 8;
                int usef1 = ((kk >= 256) ? 1 : 0) ^ vv;
                sh = g_sph + ((size_t)(base + (usef1 ? 16384 : 0))) * DMODEL + (kk & 255);
            } else {
                sh = Ah + (size_t)(bm + row) * K + k0 + seg * 8;
            }
            CP16(st + row * ROWB + seg * 16, sh, 16);
        }
        #pragma unroll
        for (int j = 0; j < 2; j++) {
            int idx = j * 256 + tid;
            int row = idx >> 2, seg = idx & 3;
            int gn = bn + row;
            int sz = (gn < N) ? 16 : 0;
            size_t off = (size_t)gn * K + k0 + seg * 8;
            uint32_t d = st + MATB + row * ROWB + seg * 16;
            CP16(d, Bh + off, sz);
            if (NPROD == 2) CP16(d + MATB, Bl + off, sz);
        }
    };

    auto compute_stage = [&](int s) {
        uint32_t stA = sb + s * STAGEB;
        uint32_t stB = stA + MATB;
        int q = lane >> 3, r = lane & 7;
        #pragma unroll
        for (int ks = 0; ks < 2; ks++) {
            int kc = ks * 16;
            uint32_t ah[4][4];
            #pragma unroll
            for (int mi = 0; mi < 4; mi++) {
                int arow = wm * 64 + mi * 16 + (q & 1) * 8 + r;
                int acol = kc + (q >> 1) * 8;
                LDSM4(ah[mi][0], ah[mi][1], ah[mi][2], ah[mi][3],
                      stA + arow * ROWB + acol * 2);
            }
            uint32_t bh[4][2], bl[4][2];
            #pragma unroll
            for (int nb = 0; nb < 2; nb++) {
                int brow = wn * 32 + nb * 16 + (q >> 1) * 8 + r;
                int bcol = kc + (q & 1) * 8;
                uint32_t bd = stB + brow * ROWB + bcol * 2;
                LDSM4(bh[2 * nb][0], bh[2 * nb][1], bh[2 * nb + 1][0], bh[2 * nb + 1][1], bd);
                if (NPROD == 2)
                    LDSM4(bl[2 * nb][0], bl[2 * nb][1], bl[2 * nb + 1][0], bl[2 * nb + 1][1], bd + MATB);
            }
            #pragma unroll
            for (int mi = 0; mi < 4; mi++)
                #pragma unroll
                for (int ni = 0; ni < 4; ni++) {
                    mma_fp16(acc[mi][ni], ah[mi], bh[ni]);
                    if (NPROD == 2) mma_fp16(acc[mi][ni], ah[mi], bl[ni]);
                }
        }
    };

    int nk = K >> 5;
    fill_stage(0, 0);  CP_COMMIT();
    fill_stage(1, 32); CP_COMMIT();

    for (int i = 0; i < nk; i++) {
        CP_WAIT1();
        __syncthreads();
        if (i + 2 < nk) fill_stage((i + 2) % NSTAGE, (i + 2) << 5);
        CP_COMMIT();
        compute_stage(i % NSTAGE);
    }

    // epilogue
    #pragma unroll
    for (int mi = 0; mi < 4; mi++) {
        int gr0 = bm + wm * 64 + mi * 16 + gq;
        int gr1 = gr0 + 8;
        const float *res0 = nullptr, *res1 = nullptr;
        if (MODE == 1) {
            int b0i = gr0 >> 12, t0 = gr0 & 4095;
            int b1i = gr1 >> 12, t1 = gr1 & 4095;
            res0 = (b0i < 4) ? (e0 + ((size_t)(b0i * SEQ + t0)) * DMODEL)
                             : (e1 + ((size_t)((b0i - 4) * SEQ + t0)) * DMODEL);
            res1 = (b1i < 4) ? (e0 + ((size_t)(b1i * SEQ + t1)) * DMODEL)
                             : (e1 + ((size_t)((b1i - 4) * SEQ + t1)) * DMODEL);
        }
        #pragma unroll
        for (int ni = 0; ni < 4; ni++) {
            int gc = bn + wn * 32 + ni * 8 + 2 * tq;
            if (gc >= N) continue;
            float v0 = acc[mi][ni][0], v1 = acc[mi][ni][1];
            float v2 = acc[mi][ni][2], v3 = acc[mi][ni][3];
            if (MODE == 0) {
                *(float2*)(C + (size_t)gr0 * N + gc) = make_float2(v0, v1);
                *(float2*)(C + (size_t)gr1 * N + gc) = make_float2(v2, v3);
            }
            if (MODE == 1) {
                v0 += res0[gc]; v1 += res0[gc + 1];
                v2 += res1[gc]; v3 += res1[gc + 1];
                *(float2*)(C + (size_t)gr0 * N + gc) = make_float2(v0, v1);
                *(float2*)(C + (size_t)gr1 * N + gc) = make_float2(v2, v3);
                *(__half2*)(g_sph + (size_t)gr0 * DMODEL + gc) = __floats2half2_rn(v0, v1);
                *(__half2*)(g_sph + (size_t)gr1 * DMODEL + gc) = __floats2half2_rn(v2, v3);
            }
            if (MODE == 2) {
                float bx = e0[gc], by = e0[gc + 1];
                v0 = siluf(v0 + bx); v1 = siluf(v1 + by);
                v2 = siluf(v2 + bx); v3 = siluf(v3 + by);
                *(__half2*)(g_hmh + (size_t)gr0 * DMODEL + gc) = __floats2half2_rn(v0, v1);
                *(__half2*)(g_hmh + (size_t)gr1 * DMODEL + gc) = __floats2half2_rn(v2, v3);
            }
            if (MODE == 3) {
                float bx = e0[gc], by = e0[gc + 1];
                const float* s0 = g_sp + (size_t)gr0 * DMODEL + gc;
                const float* s1 = g_sp + (size_t)gr1 * DMODEL + gc;
                v0 += bx + s0[0]; v1 += by + s0[1];
                v2 += bx + s1[0]; v3 += by + s1[1];
                *(float2*)(C + (size_t)gr0 * N + gc) = make_float2(v0, v1);
                *(float2*)(C + (size_t)gr1 * N + gc) = make_float2(v2, v3);
            }
        }
    }
}

// ---------------- launch ------------------------------------------------------
extern "C" void kernel_launch(void* const* d_in, const int* in_sizes, int n_in,
                              void* d_out, int out_size)
{
    const float* x0      = (const float*)d_in[0];
    const float* x1      = (const float*)d_in[1];
    const float* nsw     = (const float*)d_in[2];
    const float* nsb     = (const float*)d_in[3];
    const float* W_in    = (const float*)d_in[4];
    const float* conv_w  = (const float*)d_in[5];
    const float* conv_b  = (const float*)d_in[6];
    const float* dt_bias = (const float*)d_in[7];
    const float* A_log   = (const float*)d_in[8];
    const float* Dp      = (const float*)d_in[9];
    const float* rms_w   = (const float*)d_in[10];
    const float* W_out   = (const float*)d_in[11];
    const float* w1      = (const float*)d_in[12];
    const float* b1      = (const float*)d_in[13];
    const float* w2      = (const float*)d_in[14];
    const float* b2      = (const float*)d_in[15];
    const float* ntw     = (const float*)d_in[16];
    const float* ntb     = (const float*)d_in[17];
    float* out = (float*)d_out;

    float *p_zx, *p_sp, *p_u;
    cudaGetSymbolAddress((void**)&p_zx, g_zx);
    cudaGetSymbolAddress((void**)&p_sp, g_sp);
    cudaGetSymbolAddress((void**)&p_u,  g_u);
    __half *p_xnh, *p_ynh, *p_hmh;
    __half *p_Winh, *p_Winl, *p_Wouth, *p_w1h, *p_w2h;
    cudaGetSymbolAddress((void**)&p_xnh, g_xnh);
    cudaGetSymbolAddress((void**)&p_ynh, g_ynh);
    cudaGetSymbolAddress((void**)&p_hmh, g_hmh);
    cudaGetSymbolAddress((void**)&p_Winh,  g_Winh);
    cudaGetSymbolAddress((void**)&p_Winl,  g_Winl);
    cudaGetSymbolAddress((void**)&p_Wouth, g_Wouth);
    cudaGetSymbolAddress((void**)&p_w1h,   g_w1h);
    cudaGetSymbolAddress((void**)&p_w2h,   g_w2h);

    const int SM2 = NSTAGE * 3 * MATB;   // 92160 (NPROD=2)
    const int SM1 = NSTAGE * 2 * MATB;   // 61440 (NPROD=1)
    cudaFuncSetAttribute((const void*)gemm_mma<0, 2>, cudaFuncAttributeMaxDynamicSharedMemorySize, SM2);
    cudaFuncSetAttribute((const void*)gemm_mma<1, 1>, cudaFuncAttributeMaxDynamicSharedMemorySize, SM1);
    cudaFuncSetAttribute((const void*)gemm_mma<2, 1>, cudaFuncAttributeMaxDynamicSharedMemorySize, SM1);
    cudaFuncSetAttribute((const void*)gemm_mma<3, 1>, cudaFuncAttributeMaxDynamicSharedMemorySize, SM1);
    cudaFuncSetAttribute((const void*)scan_kernel, cudaFuncAttributeMaxDynamicSharedMemorySize, SCAN_SMEM_BYTES);

    // #1: merged weight convert
    wcvt_kernel<<<(DPROJ * DMODEL + 255) / 256, 256>>>(W_in, W_out, w1, w2);

    // #2: LayerNorm(concat(x0, x1)) -> fp16
    ln_s_kernel<<<MTOT, 256>>>(x0, x1, nsw, nsb);

    // #3: in-proj GEMM (2-product): zxbcdt = xn @ W_in^T   (32768 x 1160 x 256)
    gemm_mma<0, 2><<<dim3((DPROJ + 127) / 128, MTOT / 128), 256, SM2>>>(
        p_xnh, p_Winh, p_Winl, p_zx, DPROJ, DMODEL, nullptr, nullptr);

    // #4: fused conv + dt/dA + selective scan  (ncu captures this launch)
    scan_kernel<<<128, 256, SCAN_SMEM_BYTES>>>(dt_bias, A_log, Dp, conv_w, conv_b);

    // #5: gate + RMSNorm -> fp16
    gate_rms_kernel<<<MTOT, 256>>>(rms_w);

    // #6: out-proj GEMM (1-product) + residual -> g_sp/g_sph
    gemm_mma<1, 1><<<dim3(2, MTOT / 128), 256, SM1>>>(
        p_ynh, p_Wouth, nullptr, p_sp, DMODEL, DINNER, x0, x1);

    // #7: MLP layer 1 (1-product, cross-concat gather) + SiLU -> g_hmh
    gemm_mma<2, 1><<<dim3(2, MTOT / 128), 256, SM1>>>(
        nullptr, p_w1h, nullptr, nullptr, DMODEL, DINNER, b1, nullptr);

    // #8: MLP layer 2 (1-product) + bias + g_sp residual -> g_u
    gemm_mma<3, 1><<<dim3(2, MTOT / 128), 256, SM1>>>(
        p_hmh, p_w2h, nullptr, p_u, DMODEL, DMODEL, b2, nullptr);

    // #9: final LayerNorm -> d_out
    ln_t_kernel<<<MTOT, 256>>>(ntw, ntb, out);

    (void)in_sizes; (void)n_in; (void)out_size;
}

// round 9
// speedup vs baseline: 1.4325x; 1.4325x over previous
#include <cuda_runtime.h>
#include <cuda_fp16.h>
#include <math.h>
#include <stdint.h>

#define SEQ      4096
#define DMODEL   256
#define DINNER   512
#define DSTATE   64
#define NHEADS   8
#define HEADDIM  64
#define CONVDIM  640
#define DPROJ    1160
#define MTOT     32768          // 8 * 4096 rows (concat of both batch stacks)
#define NSEG     16
#define SEGLEN   256            // SEQ / NSEG

// ---------------- scratch (static device globals; no allocations allowed) ----
__device__ float g_zx   [(size_t)MTOT * DPROJ];
__device__ float g_xconv[(size_t)MTOT * CONVDIM];
__device__ float g_yraw [(size_t)MTOT * DINNER];
__device__ float g_sp   [(size_t)MTOT * DMODEL];
__device__ float g_u    [(size_t)MTOT * DMODEL];
__device__ float g_cda  [(size_t)MTOT * NHEADS];          // cumulative dA within segment
__device__ float g_hseg [(size_t)2048 * 2048];            // local end states per segment
__device__ float g_h0s  [(size_t)2048 * 2048];            // true start states per segment

// fp16 activations
__device__ __half g_xnh[(size_t)MTOT * DMODEL];
__device__ __half g_ynh[(size_t)MTOT * DINNER];
__device__ __half g_sph[(size_t)MTOT * DMODEL];
__device__ __half g_hmh[(size_t)MTOT * DMODEL];

// fp16 weights (in-proj keeps hi/lo split; others hi only)
__device__ __half g_Winh[DPROJ * DMODEL], g_Winl[DPROJ * DMODEL];
__device__ __half g_Wouth[DMODEL * DINNER];
__device__ __half g_w1h[DMODEL * DINNER];
__device__ __half g_w2h[DMODEL * DMODEL];

__device__ __forceinline__ float siluf(float x) {
    return x / (1.f + expf(-x));
}

// ---------------- merged weight convert --------------------------------------
__global__ void wcvt_kernel(const float* __restrict__ W_in, const float* __restrict__ W_out,
                            const float* __restrict__ w1,  const float* __restrict__ w2)
{
    int i = blockIdx.x * blockDim.x + threadIdx.x;
    if (i < DPROJ * DMODEL) {
        float v = W_in[i];
        __half h = __float2half(v);
        g_Winh[i] = h;
        g_Winl[i] = __float2half(v - __half2float(h));
    }
    if (i < DMODEL * DINNER) {
        g_Wouth[i] = __float2half(W_out[i]);
        g_w1h[i]   = __float2half(w1[i]);
    }
    if (i < DMODEL * DMODEL) {
        g_w2h[i] = __float2half(w2[i]);
    }
}

// ---------------- LayerNorm of concatenated input -> fp16 -------------------
__global__ void ln_s_kernel(const float* __restrict__ x0, const float* __restrict__ x1,
                            const float* __restrict__ w,  const float* __restrict__ bias)
{
    int m = blockIdx.x;
    int b = m >> 12;
    int t = m & 4095;
    const float* src = (b < 4) ? (x0 + ((size_t)(b * SEQ + t)) * DMODEL)
                               : (x1 + ((size_t)((b - 4) * SEQ + t)) * DMODEL);
    int n = threadIdx.x;
    float v = src[n];
    float s = v, s2 = v * v;
    #pragma unroll
    for (int o = 16; o; o >>= 1) {
        s  += __shfl_xor_sync(0xffffffffu, s,  o);
        s2 += __shfl_xor_sync(0xffffffffu, s2, o);
    }
    __shared__ float rs[8], rs2[8];
    int wid = n >> 5, lid = n & 31;
    if (lid == 0) { rs[wid] = s; rs2[wid] = s2; }
    __syncthreads();
    float ts = 0.f, ts2 = 0.f;
    #pragma unroll
    for (int i = 0; i < 8; i++) { ts += rs[i]; ts2 += rs2[i]; }
    float mu  = ts  * (1.f / 256.f);
    float var = ts2 * (1.f / 256.f) - mu * mu;
    float r = rsqrtf(var + 1e-5f);
    float o = (v - mu) * r * w[n] + bias[n];
    g_xnh[(size_t)m * DMODEL + n] = __float2half(o);
}

// ---------------- final LayerNorm: g_u -> d_out ------------------------------
__global__ void ln_t_kernel(const float* __restrict__ w, const float* __restrict__ bias,
                            float* __restrict__ out)
{
    int m = blockIdx.x;
    int n = threadIdx.x;
    float v = g_u[(size_t)m * DMODEL + n];
    float s = v, s2 = v * v;
    #pragma unroll
    for (int o = 16; o; o >>= 1) {
        s  += __shfl_xor_sync(0xffffffffu, s,  o);
        s2 += __shfl_xor_sync(0xffffffffu, s2, o);
    }
    __shared__ float rs[8], rs2[8];
    int wid = n >> 5, lid = n & 31;
    if (lid == 0) { rs[wid] = s; rs2[wid] = s2; }
    __syncthreads();
    float ts = 0.f, ts2 = 0.f;
    #pragma unroll
    for (int i = 0; i < 8; i++) { ts += rs[i]; ts2 += rs2[i]; }
    float mu  = ts  * (1.f / 256.f);
    float var = ts2 * (1.f / 256.f) - mu * mu;
    float r = rsqrtf(var + 1e-5f);
    out[(size_t)m * DMODEL + n] = (v - mu) * r * w[n] + bias[n];
}

// ---------------- depthwise conv (k=4) + SiLU, 4 timesteps/thread -----------
__global__ void conv_kernel(const float* __restrict__ conv_w, const float* __restrict__ conv_b)
{
    int idx = blockIdx.x * blockDim.x + threadIdx.x;
    if (idx >= (MTOT / 4) * CONVDIM) return;
    int c  = idx % CONVDIM;
    int m4 = idx / CONVDIM;
    int b  = m4 >> 10;
    int t0 = (m4 & 1023) << 2;
    const float* base = g_zx + (size_t)(b * SEQ) * DPROJ + DINNER + c;
    float4 w4 = *(const float4*)(conv_w + c * 4);
    float bia = conv_b[c];
    float v[7];
    #pragma unroll
    for (int j = 0; j < 7; j++) {
        int tt = t0 - 3 + j;
        v[j] = (tt >= 0) ? base[(size_t)tt * DPROJ] : 0.f;
    }
    size_t obase = (size_t)(b * SEQ + t0) * CONVDIM + c;
    #pragma unroll
    for (int i = 0; i < 4; i++) {
        float acc = bia;
        acc = fmaf(v[i + 0], w4.x, acc);
        acc = fmaf(v[i + 1], w4.y, acc);
        acc = fmaf(v[i + 2], w4.z, acc);
        acc = fmaf(v[i + 3], w4.w, acc);
        g_xconv[obase + (size_t)i * CONVDIM] = siluf(acc);
    }
}

// ========== Pass A: segmented local scan (h0 = 0) ============================
// grid = 2048: blk = b*256 + h*32 + ps*16 + seg; block = 256: tid = pl*8 + nq
__global__ void __launch_bounds__(256) scan_seg_kernel(
    const float* __restrict__ dt_bias, const float* __restrict__ A_log,
    const float* __restrict__ D_param)
{
    int blk = blockIdx.x;
    int seg = blk & 15;
    int ps  = (blk >> 4) & 1;
    int h   = (blk >> 5) & 7;
    int b   = blk >> 8;
    int tid = threadIdx.x;
    int pl  = tid >> 3;
    int nq  = tid & 7;

    __shared__ __align__(16) float sx[64][32];
    __shared__ __align__(16) float sB[64][64];
    __shared__ __align__(16) float sC[64][64];
    __shared__ float sdt[64];
    __shared__ float sdA[64];

    float hs[8];
    #pragma unroll
    for (int j = 0; j < 8; j++) hs[j] = 0.f;
    float cum = 1.f;

    float Dh  = D_param[h];
    float eA  = expf(A_log[h]);
    float dtb = dt_bias[h];
    const float* xbase = g_xconv + (size_t)b * SEQ * CONVDIM;
    int pofs = h * 64 + ps * 32;
    int tseg = seg * SEGLEN;

    for (int c0 = tseg; c0 < tseg + SEGLEN; c0 += 64) {
        for (int i = tid; i < 64 * 32; i += 256) {
            int t = i >> 5, p = i & 31;
            sx[t][p] = xbase[(size_t)(c0 + t) * CONVDIM + pofs + p];
        }
        for (int i = tid; i < 64 * 64; i += 256) {
            int t = i >> 6, n = i & 63;
            sB[t][n] = xbase[(size_t)(c0 + t) * CONVDIM + 512 + n];
            sC[t][n] = xbase[(size_t)(c0 + t) * CONVDIM + 576 + n];
        }
        if (tid < 64) {
            float raw = g_zx[(size_t)(b * SEQ + c0 + tid) * DPROJ + (DPROJ - NHEADS) + h] + dtb;
            float dt = (raw > 20.f) ? raw : log1pf(expf(raw));
            sdt[tid] = dt;
            sdA[tid] = expf(-eA * dt);
        }
        __syncthreads();

        #pragma unroll 2
        for (int t = 0; t < 64; t++) {
            float dAv = sdA[t];
            float xv  = sx[t][pl];
            float dtx = sdt[t] * xv;
            float4 B0 = *(const float4*)&sB[t][nq * 8];
            float4 B1 = *(const float4*)&sB[t][nq * 8 + 4];
            float4 C0 = *(const float4*)&sC[t][nq * 8];
            float4 C1 = *(const float4*)&sC[t][nq * 8 + 4];
            hs[0] = fmaf(dAv, hs[0], dtx * B0.x);
            hs[1] = fmaf(dAv, hs[1], dtx * B0.y);
            hs[2] = fmaf(dAv, hs[2], dtx * B0.z);
            hs[3] = fmaf(dAv, hs[3], dtx * B0.w);
            hs[4] = fmaf(dAv, hs[4], dtx * B1.x);
            hs[5] = fmaf(dAv, hs[5], dtx * B1.y);
            hs[6] = fmaf(dAv, hs[6], dtx * B1.z);
            hs[7] = fmaf(dAv, hs[7], dtx * B1.w);
            float p0 = fmaf(hs[1], C0.y, hs[0] * C0.x);
            float p1 = fmaf(hs[3], C0.w, hs[2] * C0.z);
            float p2 = fmaf(hs[5], C1.y, hs[4] * C1.x);
            float p3 = fmaf(hs[7], C1.w, hs[6] * C1.z);
            float yp = (p0 + p1) + (p2 + p3);
            yp += __shfl_xor_sync(0xffffffffu, yp, 1);
            yp += __shfl_xor_sync(0xffffffffu, yp, 2);
            yp += __shfl_xor_sync(0xffffffffu, yp, 4);
            cum *= dAv;
            if (nq == 0) {
                g_yraw[(size_t)(b * SEQ + c0 + t) * DINNER + pofs + pl] = fmaf(Dh, xv, yp);
            }
            if (tid == 0) {
                g_cda[(size_t)(b * SEQ + c0 + t) * NHEADS + h] = cum;
            }
        }
        __syncthreads();
    }

    // local end state out
    size_t base = (size_t)blk * 2048 + tid * 8;
    #pragma unroll
    for (int j = 0; j < 8; j++) g_hseg[base + j] = hs[j];
}

// ========== Pass B: sequential combine across segments =======================
// grid = 128: blk = b*16 + h*2 + ps
__global__ void __launch_bounds__(256) combine_kernel()
{
    int blk = blockIdx.x;
    int tid = threadIdx.x;
    int h = (blk >> 1) & 7;
    int b = blk >> 4;
    float hstart[8];
    #pragma unroll
    for (int j = 0; j < 8; j++) hstart[j] = 0.f;
    for (int s = 0; s < NSEG; s++) {
        size_t base = ((size_t)(blk * NSEG + s)) * 2048 + tid * 8;
        #pragma unroll
        for (int j = 0; j < 8; j++) g_h0s[base + j] = hstart[j];
        float P = g_cda[(size_t)(b * SEQ + s * SEGLEN + SEGLEN - 1) * NHEADS + h];
        #pragma unroll
        for (int j = 0; j < 8; j++)
            hstart[j] = fmaf(P, hstart[j], g_hseg[base + j]);
    }
}

// ========== Pass C: correction y += cumdA * (C . h0) =========================
// grid = 2048 (same decode as pass A); seg 0 exits
__global__ void __launch_bounds__(256) correct_kernel()
{
    int blk = blockIdx.x;
    int seg = blk & 15;
    if (seg == 0) return;
    int ps  = (blk >> 4) & 1;
    int h   = (blk >> 5) & 7;
    int b   = blk >> 8;
    int tid = threadIdx.x;
    int pl  = tid >> 3;
    int nq  = tid & 7;

    __shared__ float sh0[2048];
    __shared__ float scd[256];
    for (int i = tid; i < 2048; i += 256) sh0[i] = g_h0s[(size_t)blk * 2048 + i];
    scd[tid] = g_cda[(size_t)(b * SEQ + seg * SEGLEN + tid) * NHEADS + h];
    __syncthreads();

    int pofs = h * 64 + ps * 32;
    const float* Cb = g_xconv + ((size_t)(b * SEQ + seg * SEGLEN)) * CONVDIM + 576;
    const float* h0 = sh0 + pl * 64 + nq * 8;
    float h00 = h0[0], h01 = h0[1], h02 = h0[2], h03 = h0[3];
    float h04 = h0[4], h05 = h0[5], h06 = h0[6], h07 = h0[7];

    #pragma unroll 4
    for (int t = 0; t < SEGLEN; t++) {
        const float* cp = Cb + (size_t)t * CONVDIM + nq * 8;
        float4 C0 = *(const float4*)cp;
        float4 C1 = *(const float4*)(cp + 4);
        float p0 = fmaf(C0.y, h01, C0.x * h00);
        float p1 = fmaf(C0.w, h03, C0.z * h02);
        float p2 = fmaf(C1.y, h05, C1.x * h04);
        float p3 = fmaf(C1.w, h07, C1.z * h06);
        float p = (p0 + p1) + (p2 + p3);
        p += __shfl_xor_sync(0xffffffffu, p, 1);
        p += __shfl_xor_sync(0xffffffffu, p, 2);
        p += __shfl_xor_sync(0xffffffffu, p, 4);
        if (nq == 0) {
            size_t yi = (size_t)(b * SEQ + seg * SEGLEN + t) * DINNER + pofs + pl;
            g_yraw[yi] += scd[t] * p;
        }
    }
}

// ---------------- gate with silu(z) + RMSNorm -> fp16 ------------------------
__global__ void gate_rms_kernel(const float* __restrict__ rms_w)
{
    int m = blockIdx.x;
    int tid = threadIdx.x;
    float yg[2];
    float s2 = 0.f;
    #pragma unroll
    for (int e = 0; e < 2; e++) {
        int i = tid + e * 256;
        float z = g_zx[(size_t)m * DPROJ + i];
        float y = g_yraw[(size_t)m * DINNER + i];
        float g = y * siluf(z);
        yg[e] = g;
        s2 += g * g;
    }
    #pragma unroll
    for (int o = 16; o; o >>= 1) s2 += __shfl_xor_sync(0xffffffffu, s2, o);
    __shared__ float rs[8];
    int wid = tid >> 5, lid = tid & 31;
    if (lid == 0) rs[wid] = s2;
    __syncthreads();
    float tot = 0.f;
    #pragma unroll
    for (int i = 0; i < 8; i++) tot += rs[i];
    float r = rsqrtf(tot * (1.f / 512.f) + 1e-5f);
    #pragma unroll
    for (int e = 0; e < 2; e++) {
        int i = tid + e * 256;
        g_ynh[(size_t)m * DINNER + i] = __float2half(yg[e] * r * rms_w[i]);
    }
}

// ======== pipelined fp16 mma.sync GEMM: C = A * (Bh [+ Bl])^T ================
__device__ __forceinline__ uint32_t smem_u32(const void* p) {
    uint32_t a;
    asm("{ .reg .u64 t; cvta.to.shared.u64 t, %1; cvt.u32.u64 %0, t; }" : "=r"(a) : "l"(p));
    return a;
}

#define CP16(dst, src, sz) \
    asm volatile("cp.async.cg.shared.global [%0], [%1], 16, %2;" \
                 :: "r"(dst), "l"(src), "r"(sz))
#define CP_COMMIT() asm volatile("cp.async.commit_group;" ::: "memory")
#define CP_WAIT1()  asm volatile("cp.async.wait_group 1;" ::: "memory")

#define LDSM4(d0, d1, d2, d3, a) \
    asm volatile("ldmatrix.sync.aligned.m8n8.x4.shared.b16 {%0,%1,%2,%3}, [%4];" \
                 : "=r"(d0), "=r"(d1), "=r"(d2), "=r"(d3) : "r"(a))

__device__ __forceinline__ void mma_fp16(float* d, const uint32_t* a, const uint32_t* b) {
    asm volatile(
        "mma.sync.aligned.m16n8k16.row.col.f32.f16.f16.f32 "
        "{%0,%1,%2,%3}, {%4,%5,%6,%7}, {%8,%9}, {%0,%1,%2,%3};"
        : "+f"(d[0]), "+f"(d[1]), "+f"(d[2]), "+f"(d[3])
        : "r"(a[0]), "r"(a[1]), "r"(a[2]), "r"(a[3]), "r"(b[0]), "r"(b[1]));
}

#define ROWB     80
#define MATB     (128 * ROWB)        // 10240
#define NSTAGE   3

template <int MODE, int NPROD>
__global__ void __launch_bounds__(256, 2) gemm_mma(
    const __half* __restrict__ Ah,
    const __half* __restrict__ Bh, const __half* __restrict__ Bl,
    float* __restrict__ C, int N, int K,
    const float* __restrict__ e0, const float* __restrict__ e1)
{
    constexpr int STAGEB = (1 + NPROD) * MATB;
    extern __shared__ char smem[];
    uint32_t sb = smem_u32(smem);
    int tid  = threadIdx.x;
    int wid  = tid >> 5, lane = tid & 31;
    int wm   = wid >> 2, wn = wid & 3;
    int bm   = blockIdx.y * 128;
    int bn   = blockIdx.x * 128;
    int gq   = lane >> 2;
    int tq   = lane & 3;

    float acc[4][4][4];
    #pragma unroll
    for (int mi = 0; mi < 4; mi++)
        #pragma unroll
        for (int ni = 0; ni < 4; ni++)
            #pragma unroll
            for (int r = 0; r < 4; r++) acc[mi][ni][r] = 0.f;

    auto fill_stage = [&](int s, int k0) {
        uint32_t st = sb + s * STAGEB;
        #pragma unroll
        for (int j = 0; j < 2; j++) {
            int idx = j * 256 + tid;
            int row = idx >> 2, seg = idx & 3;
            const __half* sh;
            if (MODE == 2) {
                int gr = bm + row;
                int vv = gr >> 14;
                int base = gr & 16383;
                int kk = k0 + seg * 8;
                int usef1 = ((kk >= 256) ? 1 : 0) ^ vv;
                sh = g_sph + ((size_t)(base + (usef1 ? 16384 : 0))) * DMODEL + (kk & 255);
            } else {
                sh = Ah + (size_t)(bm + row) * K + k0 + seg * 8;
            }
            CP16(st + row * ROWB + seg * 16, sh, 16);
        }
        #pragma unroll
        for (int j = 0; j < 2; j++) {
            int idx = j * 256 + tid;
            int row = idx >> 2, seg = idx & 3;
            int gn = bn + row;
            int sz = (gn < N) ? 16 : 0;
            size_t off = (size_t)gn * K + k0 + seg * 8;
            uint32_t d = st + MATB + row * ROWB + seg * 16;
            CP16(d, Bh + off, sz);
            if (NPROD == 2) CP16(d + MATB, Bl + off, sz);
        }
    };

    auto compute_stage = [&](int s) {
        uint32_t stA = sb + s * STAGEB;
        uint32_t stB = stA + MATB;
        int q = lane >> 3, r = lane & 7;
        #pragma unroll
        for (int ks = 0; ks < 2; ks++) {
            int kc = ks * 16;
            uint32_t ah[4][4];
            #pragma unroll
            for (int mi = 0; mi < 4; mi++) {
                int arow = wm * 64 + mi * 16 + (q & 1) * 8 + r;
                int acol = kc + (q >> 1) * 8;
                LDSM4(ah[mi][0], ah[mi][1], ah[mi][2], ah[mi][3],
                      stA + arow * ROWB + acol * 2);
            }
            uint32_t bh[4][2], bl[4][2];
            #pragma unroll
            for (int nb = 0; nb < 2; nb++) {
                int brow = wn * 32 + nb * 16 + (q >> 1) * 8 + r;
                int bcol = kc + (q & 1) * 8;
                uint32_t bd = stB + brow * ROWB + bcol * 2;
                LDSM4(bh[2 * nb][0], bh[2 * nb][1], bh[2 * nb + 1][0], bh[2 * nb + 1][1], bd);
                if (NPROD == 2)
                    LDSM4(bl[2 * nb][0], bl[2 * nb][1], bl[2 * nb + 1][0], bl[2 * nb + 1][1], bd + MATB);
            }
            #pragma unroll
            for (int mi = 0; mi < 4; mi++)
                #pragma unroll
                for (int ni = 0; ni < 4; ni++) {
                    mma_fp16(acc[mi][ni], ah[mi], bh[ni]);
                    if (NPROD == 2) mma_fp16(acc[mi][ni], ah[mi], bl[ni]);
                }
        }
    };

    int nk = K >> 5;
    fill_stage(0, 0);  CP_COMMIT();
    fill_stage(1, 32); CP_COMMIT();

    for (int i = 0; i < nk; i++) {
        CP_WAIT1();
        __syncthreads();
        if (i + 2 < nk) fill_stage((i + 2) % NSTAGE, (i + 2) << 5);
        CP_COMMIT();
        compute_stage(i % NSTAGE);
    }

    // epilogue
    #pragma unroll
    for (int mi = 0; mi < 4; mi++) {
        int gr0 = bm + wm * 64 + mi * 16 + gq;
        int gr1 = gr0 + 8;
        const float *res0 = nullptr, *res1 = nullptr;
        if (MODE == 1) {
            int b0i = gr0 >> 12, t0 = gr0 & 4095;
            int b1i = gr1 >> 12, t1 = gr1 & 4095;
            res0 = (b0i < 4) ? (e0 + ((size_t)(b0i * SEQ + t0)) * DMODEL)
                             : (e1 + ((size_t)((b0i - 4) * SEQ + t0)) * DMODEL);
            res1 = (b1i < 4) ? (e0 + ((size_t)(b1i * SEQ + t1)) * DMODEL)
                             : (e1 + ((size_t)((b1i - 4) * SEQ + t1)) * DMODEL);
        }
        #pragma unroll
        for (int ni = 0; ni < 4; ni++) {
            int gc = bn + wn * 32 + ni * 8 + 2 * tq;
            if (gc >= N) continue;
            float v0 = acc[mi][ni][0], v1 = acc[mi][ni][1];
            float v2 = acc[mi][ni][2], v3 = acc[mi][ni][3];
            if (MODE == 0) {
                *(float2*)(C + (size_t)gr0 * N + gc) = make_float2(v0, v1);
                *(float2*)(C + (size_t)gr1 * N + gc) = make_float2(v2, v3);
            }
            if (MODE == 1) {
                v0 += res0[gc]; v1 += res0[gc + 1];
                v2 += res1[gc]; v3 += res1[gc + 1];
                *(float2*)(C + (size_t)gr0 * N + gc) = make_float2(v0, v1);
                *(float2*)(C + (size_t)gr1 * N + gc) = make_float2(v2, v3);
                *(__half2*)(g_sph + (size_t)gr0 * DMODEL + gc) = __floats2half2_rn(v0, v1);
                *(__half2*)(g_sph + (size_t)gr1 * DMODEL + gc) = __floats2half2_rn(v2, v3);
            }
            if (MODE == 2) {
                float bx = e0[gc], by = e0[gc + 1];
                v0 = siluf(v0 + bx); v1 = siluf(v1 + by);
                v2 = siluf(v2 + bx); v3 = siluf(v3 + by);
                *(__half2*)(g_hmh + (size_t)gr0 * DMODEL + gc) = __floats2half2_rn(v0, v1);
                *(__half2*)(g_hmh + (size_t)gr1 * DMODEL + gc) = __floats2half2_rn(v2, v3);
            }
            if (MODE == 3) {
                float bx = e0[gc], by = e0[gc + 1];
                const float* s0 = g_sp + (size_t)gr0 * DMODEL + gc;
                const float* s1 = g_sp + (size_t)gr1 * DMODEL + gc;
                v0 += bx + s0[0]; v1 += by + s0[1];
                v2 += bx + s1[0]; v3 += by + s1[1];
                *(float2*)(C + (size_t)gr0 * N + gc) = make_float2(v0, v1);
                *(float2*)(C + (size_t)gr1 * N + gc) = make_float2(v2, v3);
            }
        }
    }
}

// ---------------- launch ------------------------------------------------------
extern "C" void kernel_launch(void* const* d_in, const int* in_sizes, int n_in,
                              void* d_out, int out_size)
{
    const float* x0      = (const float*)d_in[0];
    const float* x1      = (const float*)d_in[1];
    const float* nsw     = (const float*)d_in[2];
    const float* nsb     = (const float*)d_in[3];
    const float* W_in    = (const float*)d_in[4];
    const float* conv_w  = (const float*)d_in[5];
    const float* conv_b  = (const float*)d_in[6];
    const float* dt_bias = (const float*)d_in[7];
    const float* A_log   = (const float*)d_in[8];
    const float* Dp      = (const float*)d_in[9];
    const float* rms_w   = (const float*)d_in[10];
    const float* W_out   = (const float*)d_in[11];
    const float* w1      = (const float*)d_in[12];
    const float* b1      = (const float*)d_in[13];
    const float* w2      = (const float*)d_in[14];
    const float* b2      = (const float*)d_in[15];
    const float* ntw     = (const float*)d_in[16];
    const float* ntb     = (const float*)d_in[17];
    float* out = (float*)d_out;

    float *p_zx, *p_sp, *p_u;
    cudaGetSymbolAddress((void**)&p_zx, g_zx);
    cudaGetSymbolAddress((void**)&p_sp, g_sp);
    cudaGetSymbolAddress((void**)&p_u,  g_u);
    __half *p_xnh, *p_ynh, *p_hmh;
    __half *p_Winh, *p_Winl, *p_Wouth, *p_w1h, *p_w2h;
    cudaGetSymbolAddress((void**)&p_xnh, g_xnh);
    cudaGetSymbolAddress((void**)&p_ynh, g_ynh);
    cudaGetSymbolAddress((void**)&p_hmh, g_hmh);
    cudaGetSymbolAddress((void**)&p_Winh,  g_Winh);
    cudaGetSymbolAddress((void**)&p_Winl,  g_Winl);
    cudaGetSymbolAddress((void**)&p_Wouth, g_Wouth);
    cudaGetSymbolAddress((void**)&p_w1h,   g_w1h);
    cudaGetSymbolAddress((void**)&p_w2h,   g_w2h);

    const int SM2 = NSTAGE * 3 * MATB;   // 92160 (NPROD=2)
    const int SM1 = NSTAGE * 2 * MATB;   // 61440 (NPROD=1)
    cudaFuncSetAttribute((const void*)gemm_mma<0, 2>, cudaFuncAttributeMaxDynamicSharedMemorySize, SM2);
    cudaFuncSetAttribute((const void*)gemm_mma<1, 1>, cudaFuncAttributeMaxDynamicSharedMemorySize, SM1);
    cudaFuncSetAttribute((const void*)gemm_mma<2, 1>, cudaFuncAttributeMaxDynamicSharedMemorySize, SM1);
    cudaFuncSetAttribute((const void*)gemm_mma<3, 1>, cudaFuncAttributeMaxDynamicSharedMemorySize, SM1);

    // #1: merged weight convert
    wcvt_kernel<<<(DPROJ * DMODEL + 255) / 256, 256>>>(W_in, W_out, w1, w2);

    // #2: LayerNorm(concat(x0, x1)) -> fp16
    ln_s_kernel<<<MTOT, 256>>>(x0, x1, nsw, nsb);

    // #3: in-proj GEMM (2-product): zxbcdt = xn @ W_in^T   (32768 x 1160 x 256)
    gemm_mma<0, 2><<<dim3((DPROJ + 127) / 128, MTOT / 128), 256, SM2>>>(
        p_xnh, p_Winh, p_Winl, p_zx, DPROJ, DMODEL, nullptr, nullptr);

    // #4: depthwise conv + SiLU
    conv_kernel<<<((MTOT / 4) * CONVDIM + 255) / 256, 256>>>(conv_w, conv_b);

    // #5: pass A — segmented local scans (2048-way parallel)
    scan_seg_kernel<<<2048, 256>>>(dt_bias, A_log, Dp);

    // #6: pass B — combine segment states
    combine_kernel<<<128, 256>>>();

    // #7: pass C — cross-segment correction
    correct_kernel<<<2048, 256>>>();

    // #8: gate + RMSNorm -> fp16
    gate_rms_kernel<<<MTOT, 256>>>(rms_w);

    // #9: out-proj GEMM (1-product) + residual -> g_sp/g_sph
    gemm_mma<1, 1><<<dim3(2, MTOT / 128), 256, SM1>>>(
        p_ynh, p_Wouth, nullptr, p_sp, DMODEL, DINNER, x0, x1);

    // #10: MLP layer 1 (1-product, cross-concat gather) + SiLU -> g_hmh
    gemm_mma<2, 1><<<dim3(2, MTOT / 128), 256, SM1>>>(
        nullptr, p_w1h, nullptr, nullptr, DMODEL, DINNER, b1, nullptr);

    // #11: MLP layer 2 (1-product) + bias + g_sp residual -> g_u
    gemm_mma<3, 1><<<dim3(2, MTOT / 128), 256, SM1>>>(
        p_hmh, p_w2h, nullptr, p_u, DMODEL, DMODEL, b2, nullptr);

    // #12: final LayerNorm -> d_out
    ln_t_kernel<<<MTOT, 256>>>(ntw, ntb, out);

    (void)in_sizes; (void)n_in; (void)out_size;
}

// round 10
// speedup vs baseline: 1.4499x; 1.0122x over previous
#include <cuda_runtime.h>
#include <cuda_fp16.h>
#include <math.h>
#include <stdint.h>

#define SEQ      4096
#define DMODEL   256
#define DINNER   512
#define DSTATE   64
#define NHEADS   8
#define HEADDIM  64
#define CONVDIM  640
#define DPROJ    1160
#define MTOT     32768          // 8 * 4096 rows (concat of both batch stacks)
#define NSEG     32
#define SEGLEN   128            // SEQ / NSEG
#define NSEGBLK  4096           // 8b * 8h * 2ps * 32seg

// ---------------- scratch (static device globals; no allocations allowed) ----
__device__ float g_zx   [(size_t)MTOT * DPROJ];
__device__ float g_xconv[(size_t)MTOT * CONVDIM];
__device__ float g_yraw [(size_t)MTOT * DINNER];
__device__ float g_sp   [(size_t)MTOT * DMODEL];
__device__ float g_u    [(size_t)MTOT * DMODEL];
__device__ float g_cda  [(size_t)MTOT * NHEADS];          // cumulative dA within segment
__device__ float g_hseg [(size_t)NSEGBLK * 2048];         // local end states per segment
__device__ float g_h0s  [(size_t)NSEGBLK * 2048];         // true start states per segment

// fp16 activations
__device__ __half g_xnh[(size_t)MTOT * DMODEL];
__device__ __half g_ynh[(size_t)MTOT * DINNER];
__device__ __half g_sph[(size_t)MTOT * DMODEL];
__device__ __half g_hmh[(size_t)MTOT * DMODEL];

// fp16 weights (in-proj keeps hi/lo split; others hi only)
__device__ __half g_Winh[DPROJ * DMODEL], g_Winl[DPROJ * DMODEL];
__device__ __half g_Wouth[DMODEL * DINNER];
__device__ __half g_w1h[DMODEL * DINNER];
__device__ __half g_w2h[DMODEL * DMODEL];

__device__ __forceinline__ float siluf(float x) {
    return x / (1.f + expf(-x));
}

// ------ fused: LayerNorm(concat) -> fp16  PLUS weight conversion tail -------
// grid = MTOT + 1160; blocks >= MTOT convert weights (1160*256 == DPROJ*DMODEL)
__global__ void pre_kernel(const float* __restrict__ x0, const float* __restrict__ x1,
                           const float* __restrict__ w,  const float* __restrict__ bias,
                           const float* __restrict__ W_in, const float* __restrict__ W_out,
                           const float* __restrict__ w1,  const float* __restrict__ w2)
{
    int m = blockIdx.x;
    int n = threadIdx.x;
    if (m >= MTOT) {
        int i = (m - MTOT) * 256 + n;
        // i in [0, 296960) == DPROJ*DMODEL
        float v = W_in[i];
        __half h = __float2half(v);
        g_Winh[i] = h;
        g_Winl[i] = __float2half(v - __half2float(h));
        if (i < DMODEL * DINNER) {
            g_Wouth[i] = __float2half(W_out[i]);
            g_w1h[i]   = __float2half(w1[i]);
        }
        if (i < DMODEL * DMODEL) {
            g_w2h[i] = __float2half(w2[i]);
        }
        return;
    }
    int b = m >> 12;
    int t = m & 4095;
    const float* src = (b < 4) ? (x0 + ((size_t)(b * SEQ + t)) * DMODEL)
                               : (x1 + ((size_t)((b - 4) * SEQ + t)) * DMODEL);
    float v = src[n];
    float s = v, s2 = v * v;
    #pragma unroll
    for (int o = 16; o; o >>= 1) {
        s  += __shfl_xor_sync(0xffffffffu, s,  o);
        s2 += __shfl_xor_sync(0xffffffffu, s2, o);
    }
    __shared__ float rs[8], rs2[8];
    int wid = n >> 5, lid = n & 31;
    if (lid == 0) { rs[wid] = s; rs2[wid] = s2; }
    __syncthreads();
    float ts = 0.f, ts2 = 0.f;
    #pragma unroll
    for (int i = 0; i < 8; i++) { ts += rs[i]; ts2 += rs2[i]; }
    float mu  = ts  * (1.f / 256.f);
    float var = ts2 * (1.f / 256.f) - mu * mu;
    float r = rsqrtf(var + 1e-5f);
    float o = (v - mu) * r * w[n] + bias[n];
    g_xnh[(size_t)m * DMODEL + n] = __float2half(o);
}

// ---------------- final LayerNorm: g_u -> d_out ------------------------------
__global__ void ln_t_kernel(const float* __restrict__ w, const float* __restrict__ bias,
                            float* __restrict__ out)
{
    int m = blockIdx.x;
    int n = threadIdx.x;
    float v = g_u[(size_t)m * DMODEL + n];
    float s = v, s2 = v * v;
    #pragma unroll
    for (int o = 16; o; o >>= 1) {
        s  += __shfl_xor_sync(0xffffffffu, s,  o);
        s2 += __shfl_xor_sync(0xffffffffu, s2, o);
    }
    __shared__ float rs[8], rs2[8];
    int wid = n >> 5, lid = n & 31;
    if (lid == 0) { rs[wid] = s; rs2[wid] = s2; }
    __syncthreads();
    float ts = 0.f, ts2 = 0.f;
    #pragma unroll
    for (int i = 0; i < 8; i++) { ts += rs[i]; ts2 += rs2[i]; }
    float mu  = ts  * (1.f / 256.f);
    float var = ts2 * (1.f / 256.f) - mu * mu;
    float r = rsqrtf(var + 1e-5f);
    out[(size_t)m * DMODEL + n] = (v - mu) * r * w[n] + bias[n];
}

// ---------------- depthwise conv (k=4) + SiLU, 4 timesteps/thread -----------
__global__ void conv_kernel(const float* __restrict__ conv_w, const float* __restrict__ conv_b)
{
    int idx = blockIdx.x * blockDim.x + threadIdx.x;
    if (idx >= (MTOT / 4) * CONVDIM) return;
    int c  = idx % CONVDIM;
    int m4 = idx / CONVDIM;
    int b  = m4 >> 10;
    int t0 = (m4 & 1023) << 2;
    const float* base = g_zx + (size_t)(b * SEQ) * DPROJ + DINNER + c;
    float4 w4 = *(const float4*)(conv_w + c * 4);
    float bia = conv_b[c];
    float v[7];
    #pragma unroll
    for (int j = 0; j < 7; j++) {
        int tt = t0 - 3 + j;
        v[j] = (tt >= 0) ? base[(size_t)tt * DPROJ] : 0.f;
    }
    size_t obase = (size_t)(b * SEQ + t0) * CONVDIM + c;
    #pragma unroll
    for (int i = 0; i < 4; i++) {
        float acc = bia;
        acc = fmaf(v[i + 0], w4.x, acc);
        acc = fmaf(v[i + 1], w4.y, acc);
        acc = fmaf(v[i + 2], w4.z, acc);
        acc = fmaf(v[i + 3], w4.w, acc);
        g_xconv[obase + (size_t)i * CONVDIM] = siluf(acc);
    }
}

// ========== Pass A: segmented local scan (h0 = 0) ============================
// grid = 4096: blk = b*512 + h*64 + ps*32 + seg; block = 256: tid = pl*8 + nq
__global__ void __launch_bounds__(256) scan_seg_kernel(
    const float* __restrict__ dt_bias, const float* __restrict__ A_log,
    const float* __restrict__ D_param)
{
    int blk = blockIdx.x;
    int seg = blk & 31;
    int ps  = (blk >> 5) & 1;
    int h   = (blk >> 6) & 7;
    int b   = blk >> 9;
    int tid = threadIdx.x;
    int pl  = tid >> 3;
    int nq  = tid & 7;

    __shared__ __align__(16) float sx[64][32];
    __shared__ __align__(16) float sB[64][64];
    __shared__ __align__(16) float sC[64][64];
    __shared__ float sdt[64];
    __shared__ float sdA[64];

    float hs[8];
    #pragma unroll
    for (int j = 0; j < 8; j++) hs[j] = 0.f;
    float cum = 1.f;

    float Dh  = D_param[h];
    float eA  = expf(A_log[h]);
    float dtb = dt_bias[h];
    const float* xbase = g_xconv + (size_t)b * SEQ * CONVDIM;
    int pofs = h * 64 + ps * 32;
    int tseg = seg * SEGLEN;

    for (int c0 = tseg; c0 < tseg + SEGLEN; c0 += 64) {
        for (int i = tid; i < 64 * 32; i += 256) {
            int t = i >> 5, p = i & 31;
            sx[t][p] = xbase[(size_t)(c0 + t) * CONVDIM + pofs + p];
        }
        for (int i = tid; i < 64 * 64; i += 256) {
            int t = i >> 6, n = i & 63;
            sB[t][n] = xbase[(size_t)(c0 + t) * CONVDIM + 512 + n];
            sC[t][n] = xbase[(size_t)(c0 + t) * CONVDIM + 576 + n];
        }
        if (tid < 64) {
            float raw = g_zx[(size_t)(b * SEQ + c0 + tid) * DPROJ + (DPROJ - NHEADS) + h] + dtb;
            float dt = (raw > 20.f) ? raw : log1pf(expf(raw));
            sdt[tid] = dt;
            sdA[tid] = expf(-eA * dt);
        }
        __syncthreads();

        #pragma unroll 2
        for (int t = 0; t < 64; t++) {
            float dAv = sdA[t];
            float xv  = sx[t][pl];
            float dtx = sdt[t] * xv;
            float4 B0 = *(const float4*)&sB[t][nq * 8];
            float4 B1 = *(const float4*)&sB[t][nq * 8 + 4];
            float4 C0 = *(const float4*)&sC[t][nq * 8];
            float4 C1 = *(const float4*)&sC[t][nq * 8 + 4];
            hs[0] = fmaf(dAv, hs[0], dtx * B0.x);
            hs[1] = fmaf(dAv, hs[1], dtx * B0.y);
            hs[2] = fmaf(dAv, hs[2], dtx * B0.z);
            hs[3] = fmaf(dAv, hs[3], dtx * B0.w);
            hs[4] = fmaf(dAv, hs[4], dtx * B1.x);
            hs[5] = fmaf(dAv, hs[5], dtx * B1.y);
            hs[6] = fmaf(dAv, hs[6], dtx * B1.z);
            hs[7] = fmaf(dAv, hs[7], dtx * B1.w);
            float p0 = fmaf(hs[1], C0.y, hs[0] * C0.x);
            float p1 = fmaf(hs[3], C0.w, hs[2] * C0.z);
            float p2 = fmaf(hs[5], C1.y, hs[4] * C1.x);
            float p3 = fmaf(hs[7], C1.w, hs[6] * C1.z);
            float yp = (p0 + p1) + (p2 + p3);
            yp += __shfl_xor_sync(0xffffffffu, yp, 1);
            yp += __shfl_xor_sync(0xffffffffu, yp, 2);
            yp += __shfl_xor_sync(0xffffffffu, yp, 4);
            cum *= dAv;
            if (nq == 0) {
                g_yraw[(size_t)(b * SEQ + c0 + t) * DINNER + pofs + pl] = fmaf(Dh, xv, yp);
            }
            if (tid == 0) {
                g_cda[(size_t)(b * SEQ + c0 + t) * NHEADS + h] = cum;
            }
        }
        __syncthreads();
    }

    // local end state out
    size_t base = (size_t)blk * 2048 + tid * 8;
    #pragma unroll
    for (int j = 0; j < 8; j++) g_hseg[base + j] = hs[j];
}

// ========== Pass B: sequential combine across segments =======================
// grid = 128: blk = b*16 + h*2 + ps
__global__ void __launch_bounds__(256) combine_kernel()
{
    int blk = blockIdx.x;
    int tid = threadIdx.x;
    int ps = blk & 1;
    int h  = (blk >> 1) & 7;
    int b  = blk >> 4;
    int segbase = b * 512 + h * 64 + ps * 32;   // pass-A block id of seg 0
    float hstart[8];
    #pragma unroll
    for (int j = 0; j < 8; j++) hstart[j] = 0.f;
    for (int s = 0; s < NSEG; s++) {
        size_t base = ((size_t)(segbase + s)) * 2048 + tid * 8;
        #pragma unroll
        for (int j = 0; j < 8; j++) g_h0s[base + j] = hstart[j];
        float P = g_cda[(size_t)(b * SEQ + s * SEGLEN + SEGLEN - 1) * NHEADS + h];
        #pragma unroll
        for (int j = 0; j < 8; j++)
            hstart[j] = fmaf(P, hstart[j], g_hseg[base + j]);
    }
}

// ========== Pass C: correction y += cumdA * (C . h0) =========================
// grid = 4096 (same decode as pass A); seg 0 exits
__global__ void __launch_bounds__(256) correct_kernel()
{
    int blk = blockIdx.x;
    int seg = blk & 31;
    if (seg == 0) return;
    int ps  = (blk >> 5) & 1;
    int h   = (blk >> 6) & 7;
    int b   = blk >> 9;
    int tid = threadIdx.x;
    int pl  = tid >> 3;
    int nq  = tid & 7;

    __shared__ float sh0[2048];
    __shared__ float scd[SEGLEN];
    for (int i = tid; i < 2048; i += 256) sh0[i] = g_h0s[(size_t)blk * 2048 + i];
    if (tid < SEGLEN)
        scd[tid] = g_cda[(size_t)(b * SEQ + seg * SEGLEN + tid) * NHEADS + h];
    __syncthreads();

    int pofs = h * 64 + ps * 32;
    const float* Cb = g_xconv + ((size_t)(b * SEQ + seg * SEGLEN)) * CONVDIM + 576;
    const float* h0 = sh0 + pl * 64 + nq * 8;
    float h00 = h0[0], h01 = h0[1], h02 = h0[2], h03 = h0[3];
    float h04 = h0[4], h05 = h0[5], h06 = h0[6], h07 = h0[7];

    #pragma unroll 4
    for (int t = 0; t < SEGLEN; t++) {
        const float* cp = Cb + (size_t)t * CONVDIM + nq * 8;
        float4 C0 = *(const float4*)cp;
        float4 C1 = *(const float4*)(cp + 4);
        float p0 = fmaf(C0.y, h01, C0.x * h00);
        float p1 = fmaf(C0.w, h03, C0.z * h02);
        float p2 = fmaf(C1.y, h05, C1.x * h04);
        float p3 = fmaf(C1.w, h07, C1.z * h06);
        float p = (p0 + p1) + (p2 + p3);
        p += __shfl_xor_sync(0xffffffffu, p, 1);
        p += __shfl_xor_sync(0xffffffffu, p, 2);
        p += __shfl_xor_sync(0xffffffffu, p, 4);
        if (nq == 0) {
            size_t yi = (size_t)(b * SEQ + seg * SEGLEN + t) * DINNER + pofs + pl;
            g_yraw[yi] += scd[t] * p;
        }
    }
}

// ---------------- gate with silu(z) + RMSNorm -> fp16 ------------------------
__global__ void gate_rms_kernel(const float* __restrict__ rms_w)
{
    int m = blockIdx.x;
    int tid = threadIdx.x;
    float yg[2];
    float s2 = 0.f;
    #pragma unroll
    for (int e = 0; e < 2; e++) {
        int i = tid + e * 256;
        float z = g_zx[(size_t)m * DPROJ + i];
        float y = g_yraw[(size_t)m * DINNER + i];
        float g = y * siluf(z);
        yg[e] = g;
        s2 += g * g;
    }
    #pragma unroll
    for (int o = 16; o; o >>= 1) s2 += __shfl_xor_sync(0xffffffffu, s2, o);
    __shared__ float rs[8];
    int wid = tid >> 5, lid = tid & 31;
    if (lid == 0) rs[wid] = s2;
    __syncthreads();
    float tot = 0.f;
    #pragma unroll
    for (int i = 0; i < 8; i++) tot += rs[i];
    float r = rsqrtf(tot * (1.f / 512.f) + 1e-5f);
    #pragma unroll
    for (int e = 0; e < 2; e++) {
        int i = tid + e * 256;
        g_ynh[(size_t)m * DINNER + i] = __float2half(yg[e] * r * rms_w[i]);
    }
}

// ======== pipelined fp16 mma.sync GEMM: C = A * (Bh [+ Bl])^T ================
__device__ __forceinline__ uint32_t smem_u32(const void* p) {
    uint32_t a;
    asm("{ .reg .u64 t; cvta.to.shared.u64 t, %1; cvt.u32.u64 %0, t; }" : "=r"(a) : "l"(p));
    return a;
}

#define CP16(dst, src, sz) \
    asm volatile("cp.async.cg.shared.global [%0], [%1], 16, %2;" \
                 :: "r"(dst), "l"(src), "r"(sz))
#define CP_COMMIT() asm volatile("cp.async.commit_group;" ::: "memory")
#define CP_WAIT1()  asm volatile("cp.async.wait_group 1;" ::: "memory")

#define LDSM4(d0, d1, d2, d3, a) \
    asm volatile("ldmatrix.sync.aligned.m8n8.x4.shared.b16 {%0,%1,%2,%3}, [%4];" \
                 : "=r"(d0), "=r"(d1), "=r"(d2), "=r"(d3) : "r"(a))

__device__ __forceinline__ void mma_fp16(float* d, const uint32_t* a, const uint32_t* b) {
    asm volatile(
        "mma.sync.aligned.m16n8k16.row.col.f32.f16.f16.f32 "
        "{%0,%1,%2,%3}, {%4,%5,%6,%7}, {%8,%9}, {%0,%1,%2,%3};"
        : "+f"(d[0]), "+f"(d[1]), "+f"(d[2]), "+f"(d[3])
        : "r"(a[0]), "r"(a[1]), "r"(a[2]), "r"(a[3]), "r"(b[0]), "r"(b[1]));
}

#define ROWB     80
#define MATB     (128 * ROWB)        // 10240
#define NSTAGE   3

template <int MODE, int NPROD>
__global__ void __launch_bounds__(256, 2) gemm_mma(
    const __half* __restrict__ Ah,
    const __half* __restrict__ Bh, const __half* __restrict__ Bl,
    float* __restrict__ C, int N, int K,
    const float* __restrict__ e0, const float* __restrict__ e1)
{
    constexpr int STAGEB = (1 + NPROD) * MATB;
    extern __shared__ char smem[];
    uint32_t sb = smem_u32(smem);
    int tid  = threadIdx.x;
    int wid  = tid >> 5, lane = tid & 31;
    int wm   = wid >> 2, wn = wid & 3;
    int bm   = blockIdx.y * 128;
    int bn   = blockIdx.x * 128;
    int gq   = lane >> 2;
    int tq   = lane & 3;

    float acc[4][4][4];
    #pragma unroll
    for (int mi = 0; mi < 4; mi++)
        #pragma unroll
        for (int ni = 0; ni < 4; ni++)
            #pragma unroll
            for (int r = 0; r < 4; r++) acc[mi][ni][r] = 0.f;

    auto fill_stage = [&](int s, int k0) {
        uint32_t st = sb + s * STAGEB;
        #pragma unroll
        for (int j = 0; j < 2; j++) {
            int idx = j * 256 + tid;
            int row = idx >> 2, seg = idx & 3;
            const __half* sh;
            if (MODE == 2) {
                int gr = bm + row;
                int vv = gr >> 14;
                int base = gr & 16383;
                int kk = k0 + seg * 8;
                int usef1 = ((kk >= 256) ? 1 : 0) ^ vv;
                sh = g_sph + ((size_t)(base + (usef1 ? 16384 : 0))) * DMODEL + (kk & 255);
            } else {
                sh = Ah + (size_t)(bm + row) * K + k0 + seg * 8;
            }
            CP16(st + row * ROWB + seg * 16, sh, 16);
        }
        #pragma unroll
        for (int j = 0; j < 2; j++) {
            int idx = j * 256 + tid;
            int row = idx >> 2, seg = idx & 3;
            int gn = bn + row;
            int sz = (gn < N) ? 16 : 0;
            size_t off = (size_t)gn * K + k0 + seg * 8;
            uint32_t d = st + MATB + row * ROWB + seg * 16;
            CP16(d, Bh + off, sz);
            if (NPROD == 2) CP16(d + MATB, Bl + off, sz);
        }
    };

    auto compute_stage = [&](int s) {
        uint32_t stA = sb + s * STAGEB;
        uint32_t stB = stA + MATB;
        int q = lane >> 3, r = lane & 7;
        #pragma unroll
        for (int ks = 0; ks < 2; ks++) {
            int kc = ks * 16;
            uint32_t ah[4][4];
            #pragma unroll
            for (int mi = 0; mi < 4; mi++) {
                int arow = wm * 64 + mi * 16 + (q & 1) * 8 + r;
                int acol = kc + (q >> 1) * 8;
                LDSM4(ah[mi][0], ah[mi][1], ah[mi][2], ah[mi][3],
                      stA + arow * ROWB + acol * 2);
            }
            uint32_t bh[4][2], bl[4][2];
            #pragma unroll
            for (int nb = 0; nb < 2; nb++) {
                int brow = wn * 32 + nb * 16 + (q >> 1) * 8 + r;
                int bcol = kc + (q & 1) * 8;
                uint32_t bd = stB + brow * ROWB + bcol * 2;
                LDSM4(bh[2 * nb][0], bh[2 * nb][1], bh[2 * nb + 1][0], bh[2 * nb + 1][1], bd);
                if (NPROD == 2)
                    LDSM4(bl[2 * nb][0], bl[2 * nb][1], bl[2 * nb + 1][0], bl[2 * nb + 1][1], bd + MATB);
            }
            #pragma unroll
            for (int mi = 0; mi < 4; mi++)
                #pragma unroll
                for (int ni = 0; ni < 4; ni++) {
                    mma_fp16(acc[mi][ni], ah[mi], bh[ni]);
                    if (NPROD == 2) mma_fp16(acc[mi][ni], ah[mi], bl[ni]);
                }
        }
    };

    int nk = K >> 5;
    fill_stage(0, 0);  CP_COMMIT();
    fill_stage(1, 32); CP_COMMIT();

    for (int i = 0; i < nk; i++) {
        CP_WAIT1();
        __syncthreads();
        if (i + 2 < nk) fill_stage((i + 2) % NSTAGE, (i + 2) << 5);
        CP_COMMIT();
        compute_stage(i % NSTAGE);
    }

    // epilogue
    #pragma unroll
    for (int mi = 0; mi < 4; mi++) {
        int gr0 = bm + wm * 64 + mi * 16 + gq;
        int gr1 = gr0 + 8;
        const float *res0 = nullptr, *res1 = nullptr;
        if (MODE == 1) {
            int b0i = gr0 >> 12, t0 = gr0 & 4095;
            int b1i = gr1 >> 12, t1 = gr1 & 4095;
            res0 = (b0i < 4) ? (e0 + ((size_t)(b0i * SEQ + t0)) * DMODEL)
                             : (e1 + ((size_t)((b0i - 4) * SEQ + t0)) * DMODEL);
            res1 = (b1i < 4) ? (e0 + ((size_t)(b1i * SEQ + t1)) * DMODEL)
                             : (e1 + ((size_t)((b1i - 4) * SEQ + t1)) * DMODEL);
        }
        #pragma unroll
        for (int ni = 0; ni < 4; ni++) {
            int gc = bn + wn * 32 + ni * 8 + 2 * tq;
            if (gc >= N) continue;
            float v0 = acc[mi][ni][0], v1 = acc[mi][ni][1];
            float v2 = acc[mi][ni][2], v3 = acc[mi][ni][3];
            if (MODE == 0) {
                *(float2*)(C + (size_t)gr0 * N + gc) = make_float2(v0, v1);
                *(float2*)(C + (size_t)gr1 * N + gc) = make_float2(v2, v3);
            }
            if (MODE == 1) {
                v0 += res0[gc]; v1 += res0[gc + 1];
                v2 += res1[gc]; v3 += res1[gc + 1];
                *(float2*)(C + (size_t)gr0 * N + gc) = make_float2(v0, v1);
                *(float2*)(C + (size_t)gr1 * N + gc) = make_float2(v2, v3);
                *(__half2*)(g_sph + (size_t)gr0 * DMODEL + gc) = __floats2half2_rn(v0, v1);
                *(__half2*)(g_sph + (size_t)gr1 * DMODEL + gc) = __floats2half2_rn(v2, v3);
            }
            if (MODE == 2) {
                float bx = e0[gc], by = e0[gc + 1];
                v0 = siluf(v0 + bx); v1 = siluf(v1 + by);
                v2 = siluf(v2 + bx); v3 = siluf(v3 + by);
                *(__half2*)(g_hmh + (size_t)gr0 * DMODEL + gc) = __floats2half2_rn(v0, v1);
                *(__half2*)(g_hmh + (size_t)gr1 * DMODEL + gc) = __floats2half2_rn(v2, v3);
            }
            if (MODE == 3) {
                float bx = e0[gc], by = e0[gc + 1];
                const float* s0 = g_sp + (size_t)gr0 * DMODEL + gc;
                const float* s1 = g_sp + (size_t)gr1 * DMODEL + gc;
                v0 += bx + s0[0]; v1 += by + s0[1];
                v2 += bx + s1[0]; v3 += by + s1[1];
                *(float2*)(C + (size_t)gr0 * N + gc) = make_float2(v0, v1);
                *(float2*)(C + (size_t)gr1 * N + gc) = make_float2(v2, v3);
            }
        }
    }
}

// ---------------- launch ------------------------------------------------------
extern "C" void kernel_launch(void* const* d_in, const int* in_sizes, int n_in,
                              void* d_out, int out_size)
{
    const float* x0      = (const float*)d_in[0];
    const float* x1      = (const float*)d_in[1];
    const float* nsw     = (const float*)d_in[2];
    const float* nsb     = (const float*)d_in[3];
    const float* W_in    = (const float*)d_in[4];
    const float* conv_w  = (const float*)d_in[5];
    const float* conv_b  = (const float*)d_in[6];
    const float* dt_bias = (const float*)d_in[7];
    const float* A_log   = (const float*)d_in[8];
    const float* Dp      = (const float*)d_in[9];
    const float* rms_w   = (const float*)d_in[10];
    const float* W_out   = (const float*)d_in[11];
    const float* w1      = (const float*)d_in[12];
    const float* b1      = (const float*)d_in[13];
    const float* w2      = (const float*)d_in[14];
    const float* b2      = (const float*)d_in[15];
    const float* ntw     = (const float*)d_in[16];
    const float* ntb     = (const float*)d_in[17];
    float* out = (float*)d_out;

    float *p_zx, *p_sp, *p_u;
    cudaGetSymbolAddress((void**)&p_zx, g_zx);
    cudaGetSymbolAddress((void**)&p_sp, g_sp);
    cudaGetSymbolAddress((void**)&p_u,  g_u);
    __half *p_xnh, *p_ynh, *p_hmh;
    __half *p_Winh, *p_Winl, *p_Wouth, *p_w1h, *p_w2h;
    cudaGetSymbolAddress((void**)&p_xnh, g_xnh);
    cudaGetSymbolAddress((void**)&p_ynh, g_ynh);
    cudaGetSymbolAddress((void**)&p_hmh, g_hmh);
    cudaGetSymbolAddress((void**)&p_Winh,  g_Winh);
    cudaGetSymbolAddress((void**)&p_Winl,  g_Winl);
    cudaGetSymbolAddress((void**)&p_Wouth, g_Wouth);
    cudaGetSymbolAddress((void**)&p_w1h,   g_w1h);
    cudaGetSymbolAddress((void**)&p_w2h,   g_w2h);

    const int SM2 = NSTAGE * 3 * MATB;   // 92160 (NPROD=2)
    const int SM1 = NSTAGE * 2 * MATB;   // 61440 (NPROD=1)
    cudaFuncSetAttribute((const void*)gemm_mma<0, 2>, cudaFuncAttributeMaxDynamicSharedMemorySize, SM2);
    cudaFuncSetAttribute((const void*)gemm_mma<1, 1>, cudaFuncAttributeMaxDynamicSharedMemorySize, SM1);
    cudaFuncSetAttribute((const void*)gemm_mma<2, 1>, cudaFuncAttributeMaxDynamicSharedMemorySize, SM1);
    cudaFuncSetAttribute((const void*)gemm_mma<3, 1>, cudaFuncAttributeMaxDynamicSharedMemorySize, SM1);

    // #1: fused LayerNorm + weight convert
    pre_kernel<<<MTOT + 1160, 256>>>(x0, x1, nsw, nsb, W_in, W_out, w1, w2);

    // #2: in-proj GEMM (2-product): zxbcdt = xn @ W_in^T   (32768 x 1160 x 256)
    gemm_mma<0, 2><<<dim3((DPROJ + 127) / 128, MTOT / 128), 256, SM2>>>(
        p_xnh, p_Winh, p_Winl, p_zx, DPROJ, DMODEL, nullptr, nullptr);

    // #3: depthwise conv + SiLU
    conv_kernel<<<((MTOT / 4) * CONVDIM + 255) / 256, 256>>>(conv_w, conv_b);

    // #4: pass A — segmented local scans (4096-way parallel)  [ncu captures this]
    scan_seg_kernel<<<NSEGBLK, 256>>>(dt_bias, A_log, Dp);

    // #5: pass B — combine segment states
    combine_kernel<<<128, 256>>>();

    // #6: pass C — cross-segment correction
    correct_kernel<<<NSEGBLK, 256>>>();

    // #7: gate + RMSNorm -> fp16
    gate_rms_kernel<<<MTOT, 256>>>(rms_w);

    // #8: out-proj GEMM (1-product) + residual -> g_sp/g_sph
    gemm_mma<1, 1><<<dim3(2, MTOT / 128), 256, SM1>>>(
        p_ynh, p_Wouth, nullptr, p_sp, DMODEL, DINNER, x0, x1);

    // #9: MLP layer 1 (1-product, cross-concat gather) + SiLU -> g_hmh
    gemm_mma<2, 1><<<dim3(2, MTOT / 128), 256, SM1>>>(
        nullptr, p_w1h, nullptr, nullptr, DMODEL, DINNER, b1, nullptr);

    // #10: MLP layer 2 (1-product) + bias + g_sp residual -> g_u
    gemm_mma<3, 1><<<dim3(2, MTOT / 128), 256, SM1>>>(
        p_hmh, p_w2h, nullptr, p_u, DMODEL, DMODEL, b2, nullptr);

    // #11: final LayerNorm -> d_out
    ln_t_kernel<<<MTOT, 256>>>(ntw, ntb, out);

    (void)in_sizes; (void)n_in; (void)out_size;
}

// round 11
// speedup vs baseline: 2.0388x; 1.4062x over previous
#include <cuda_runtime.h>
#include <cuda_fp16.h>
#include <math.h>
#include <stdint.h>

#define SEQ      4096
#define DMODEL   256
#define DINNER   512
#define DSTATE   64
#define NHEADS   8
#define HEADDIM  64
#define CONVDIM  640
#define DPROJ    1160
#define MTOT     32768          // 8 * 4096 rows (concat of both batch stacks)
#define NSEG     32
#define SEGLEN   128            // SEQ / NSEG
#define NSCANBLK 2048           // 8b * 8h * 32seg (full head per block)

// ---------------- scratch (static device globals; no allocations allowed) ----
__device__ float g_zx   [(size_t)MTOT * DPROJ];
__device__ float g_xconv[(size_t)MTOT * CONVDIM];
__device__ float g_yraw [(size_t)MTOT * DINNER];
__device__ float g_sp   [(size_t)MTOT * DMODEL];
__device__ float g_u    [(size_t)MTOT * DMODEL];
__device__ float g_cda  [(size_t)MTOT * NHEADS];          // cumulative dA within segment
__device__ float g_hseg [(size_t)NSCANBLK * 4096];        // local end states per segment
__device__ float g_h0s  [(size_t)NSCANBLK * 4096];        // true start states per segment

// fp16 activations
__device__ __half g_xnh[(size_t)MTOT * DMODEL];
__device__ __half g_ynh[(size_t)MTOT * DINNER];
__device__ __half g_sph[(size_t)MTOT * DMODEL];
__device__ __half g_hmh[(size_t)MTOT * DMODEL];

// fp16 weights (in-proj keeps hi/lo split; others hi only)
__device__ __half g_Winh[DPROJ * DMODEL], g_Winl[DPROJ * DMODEL];
__device__ __half g_Wouth[DMODEL * DINNER];
__device__ __half g_w1h[DMODEL * DINNER];
__device__ __half g_w2h[DMODEL * DMODEL];

__device__ __forceinline__ float siluf(float x) {
    return x / (1.f + expf(-x));
}

// bank-swizzled position for B/C rows: n = nq*16 + s*4 + e  ->  s*16 + nq*4 + e
__device__ __forceinline__ int bc_phys(int n) {
    return ((n >> 2) & 3) * 16 + (n >> 4) * 4 + (n & 3);
}

// ------ fused: LayerNorm(concat) -> fp16  PLUS weight conversion tail -------
__global__ void pre_kernel(const float* __restrict__ x0, const float* __restrict__ x1,
                           const float* __restrict__ w,  const float* __restrict__ bias,
                           const float* __restrict__ W_in, const float* __restrict__ W_out,
                           const float* __restrict__ w1,  const float* __restrict__ w2)
{
    int m = blockIdx.x;
    int n = threadIdx.x;
    if (m >= MTOT) {
        int i = (m - MTOT) * 256 + n;
        float v = W_in[i];
        __half h = __float2half(v);
        g_Winh[i] = h;
        g_Winl[i] = __float2half(v - __half2float(h));
        if (i < DMODEL * DINNER) {
            g_Wouth[i] = __float2half(W_out[i]);
            g_w1h[i]   = __float2half(w1[i]);
        }
        if (i < DMODEL * DMODEL) {
            g_w2h[i] = __float2half(w2[i]);
        }
        return;
    }
    int b = m >> 12;
    int t = m & 4095;
    const float* src = (b < 4) ? (x0 + ((size_t)(b * SEQ + t)) * DMODEL)
                               : (x1 + ((size_t)((b - 4) * SEQ + t)) * DMODEL);
    float v = src[n];
    float s = v, s2 = v * v;
    #pragma unroll
    for (int o = 16; o; o >>= 1) {
        s  += __shfl_xor_sync(0xffffffffu, s,  o);
        s2 += __shfl_xor_sync(0xffffffffu, s2, o);
    }
    __shared__ float rs[8], rs2[8];
    int wid = n >> 5, lid = n & 31;
    if (lid == 0) { rs[wid] = s; rs2[wid] = s2; }
    __syncthreads();
    float ts = 0.f, ts2 = 0.f;
    #pragma unroll
    for (int i = 0; i < 8; i++) { ts += rs[i]; ts2 += rs2[i]; }
    float mu  = ts  * (1.f / 256.f);
    float var = ts2 * (1.f / 256.f) - mu * mu;
    float r = rsqrtf(var + 1e-5f);
    float o = (v - mu) * r * w[n] + bias[n];
    g_xnh[(size_t)m * DMODEL + n] = __float2half(o);
}

// ---------------- final LayerNorm: g_u -> d_out ------------------------------
__global__ void ln_t_kernel(const float* __restrict__ w, const float* __restrict__ bias,
                            float* __restrict__ out)
{
    int m = blockIdx.x;
    int n = threadIdx.x;
    float v = g_u[(size_t)m * DMODEL + n];
    float s = v, s2 = v * v;
    #pragma unroll
    for (int o = 16; o; o >>= 1) {
        s  += __shfl_xor_sync(0xffffffffu, s,  o);
        s2 += __shfl_xor_sync(0xffffffffu, s2, o);
    }
    __shared__ float rs[8], rs2[8];
    int wid = n >> 5, lid = n & 31;
    if (lid == 0) { rs[wid] = s; rs2[wid] = s2; }
    __syncthreads();
    float ts = 0.f, ts2 = 0.f;
    #pragma unroll
    for (int i = 0; i < 8; i++) { ts += rs[i]; ts2 += rs2[i]; }
    float mu  = ts  * (1.f / 256.f);
    float var = ts2 * (1.f / 256.f) - mu * mu;
    float r = rsqrtf(var + 1e-5f);
    out[(size_t)m * DMODEL + n] = (v - mu) * r * w[n] + bias[n];
}

// ---------------- depthwise conv (k=4) + SiLU, 4 timesteps/thread -----------
__global__ void conv_kernel(const float* __restrict__ conv_w, const float* __restrict__ conv_b)
{
    int idx = blockIdx.x * blockDim.x + threadIdx.x;
    if (idx >= (MTOT / 4) * CONVDIM) return;
    int c  = idx % CONVDIM;
    int m4 = idx / CONVDIM;
    int b  = m4 >> 10;
    int t0 = (m4 & 1023) << 2;
    const float* base = g_zx + (size_t)(b * SEQ) * DPROJ + DINNER + c;
    float4 w4 = *(const float4*)(conv_w + c * 4);
    float bia = conv_b[c];
    float v[7];
    #pragma unroll
    for (int j = 0; j < 7; j++) {
        int tt = t0 - 3 + j;
        v[j] = (tt >= 0) ? base[(size_t)tt * DPROJ] : 0.f;
    }
    size_t obase = (size_t)(b * SEQ + t0) * CONVDIM + c;
    #pragma unroll
    for (int i = 0; i < 4; i++) {
        float acc = bia;
        acc = fmaf(v[i + 0], w4.x, acc);
        acc = fmaf(v[i + 1], w4.y, acc);
        acc = fmaf(v[i + 2], w4.z, acc);
        acc = fmaf(v[i + 3], w4.w, acc);
        g_xconv[obase + (size_t)i * CONVDIM] = siluf(acc);
    }
}

// ========== Pass A: segmented local scan, full head per block ================
// grid = 2048: blk = (b*8 + h)*32 + seg; block = 256: pl = tid>>2 in [0,64), nq = tid&3
#define SA_FLOATS (3 * 4096 + 128)
#define SA_BYTES  (SA_FLOATS * 4)          // 49664
__global__ void __launch_bounds__(256) scan_seg_kernel(
    const float* __restrict__ dt_bias, const float* __restrict__ A_log,
    const float* __restrict__ D_param)
{
    extern __shared__ float sm[];
    float* sx  = sm;            // [64][64]
    float* sB  = sm + 4096;     // [64][64] swizzled
    float* sC  = sm + 8192;     // [64][64] swizzled
    float* sdt = sm + 12288;    // [64]
    float* sdA = sm + 12352;    // [64]

    int blk = blockIdx.x;
    int seg = blk & 31;
    int h   = (blk >> 5) & 7;
    int b   = blk >> 8;
    int tid = threadIdx.x;
    int pl  = tid >> 2;
    int nq  = tid & 3;

    float hs[16];
    #pragma unroll
    for (int j = 0; j < 16; j++) hs[j] = 0.f;
    float cum = 1.f;

    float Dh  = D_param[h];
    float eA  = expf(A_log[h]);
    float dtb = dt_bias[h];
    const float* xbase = g_xconv + (size_t)b * SEQ * CONVDIM;
    int pofs = h * 64;
    int tseg = seg * SEGLEN;

    for (int c0 = tseg; c0 < tseg + SEGLEN; c0 += 64) {
        #pragma unroll
        for (int i = 0; i < 16; i++) {
            int idx = i * 256 + tid;
            int t = idx >> 6, n = idx & 63;
            const float* rowp = xbase + (size_t)(c0 + t) * CONVDIM;
            sx[t * 64 + n] = rowp[pofs + n];
            int ph = bc_phys(n);
            sB[t * 64 + ph] = rowp[512 + n];
            sC[t * 64 + ph] = rowp[576 + n];
        }
        if (tid < 64) {
            float raw = g_zx[(size_t)(b * SEQ + c0 + tid) * DPROJ + (DPROJ - NHEADS) + h] + dtb;
            float dt = (raw > 20.f) ? raw : log1pf(expf(raw));
            sdt[tid] = dt;
            sdA[tid] = expf(-eA * dt);
        }
        __syncthreads();

        #pragma unroll 2
        for (int t = 0; t < 64; t++) {
            float dAv = sdA[t];
            float xv  = sx[t * 64 + pl];
            float dtx = sdt[t] * xv;
            const float* bp = sB + t * 64 + nq * 4;
            const float* cp = sC + t * 64 + nq * 4;
            float4 B0 = *(const float4*)(bp);
            float4 B1 = *(const float4*)(bp + 16);
            float4 B2 = *(const float4*)(bp + 32);
            float4 B3 = *(const float4*)(bp + 48);
            float4 C0 = *(const float4*)(cp);
            float4 C1 = *(const float4*)(cp + 16);
            float4 C2 = *(const float4*)(cp + 32);
            float4 C3 = *(const float4*)(cp + 48);
            hs[0]  = fmaf(dAv, hs[0],  dtx * B0.x);
            hs[1]  = fmaf(dAv, hs[1],  dtx * B0.y);
            hs[2]  = fmaf(dAv, hs[2],  dtx * B0.z);
            hs[3]  = fmaf(dAv, hs[3],  dtx * B0.w);
            hs[4]  = fmaf(dAv, hs[4],  dtx * B1.x);
            hs[5]  = fmaf(dAv, hs[5],  dtx * B1.y);
            hs[6]  = fmaf(dAv, hs[6],  dtx * B1.z);
            hs[7]  = fmaf(dAv, hs[7],  dtx * B1.w);
            hs[8]  = fmaf(dAv, hs[8],  dtx * B2.x);
            hs[9]  = fmaf(dAv, hs[9],  dtx * B2.y);
            hs[10] = fmaf(dAv, hs[10], dtx * B2.z);
            hs[11] = fmaf(dAv, hs[11], dtx * B2.w);
            hs[12] = fmaf(dAv, hs[12], dtx * B3.x);
            hs[13] = fmaf(dAv, hs[13], dtx * B3.y);
            hs[14] = fmaf(dAv, hs[14], dtx * B3.z);
            hs[15] = fmaf(dAv, hs[15], dtx * B3.w);
            float p0 = fmaf(hs[1],  C0.y, hs[0]  * C0.x);
            float p1 = fmaf(hs[3],  C0.w, hs[2]  * C0.z);
            float p2 = fmaf(hs[5],  C1.y, hs[4]  * C1.x);
            float p3 = fmaf(hs[7],  C1.w, hs[6]  * C1.z);
            float p4 = fmaf(hs[9],  C2.y, hs[8]  * C2.x);
            float p5 = fmaf(hs[11], C2.w, hs[10] * C2.z);
            float p6 = fmaf(hs[13], C3.y, hs[12] * C3.x);
            float p7 = fmaf(hs[15], C3.w, hs[14] * C3.z);
            float yp = ((p0 + p1) + (p2 + p3)) + ((p4 + p5) + (p6 + p7));
            yp += __shfl_xor_sync(0xffffffffu, yp, 1);
            yp += __shfl_xor_sync(0xffffffffu, yp, 2);
            cum *= dAv;
            if (nq == 0) {
                g_yraw[(size_t)(b * SEQ + c0 + t) * DINNER + pofs + pl] = fmaf(Dh, xv, yp);
            }
            if (tid == 0) {
                g_cda[(size_t)(b * SEQ + c0 + t) * NHEADS + h] = cum;
            }
        }
        __syncthreads();
    }

    // export local end state: state (p=pl, n=nq*16+j) at [pl*64 + nq*16 + j]
    size_t base = (size_t)blk * 4096 + pl * 64 + nq * 16;
    #pragma unroll
    for (int j = 0; j < 4; j++)
        *(float4*)(g_hseg + base + j * 4) = make_float4(hs[j*4], hs[j*4+1], hs[j*4+2], hs[j*4+3]);
}

// ========== Pass B: sequential combine across segments =======================
// grid = 64: blk = b*8 + h; thread handles 16 consecutive state floats
__global__ void __launch_bounds__(256) combine_kernel()
{
    int blk = blockIdx.x;
    int tid = threadIdx.x;
    int h = blk & 7;
    int b = blk >> 3;
    float hstart[16];
    #pragma unroll
    for (int j = 0; j < 16; j++) hstart[j] = 0.f;
    for (int s = 0; s < NSEG; s++) {
        size_t base = ((size_t)(blk * NSEG + s)) * 4096 + tid * 16;
        #pragma unroll
        for (int j = 0; j < 4; j++)
            *(float4*)(g_h0s + base + j * 4) =
                make_float4(hstart[j*4], hstart[j*4+1], hstart[j*4+2], hstart[j*4+3]);
        float P = g_cda[(size_t)(b * SEQ + s * SEGLEN + SEGLEN - 1) * NHEADS + h];
        #pragma unroll
        for (int j = 0; j < 4; j++) {
            float4 v = *(const float4*)(g_hseg + base + j * 4);
            hstart[j*4]   = fmaf(P, hstart[j*4],   v.x);
            hstart[j*4+1] = fmaf(P, hstart[j*4+1], v.y);
            hstart[j*4+2] = fmaf(P, hstart[j*4+2], v.z);
            hstart[j*4+3] = fmaf(P, hstart[j*4+3], v.w);
        }
    }
}

// ========== Pass C: correction y += cumdA * (C . h0) =========================
// grid = 2048 (same decode as pass A); seg 0 exits
#define SC_FLOATS (4096 + SEGLEN * 64 + SEGLEN)
#define SC_BYTES  (SC_FLOATS * 4)     // (4096 + 8192 + 128)*4 = 49664
__global__ void __launch_bounds__(256) correct_kernel()
{
    int blk = blockIdx.x;
    int seg = blk & 31;
    if (seg == 0) return;
    extern __shared__ float sm[];
    float* sh0 = sm;                   // [4096]
    float* sC  = sm + 4096;            // [128][64] swizzled
    float* scd = sm + 4096 + SEGLEN * 64;  // [128]

    int h   = (blk >> 5) & 7;
    int b   = blk >> 8;
    int tid = threadIdx.x;
    int pl  = tid >> 2;
    int nq  = tid & 3;

    for (int i = tid; i < 4096; i += 256) sh0[i] = g_h0s[(size_t)blk * 4096 + i];
    {
        const float* Cb = g_xconv + ((size_t)(b * SEQ + seg * SEGLEN)) * CONVDIM + 576;
        #pragma unroll
        for (int i = 0; i < 32; i++) {
            int idx = i * 256 + tid;
            int t = idx >> 6, n = idx & 63;
            sC[t * 64 + bc_phys(n)] = Cb[(size_t)t * CONVDIM + n];
        }
    }
    if (tid < SEGLEN)
        scd[tid] = g_cda[(size_t)(b * SEQ + seg * SEGLEN + tid) * NHEADS + h];
    __syncthreads();

    const float* h0 = sh0 + pl * 64 + nq * 16;
    float h00 = h0[0],  h01 = h0[1],  h02 = h0[2],  h03 = h0[3];
    float h04 = h0[4],  h05 = h0[5],  h06 = h0[6],  h07 = h0[7];
    float h08 = h0[8],  h09 = h0[9],  h10 = h0[10], h11 = h0[11];
    float h12 = h0[12], h13 = h0[13], h14 = h0[14], h15 = h0[15];
    int pofs = h * 64;

    #pragma unroll 4
    for (int t = 0; t < SEGLEN; t++) {
        const float* cp = sC + t * 64 + nq * 4;
        float4 C0 = *(const float4*)(cp);
        float4 C1 = *(const float4*)(cp + 16);
        float4 C2 = *(const float4*)(cp + 32);
        float4 C3 = *(const float4*)(cp + 48);
        float p0 = fmaf(C0.y, h01, C0.x * h00);
        float p1 = fmaf(C0.w, h03, C0.z * h02);
        float p2 = fmaf(C1.y, h05, C1.x * h04);
        float p3 = fmaf(C1.w, h07, C1.z * h06);
        float p4 = fmaf(C2.y, h09, C2.x * h08);
        float p5 = fmaf(C2.w, h11, C2.z * h10);
        float p6 = fmaf(C3.y, h13, C3.x * h12);
        float p7 = fmaf(C3.w, h15, C3.z * h14);
        float p = ((p0 + p1) + (p2 + p3)) + ((p4 + p5) + (p6 + p7));
        p += __shfl_xor_sync(0xffffffffu, p, 1);
        p += __shfl_xor_sync(0xffffffffu, p, 2);
        if (nq == 0) {
            size_t yi = (size_t)(b * SEQ + seg * SEGLEN + t) * DINNER + pofs + pl;
            g_yraw[yi] += scd[t] * p;
        }
    }
}

// ---------------- gate with silu(z) + RMSNorm -> fp16 ------------------------
__global__ void gate_rms_kernel(const float* __restrict__ rms_w)
{
    int m = blockIdx.x;
    int tid = threadIdx.x;
    float yg[2];
    float s2 = 0.f;
    #pragma unroll
    for (int e = 0; e < 2; e++) {
        int i = tid + e * 256;
        float z = g_zx[(size_t)m * DPROJ + i];
        float y = g_yraw[(size_t)m * DINNER + i];
        float g = y * siluf(z);
        yg[e] = g;
        s2 += g * g;
    }
    #pragma unroll
    for (int o = 16; o; o >>= 1) s2 += __shfl_xor_sync(0xffffffffu, s2, o);
    __shared__ float rs[8];
    int wid = tid >> 5, lid = tid & 31;
    if (lid == 0) rs[wid] = s2;
    __syncthreads();
    float tot = 0.f;
    #pragma unroll
    for (int i = 0; i < 8; i++) tot += rs[i];
    float r = rsqrtf(tot * (1.f / 512.f) + 1e-5f);
    #pragma unroll
    for (int e = 0; e < 2; e++) {
        int i = tid + e * 256;
        g_ynh[(size_t)m * DINNER + i] = __float2half(yg[e] * r * rms_w[i]);
    }
}

// ======== pipelined fp16 mma.sync GEMM: C = A * (Bh [+ Bl])^T ================
__device__ __forceinline__ uint32_t smem_u32(const void* p) {
    uint32_t a;
    asm("{ .reg .u64 t; cvta.to.shared.u64 t, %1; cvt.u32.u64 %0, t; }" : "=r"(a) : "l"(p));
    return a;
}

#define CP16(dst, src, sz) \
    asm volatile("cp.async.cg.shared.global [%0], [%1], 16, %2;" \
                 :: "r"(dst), "l"(src), "r"(sz))
#define CP_COMMIT() asm volatile("cp.async.commit_group;" ::: "memory")
#define CP_WAIT1()  asm volatile("cp.async.wait_group 1;" ::: "memory")

#define LDSM4(d0, d1, d2, d3, a) \
    asm volatile("ldmatrix.sync.aligned.m8n8.x4.shared.b16 {%0,%1,%2,%3}, [%4];" \
                 : "=r"(d0), "=r"(d1), "=r"(d2), "=r"(d3) : "r"(a))

__device__ __forceinline__ void mma_fp16(float* d, const uint32_t* a, const uint32_t* b) {
    asm volatile(
        "mma.sync.aligned.m16n8k16.row.col.f32.f16.f16.f32 "
        "{%0,%1,%2,%3}, {%4,%5,%6,%7}, {%8,%9}, {%0,%1,%2,%3};"
        : "+f"(d[0]), "+f"(d[1]), "+f"(d[2]), "+f"(d[3])
        : "r"(a[0]), "r"(a[1]), "r"(a[2]), "r"(a[3]), "r"(b[0]), "r"(b[1]));
}

#define ROWB     80
#define MATB     (128 * ROWB)        // 10240
#define NSTAGE   3

template <int MODE, int NPROD>
__global__ void __launch_bounds__(256, 2) gemm_mma(
    const __half* __restrict__ Ah,
    const __half* __restrict__ Bh, const __half* __restrict__ Bl,
    float* __restrict__ C, int N, int K,
    const float* __restrict__ e0, const float* __restrict__ e1)
{
    constexpr int STAGEB = (1 + NPROD) * MATB;
    extern __shared__ char smem[];
    uint32_t sb = smem_u32(smem);
    int tid  = threadIdx.x;
    int wid  = tid >> 5, lane = tid & 31;
    int wm   = wid >> 2, wn = wid & 3;
    int bm   = blockIdx.y * 128;
    int bn   = blockIdx.x * 128;
    int gq   = lane >> 2;
    int tq   = lane & 3;

    float acc[4][4][4];
    #pragma unroll
    for (int mi = 0; mi < 4; mi++)
        #pragma unroll
        for (int ni = 0; ni < 4; ni++)
            #pragma unroll
            for (int r = 0; r < 4; r++) acc[mi][ni][r] = 0.f;

    auto fill_stage = [&](int s, int k0) {
        uint32_t st = sb + s * STAGEB;
        #pragma unroll
        for (int j = 0; j < 2; j++) {
            int idx = j * 256 + tid;
            int row = idx >> 2, seg = idx & 3;
            const __half* sh;
            if (MODE == 2) {
                int gr = bm + row;
                int vv = gr >> 14;
                int base = gr & 16383;
                int kk = k0 + seg * 8;
                int usef1 = ((kk >= 256) ? 1 : 0) ^ vv;
                sh = g_sph + ((size_t)(base + (usef1 ? 16384 : 0))) * DMODEL + (kk & 255);
            } else {
                sh = Ah + (size_t)(bm + row) * K + k0 + seg * 8;
            }
            CP16(st + row * ROWB + seg * 16, sh, 16);
        }
        #pragma unroll
        for (int j = 0; j < 2; j++) {
            int idx = j * 256 + tid;
            int row = idx >> 2, seg = idx & 3;
            int gn = bn + row;
            int sz = (gn < N) ? 16 : 0;
            size_t off = (size_t)gn * K + k0 + seg * 8;
            uint32_t d = st + MATB + row * ROWB + seg * 16;
            CP16(d, Bh + off, sz);
            if (NPROD == 2) CP16(d + MATB, Bl + off, sz);
        }
    };

    auto compute_stage = [&](int s) {
        uint32_t stA = sb + s * STAGEB;
        uint32_t stB = stA + MATB;
        int q = lane >> 3, r = lane & 7;
        #pragma unroll
        for (int ks = 0; ks < 2; ks++) {
            int kc = ks * 16;
            uint32_t ah[4][4];
            #pragma unroll
            for (int mi = 0; mi < 4; mi++) {
                int arow = wm * 64 + mi * 16 + (q & 1) * 8 + r;
                int acol = kc + (q >> 1) * 8;
                LDSM4(ah[mi][0], ah[mi][1], ah[mi][2], ah[mi][3],
                      stA + arow * ROWB + acol * 2);
            }
            uint32_t bh[4][2], bl[4][2];
            #pragma unroll
            for (int nb = 0; nb < 2; nb++) {
                int brow = wn * 32 + nb * 16 + (q >> 1) * 8 + r;
                int bcol = kc + (q & 1) * 8;
                uint32_t bd = stB + brow * ROWB + bcol * 2;
                LDSM4(bh[2 * nb][0], bh[2 * nb][1], bh[2 * nb + 1][0], bh[2 * nb + 1][1], bd);
                if (NPROD == 2)
                    LDSM4(bl[2 * nb][0], bl[2 * nb][1], bl[2 * nb + 1][0], bl[2 * nb + 1][1], bd + MATB);
            }
            #pragma unroll
            for (int mi = 0; mi < 4; mi++)
                #pragma unroll
                for (int ni = 0; ni < 4; ni++) {
                    mma_fp16(acc[mi][ni], ah[mi], bh[ni]);
                    if (NPROD == 2) mma_fp16(acc[mi][ni], ah[mi], bl[ni]);
                }
        }
    };

    int nk = K >> 5;
    fill_stage(0, 0);  CP_COMMIT();
    fill_stage(1, 32); CP_COMMIT();

    for (int i = 0; i < nk; i++) {
        CP_WAIT1();
        __syncthreads();
        if (i + 2 < nk) fill_stage((i + 2) % NSTAGE, (i + 2) << 5);
        CP_COMMIT();
        compute_stage(i % NSTAGE);
    }

    // epilogue
    #pragma unroll
    for (int mi = 0; mi < 4; mi++) {
        int gr0 = bm + wm * 64 + mi * 16 + gq;
        int gr1 = gr0 + 8;
        const float *res0 = nullptr, *res1 = nullptr;
        if (MODE == 1) {
            int b0i = gr0 >> 12, t0 = gr0 & 4095;
            int b1i = gr1 >> 12, t1 = gr1 & 4095;
            res0 = (b0i < 4) ? (e0 + ((size_t)(b0i * SEQ + t0)) * DMODEL)
                             : (e1 + ((size_t)((b0i - 4) * SEQ + t0)) * DMODEL);
            res1 = (b1i < 4) ? (e0 + ((size_t)(b1i * SEQ + t1)) * DMODEL)
                             : (e1 + ((size_t)((b1i - 4) * SEQ + t1)) * DMODEL);
        }
        #pragma unroll
        for (int ni = 0; ni < 4; ni++) {
            int gc = bn + wn * 32 + ni * 8 + 2 * tq;
            if (gc >= N) continue;
            float v0 = acc[mi][ni][0], v1 = acc[mi][ni][1];
            float v2 = acc[mi][ni][2], v3 = acc[mi][ni][3];
            if (MODE == 0) {
                *(float2*)(C + (size_t)gr0 * N + gc) = make_float2(v0, v1);
                *(float2*)(C + (size_t)gr1 * N + gc) = make_float2(v2, v3);
            }
            if (MODE == 1) {
                v0 += res0[gc]; v1 += res0[gc + 1];
                v2 += res1[gc]; v3 += res1[gc + 1];
                *(float2*)(C + (size_t)gr0 * N + gc) = make_float2(v0, v1);
                *(float2*)(C + (size_t)gr1 * N + gc) = make_float2(v2, v3);
                *(__half2*)(g_sph + (size_t)gr0 * DMODEL + gc) = __floats2half2_rn(v0, v1);
                *(__half2*)(g_sph + (size_t)gr1 * DMODEL + gc) = __floats2half2_rn(v2, v3);
            }
            if (MODE == 2) {
                float bx = e0[gc], by = e0[gc + 1];
                v0 = siluf(v0 + bx); v1 = siluf(v1 + by);
                v2 = siluf(v2 + bx); v3 = siluf(v3 + by);
                *(__half2*)(g_hmh + (size_t)gr0 * DMODEL + gc) = __floats2half2_rn(v0, v1);
                *(__half2*)(g_hmh + (size_t)gr1 * DMODEL + gc) = __floats2half2_rn(v2, v3);
            }
            if (MODE == 3) {
                float bx = e0[gc], by = e0[gc + 1];
                const float* s0 = g_sp + (size_t)gr0 * DMODEL + gc;
                const float* s1 = g_sp + (size_t)gr1 * DMODEL + gc;
                v0 += bx + s0[0]; v1 += by + s0[1];
                v2 += bx + s1[0]; v3 += by + s1[1];
                *(float2*)(C + (size_t)gr0 * N + gc) = make_float2(v0, v1);
                *(float2*)(C + (size_t)gr1 * N + gc) = make_float2(v2, v3);
            }
        }
    }
}

// ---------------- launch ------------------------------------------------------
extern "C" void kernel_launch(void* const* d_in, const int* in_sizes, int n_in,
                              void* d_out, int out_size)
{
    const float* x0      = (const float*)d_in[0];
    const float* x1      = (const float*)d_in[1];
    const float* nsw     = (const float*)d_in[2];
    const float* nsb     = (const float*)d_in[3];
    const float* W_in    = (const float*)d_in[4];
    const float* conv_w  = (const float*)d_in[5];
    const float* conv_b  = (const float*)d_in[6];
    const float* dt_bias = (const float*)d_in[7];
    const float* A_log   = (const float*)d_in[8];
    const float* Dp      = (const float*)d_in[9];
    const float* rms_w   = (const float*)d_in[10];
    const float* W_out   = (const float*)d_in[11];
    const float* w1      = (const float*)d_in[12];
    const float* b1      = (const float*)d_in[13];
    const float* w2      = (const float*)d_in[14];
    const float* b2      = (const float*)d_in[15];
    const float* ntw     = (const float*)d_in[16];
    const float* ntb     = (const float*)d_in[17];
    float* out = (float*)d_out;

    float *p_zx, *p_sp, *p_u;
    cudaGetSymbolAddress((void**)&p_zx, g_zx);
    cudaGetSymbolAddress((void**)&p_sp, g_sp);
    cudaGetSymbolAddress((void**)&p_u,  g_u);
    __half *p_xnh, *p_ynh, *p_hmh;
    __half *p_Winh, *p_Winl, *p_Wouth, *p_w1h, *p_w2h;
    cudaGetSymbolAddress((void**)&p_xnh, g_xnh);
    cudaGetSymbolAddress((void**)&p_ynh, g_ynh);
    cudaGetSymbolAddress((void**)&p_hmh, g_hmh);
    cudaGetSymbolAddress((void**)&p_Winh,  g_Winh);
    cudaGetSymbolAddress((void**)&p_Winl,  g_Winl);
    cudaGetSymbolAddress((void**)&p_Wouth, g_Wouth);
    cudaGetSymbolAddress((void**)&p_w1h,   g_w1h);
    cudaGetSymbolAddress((void**)&p_w2h,   g_w2h);

    const int SM2 = NSTAGE * 3 * MATB;   // 92160 (NPROD=2)
    const int SM1 = NSTAGE * 2 * MATB;   // 61440 (NPROD=1)
    cudaFuncSetAttribute((const void*)gemm_mma<0, 2>, cudaFuncAttributeMaxDynamicSharedMemorySize, SM2);
    cudaFuncSetAttribute((const void*)gemm_mma<1, 1>, cudaFuncAttributeMaxDynamicSharedMemorySize, SM1);
    cudaFuncSetAttribute((const void*)gemm_mma<2, 1>, cudaFuncAttributeMaxDynamicSharedMemorySize, SM1);
    cudaFuncSetAttribute((const void*)gemm_mma<3, 1>, cudaFuncAttributeMaxDynamicSharedMemorySize, SM1);
    cudaFuncSetAttribute((const void*)scan_seg_kernel, cudaFuncAttributeMaxDynamicSharedMemorySize, SA_BYTES);
    cudaFuncSetAttribute((const void*)correct_kernel,  cudaFuncAttributeMaxDynamicSharedMemorySize, SC_BYTES);

    // #1: fused LayerNorm + weight convert
    pre_kernel<<<MTOT + 1160, 256>>>(x0, x1, nsw, nsb, W_in, W_out, w1, w2);

    // #2: in-proj GEMM (2-product): zxbcdt = xn @ W_in^T   (32768 x 1160 x 256)
    gemm_mma<0, 2><<<dim3((DPROJ + 127) / 128, MTOT / 128), 256, SM2>>>(
        p_xnh, p_Winh, p_Winl, p_zx, DPROJ, DMODEL, nullptr, nullptr);

    // #3: depthwise conv + SiLU
    conv_kernel<<<((MTOT / 4) * CONVDIM + 255) / 256, 256>>>(conv_w, conv_b);

    // #4: pass A — full-head segmented local scans  [ncu captures this]
    scan_seg_kernel<<<NSCANBLK, 256, SA_BYTES>>>(dt_bias, A_log, Dp);

    // #5: pass B — combine segment states
    combine_kernel<<<64, 256>>>();

    // #6: pass C — cross-segment correction
    correct_kernel<<<NSCANBLK, 256, SC_BYTES>>>();

    // #7: gate + RMSNorm -> fp16
    gate_rms_kernel<<<MTOT, 256>>>(rms_w);

    // #8: out-proj GEMM (1-product) + residual -> g_sp/g_sph
    gemm_mma<1, 1><<<dim3(2, MTOT / 128), 256, SM1>>>(
        p_ynh, p_Wouth, nullptr, p_sp, DMODEL, DINNER, x0, x1);

    // #9: MLP layer 1 (1-product, cross-concat gather) + SiLU -> g_hmh
    gemm_mma<2, 1><<<dim3(2, MTOT / 128), 256, SM1>>>(
        nullptr, p_w1h, nullptr, nullptr, DMODEL, DINNER, b1, nullptr);

    // #10: MLP layer 2 (1-product) + bias + g_sp residual -> g_u
    gemm_mma<3, 1><<<dim3(2, MTOT / 128), 256, SM1>>>(
        p_hmh, p_w2h, nullptr, p_u, DMODEL, DMODEL, b2, nullptr);

    // #11: final LayerNorm -> d_out
    ln_t_kernel<<<MTOT, 256>>>(ntw, ntb, out);

    (void)in_sizes; (void)n_in; (void)out_size;
}

// round 12
// speedup vs baseline: 2.3396x; 1.1475x over previous
#include <cuda_runtime.h>
#include <cuda_fp16.h>
#include <math.h>
#include <stdint.h>

#define SEQ      4096
#define DMODEL   256
#define DINNER   512
#define DSTATE   64
#define NHEADS   8
#define HEADDIM  64
#define CONVDIM  640
#define DPROJ    1160
#define MTOT     32768          // 8 * 4096 rows (concat of both batch stacks)
#define NSEG     32
#define SEGLEN   128            // SEQ / NSEG
#define NSCANBLK 2048           // 8b * 8h * 32seg (full head per block)

// ---------------- scratch (static device globals; no allocations allowed) ----
__device__ float g_zx   [(size_t)MTOT * DPROJ];
__device__ float g_xconv[(size_t)MTOT * CONVDIM];
__device__ float g_yraw [(size_t)MTOT * DINNER];
__device__ float g_sp   [(size_t)MTOT * DMODEL];
__device__ float g_u    [(size_t)MTOT * DMODEL];
__device__ float g_cda  [(size_t)MTOT * NHEADS];          // cumulative dA within segment
__device__ float g_hseg [(size_t)NSCANBLK * 4096];        // local end states per segment
__device__ float g_h0s  [(size_t)NSCANBLK * 4096];        // true start states per segment

// fp16 activations
__device__ __half g_xnh[(size_t)MTOT * DMODEL];
__device__ __half g_ynh[(size_t)MTOT * DINNER];
__device__ __half g_sph[(size_t)MTOT * DMODEL];
__device__ __half g_hmh[(size_t)MTOT * DMODEL];

// fp16 weights (in-proj keeps hi/lo split; others hi only)
__device__ __half g_Winh[DPROJ * DMODEL], g_Winl[DPROJ * DMODEL];
__device__ __half g_Wouth[DMODEL * DINNER];
__device__ __half g_w1h[DMODEL * DINNER];
__device__ __half g_w2h[DMODEL * DMODEL];

__device__ __forceinline__ float siluf(float x) {
    return x / (1.f + expf(-x));
}
__device__ __forceinline__ float2 h2f(uint32_t u) {
    __half2 h = *(__half2*)&u;
    return __half22float2(h);
}

// ------ fused: LayerNorm(concat) -> fp16  PLUS weight conversion tail -------
__global__ void pre_kernel(const float* __restrict__ x0, const float* __restrict__ x1,
                           const float* __restrict__ w,  const float* __restrict__ bias,
                           const float* __restrict__ W_in, const float* __restrict__ W_out,
                           const float* __restrict__ w1,  const float* __restrict__ w2)
{
    int m = blockIdx.x;
    int n = threadIdx.x;
    if (m >= MTOT) {
        int i = (m - MTOT) * 256 + n;
        float v = W_in[i];
        __half h = __float2half(v);
        g_Winh[i] = h;
        g_Winl[i] = __float2half(v - __half2float(h));
        if (i < DMODEL * DINNER) {
            g_Wouth[i] = __float2half(W_out[i]);
            g_w1h[i]   = __float2half(w1[i]);
        }
        if (i < DMODEL * DMODEL) {
            g_w2h[i] = __float2half(w2[i]);
        }
        return;
    }
    int b = m >> 12;
    int t = m & 4095;
    const float* src = (b < 4) ? (x0 + ((size_t)(b * SEQ + t)) * DMODEL)
                               : (x1 + ((size_t)((b - 4) * SEQ + t)) * DMODEL);
    float v = src[n];
    float s = v, s2 = v * v;
    #pragma unroll
    for (int o = 16; o; o >>= 1) {
        s  += __shfl_xor_sync(0xffffffffu, s,  o);
        s2 += __shfl_xor_sync(0xffffffffu, s2, o);
    }
    __shared__ float rs[8], rs2[8];
    int wid = n >> 5, lid = n & 31;
    if (lid == 0) { rs[wid] = s; rs2[wid] = s2; }
    __syncthreads();
    float ts = 0.f, ts2 = 0.f;
    #pragma unroll
    for (int i = 0; i < 8; i++) { ts += rs[i]; ts2 += rs2[i]; }
    float mu  = ts  * (1.f / 256.f);
    float var = ts2 * (1.f / 256.f) - mu * mu;
    float r = rsqrtf(var + 1e-5f);
    float o = (v - mu) * r * w[n] + bias[n];
    g_xnh[(size_t)m * DMODEL + n] = __float2half(o);
}

// ---------------- final LayerNorm: g_u -> d_out ------------------------------
__global__ void ln_t_kernel(const float* __restrict__ w, const float* __restrict__ bias,
                            float* __restrict__ out)
{
    int m = blockIdx.x;
    int n = threadIdx.x;
    float v = g_u[(size_t)m * DMODEL + n];
    float s = v, s2 = v * v;
    #pragma unroll
    for (int o = 16; o; o >>= 1) {
        s  += __shfl_xor_sync(0xffffffffu, s,  o);
        s2 += __shfl_xor_sync(0xffffffffu, s2, o);
    }
    __shared__ float rs[8], rs2[8];
    int wid = n >> 5, lid = n & 31;
    if (lid == 0) { rs[wid] = s; rs2[wid] = s2; }
    __syncthreads();
    float ts = 0.f, ts2 = 0.f;
    #pragma unroll
    for (int i = 0; i < 8; i++) { ts += rs[i]; ts2 += rs2[i]; }
    float mu  = ts  * (1.f / 256.f);
    float var = ts2 * (1.f / 256.f) - mu * mu;
    float r = rsqrtf(var + 1e-5f);
    out[(size_t)m * DMODEL + n] = (v - mu) * r * w[n] + bias[n];
}

// ---------------- depthwise conv (k=4) + SiLU, 4 timesteps/thread -----------
__global__ void conv_kernel(const float* __restrict__ conv_w, const float* __restrict__ conv_b)
{
    int idx = blockIdx.x * blockDim.x + threadIdx.x;
    if (idx >= (MTOT / 4) * CONVDIM) return;
    int c  = idx % CONVDIM;
    int m4 = idx / CONVDIM;
    int b  = m4 >> 10;
    int t0 = (m4 & 1023) << 2;
    const float* base = g_zx + (size_t)(b * SEQ) * DPROJ + DINNER + c;
    float4 w4 = *(const float4*)(conv_w + c * 4);
    float bia = conv_b[c];
    float v[7];
    #pragma unroll
    for (int j = 0; j < 7; j++) {
        int tt = t0 - 3 + j;
        v[j] = (tt >= 0) ? base[(size_t)tt * DPROJ] : 0.f;
    }
    size_t obase = (size_t)(b * SEQ + t0) * CONVDIM + c;
    #pragma unroll
    for (int i = 0; i < 4; i++) {
        float acc = bia;
        acc = fmaf(v[i + 0], w4.x, acc);
        acc = fmaf(v[i + 1], w4.y, acc);
        acc = fmaf(v[i + 2], w4.z, acc);
        acc = fmaf(v[i + 3], w4.w, acc);
        g_xconv[obase + (size_t)i * CONVDIM] = siluf(acc);
    }
}

// ========== Pass A: segmented local scan, full head per block ================
// grid = 2048: blk = (b*8 + h)*32 + seg; block = 256: pl = tid>>2 in [0,64), nq = tid&3
// SMEM: sx fp32 [64][64] | sB half [64][64] | sC half [64][64] | sdt, sdA
#define SA_BYTES (16384 + 8192 + 8192 + 256 + 256)   // 33280
__global__ void __launch_bounds__(256) scan_seg_kernel(
    const float* __restrict__ dt_bias, const float* __restrict__ A_log,
    const float* __restrict__ D_param)
{
    extern __shared__ char smraw[];
    float*  sx  = (float*)smraw;                  // [64][64] fp32
    __half* sB  = (__half*)(smraw + 16384);       // [64][64] fp16
    __half* sC  = (__half*)(smraw + 24576);       // [64][64] fp16
    float*  sdt = (float*)(smraw + 32768);        // [64]
    float*  sdA = (float*)(smraw + 33024);        // [64]

    int blk = blockIdx.x;
    int seg = blk & 31;
    int h   = (blk >> 5) & 7;
    int b   = blk >> 8;
    int tid = threadIdx.x;
    int pl  = tid >> 2;
    int nq  = tid & 3;

    float hs[16];
    #pragma unroll
    for (int j = 0; j < 16; j++) hs[j] = 0.f;
    float cum = 1.f;

    float Dh  = D_param[h];
    float eA  = expf(A_log[h]);
    float dtb = dt_bias[h];
    const float* xbase = g_xconv + (size_t)b * SEQ * CONVDIM;
    int pofs = h * 64;
    int tseg = seg * SEGLEN;

    for (int c0 = tseg; c0 < tseg + SEGLEN; c0 += 64) {
        #pragma unroll
        for (int i = 0; i < 4; i++) {
            int idx = i * 256 + tid;            // 1024 = 64 t x 16 quads
            int t = idx >> 4, n4 = (idx & 15) * 4;
            const float* rowp = xbase + (size_t)(c0 + t) * CONVDIM;
            *(float4*)(sx + t * 64 + n4) = *(const float4*)(rowp + pofs + n4);
            float4 bv = *(const float4*)(rowp + 512 + n4);
            float4 cv = *(const float4*)(rowp + 576 + n4);
            __half2 b01 = __floats2half2_rn(bv.x, bv.y);
            __half2 b23 = __floats2half2_rn(bv.z, bv.w);
            __half2 c01 = __floats2half2_rn(cv.x, cv.y);
            __half2 c23 = __floats2half2_rn(cv.z, cv.w);
            *(uint2*)(sB + t * 64 + n4) = make_uint2(*(uint32_t*)&b01, *(uint32_t*)&b23);
            *(uint2*)(sC + t * 64 + n4) = make_uint2(*(uint32_t*)&c01, *(uint32_t*)&c23);
        }
        if (tid < 64) {
            float raw = g_zx[(size_t)(b * SEQ + c0 + tid) * DPROJ + (DPROJ - NHEADS) + h] + dtb;
            float dt = (raw > 20.f) ? raw : log1pf(expf(raw));
            sdt[tid] = dt;
            sdA[tid] = expf(-eA * dt);
        }
        __syncthreads();

        #pragma unroll 2
        for (int t = 0; t < 64; t++) {
            float dAv = sdA[t];
            float xv  = sx[t * 64 + pl];
            float dtx = sdt[t] * xv;
            const __half* bb = sB + t * 64 + nq * 16;
            const __half* cb = sC + t * 64 + nq * 16;
            uint4 bu0 = *(const uint4*)(bb);
            uint4 bu1 = *(const uint4*)(bb + 8);
            uint4 cu0 = *(const uint4*)(cb);
            uint4 cu1 = *(const uint4*)(cb + 8);
            float2 b0 = h2f(bu0.x), b1 = h2f(bu0.y), b2 = h2f(bu0.z), b3 = h2f(bu0.w);
            float2 b4 = h2f(bu1.x), b5 = h2f(bu1.y), b6 = h2f(bu1.z), b7 = h2f(bu1.w);
            float2 c0v = h2f(cu0.x), c1v = h2f(cu0.y), c2v = h2f(cu0.z), c3v = h2f(cu0.w);
            float2 c4v = h2f(cu1.x), c5v = h2f(cu1.y), c6v = h2f(cu1.z), c7v = h2f(cu1.w);
            hs[0]  = fmaf(dAv, hs[0],  dtx * b0.x);
            hs[1]  = fmaf(dAv, hs[1],  dtx * b0.y);
            hs[2]  = fmaf(dAv, hs[2],  dtx * b1.x);
            hs[3]  = fmaf(dAv, hs[3],  dtx * b1.y);
            hs[4]  = fmaf(dAv, hs[4],  dtx * b2.x);
            hs[5]  = fmaf(dAv, hs[5],  dtx * b2.y);
            hs[6]  = fmaf(dAv, hs[6],  dtx * b3.x);
            hs[7]  = fmaf(dAv, hs[7],  dtx * b3.y);
            hs[8]  = fmaf(dAv, hs[8],  dtx * b4.x);
            hs[9]  = fmaf(dAv, hs[9],  dtx * b4.y);
            hs[10] = fmaf(dAv, hs[10], dtx * b5.x);
            hs[11] = fmaf(dAv, hs[11], dtx * b5.y);
            hs[12] = fmaf(dAv, hs[12], dtx * b6.x);
            hs[13] = fmaf(dAv, hs[13], dtx * b6.y);
            hs[14] = fmaf(dAv, hs[14], dtx * b7.x);
            hs[15] = fmaf(dAv, hs[15], dtx * b7.y);
            float p0 = fmaf(hs[1],  c0v.y, hs[0]  * c0v.x);
            float p1 = fmaf(hs[3],  c1v.y, hs[2]  * c1v.x);
            float p2 = fmaf(hs[5],  c2v.y, hs[4]  * c2v.x);
            float p3 = fmaf(hs[7],  c3v.y, hs[6]  * c3v.x);
            float p4 = fmaf(hs[9],  c4v.y, hs[8]  * c4v.x);
            float p5 = fmaf(hs[11], c5v.y, hs[10] * c5v.x);
            float p6 = fmaf(hs[13], c6v.y, hs[12] * c6v.x);
            float p7 = fmaf(hs[15], c7v.y, hs[14] * c7v.x);
            float yp = ((p0 + p1) + (p2 + p3)) + ((p4 + p5) + (p6 + p7));
            yp += __shfl_xor_sync(0xffffffffu, yp, 1);
            yp += __shfl_xor_sync(0xffffffffu, yp, 2);
            cum *= dAv;
            if (nq == 0) {
                g_yraw[(size_t)(b * SEQ + c0 + t) * DINNER + pofs + pl] = fmaf(Dh, xv, yp);
            }
            if (tid == 0) {
                g_cda[(size_t)(b * SEQ + c0 + t) * NHEADS + h] = cum;
            }
        }
        __syncthreads();
    }

    // export local end state: thread owns states (p=pl, n=nq*16..nq*16+15)
    size_t base = (size_t)blk * 4096 + pl * 64 + nq * 16;
    #pragma unroll
    for (int j = 0; j < 4; j++)
        *(float4*)(g_hseg + base + j * 4) = make_float4(hs[j*4], hs[j*4+1], hs[j*4+2], hs[j*4+3]);
}

// ========== Pass B: sequential combine across segments =======================
// grid = 64: blk = b*8 + h; thread handles 16 consecutive state floats
__global__ void __launch_bounds__(256) combine_kernel()
{
    int blk = blockIdx.x;
    int tid = threadIdx.x;
    int h = blk & 7;
    int b = blk >> 3;
    float hstart[16];
    #pragma unroll
    for (int j = 0; j < 16; j++) hstart[j] = 0.f;
    for (int s = 0; s < NSEG; s++) {
        size_t base = ((size_t)(blk * NSEG + s)) * 4096 + tid * 16;
        #pragma unroll
        for (int j = 0; j < 4; j++)
            *(float4*)(g_h0s + base + j * 4) =
                make_float4(hstart[j*4], hstart[j*4+1], hstart[j*4+2], hstart[j*4+3]);
        float P = g_cda[(size_t)(b * SEQ + s * SEGLEN + SEGLEN - 1) * NHEADS + h];
        #pragma unroll
        for (int j = 0; j < 4; j++) {
            float4 v = *(const float4*)(g_hseg + base + j * 4);
            hstart[j*4]   = fmaf(P, hstart[j*4],   v.x);
            hstart[j*4+1] = fmaf(P, hstart[j*4+1], v.y);
            hstart[j*4+2] = fmaf(P, hstart[j*4+2], v.z);
            hstart[j*4+3] = fmaf(P, hstart[j*4+3], v.w);
        }
    }
}

// ========== Pass C: correction y += cumdA * (C . h0) =========================
// grid = 2048 (same decode as pass A); seg 0 exits
// SMEM: sh0 fp32 [4096] | sC half [128][64] | scd [128]
#define SC_BYTES (16384 + SEGLEN * 64 * 2 + SEGLEN * 4)   // 16384+16384+512 = 33280
__global__ void __launch_bounds__(256) correct_kernel()
{
    int blk = blockIdx.x;
    int seg = blk & 31;
    if (seg == 0) return;
    extern __shared__ char smraw[];
    float*  sh0 = (float*)smraw;                        // [4096]
    __half* sC  = (__half*)(smraw + 16384);             // [128][64]
    float*  scd = (float*)(smraw + 16384 + SEGLEN * 64 * 2);  // [128]

    int h   = (blk >> 5) & 7;
    int b   = blk >> 8;
    int tid = threadIdx.x;
    int pl  = tid >> 2;
    int nq  = tid & 3;

    for (int i = tid; i < 4096; i += 256) sh0[i] = g_h0s[(size_t)blk * 4096 + i];
    {
        const float* Cb = g_xconv + ((size_t)(b * SEQ + seg * SEGLEN)) * CONVDIM + 576;
        #pragma unroll
        for (int i = 0; i < 8; i++) {
            int idx = i * 256 + tid;            // 2048 = 128 t x 16 quads
            int t = idx >> 4, n4 = (idx & 15) * 4;
            float4 cv = *(const float4*)(Cb + (size_t)t * CONVDIM + n4);
            __half2 c01 = __floats2half2_rn(cv.x, cv.y);
            __half2 c23 = __floats2half2_rn(cv.z, cv.w);
            *(uint2*)(sC + t * 64 + n4) = make_uint2(*(uint32_t*)&c01, *(uint32_t*)&c23);
        }
    }
    if (tid < SEGLEN)
        scd[tid] = g_cda[(size_t)(b * SEQ + seg * SEGLEN + tid) * NHEADS + h];
    __syncthreads();

    const float* h0 = sh0 + pl * 64 + nq * 16;
    float h00 = h0[0],  h01 = h0[1],  h02 = h0[2],  h03 = h0[3];
    float h04 = h0[4],  h05 = h0[5],  h06 = h0[6],  h07 = h0[7];
    float h08 = h0[8],  h09 = h0[9],  h10 = h0[10], h11 = h0[11];
    float h12 = h0[12], h13 = h0[13], h14 = h0[14], h15 = h0[15];
    int pofs = h * 64;

    #pragma unroll 4
    for (int t = 0; t < SEGLEN; t++) {
        const __half* cb = sC + t * 64 + nq * 16;
        uint4 cu0 = *(const uint4*)(cb);
        uint4 cu1 = *(const uint4*)(cb + 8);
        float2 c0v = h2f(cu0.x), c1v = h2f(cu0.y), c2v = h2f(cu0.z), c3v = h2f(cu0.w);
        float2 c4v = h2f(cu1.x), c5v = h2f(cu1.y), c6v = h2f(cu1.z), c7v = h2f(cu1.w);
        float p0 = fmaf(c0v.y, h01, c0v.x * h00);
        float p1 = fmaf(c1v.y, h03, c1v.x * h02);
        float p2 = fmaf(c2v.y, h05, c2v.x * h04);
        float p3 = fmaf(c3v.y, h07, c3v.x * h06);
        float p4 = fmaf(c4v.y, h09, c4v.x * h08);
        float p5 = fmaf(c5v.y, h11, c5v.x * h10);
        float p6 = fmaf(c6v.y, h13, c6v.x * h12);
        float p7 = fmaf(c7v.y, h15, c7v.x * h14);
        float p = ((p0 + p1) + (p2 + p3)) + ((p4 + p5) + (p6 + p7));
        p += __shfl_xor_sync(0xffffffffu, p, 1);
        p += __shfl_xor_sync(0xffffffffu, p, 2);
        if (nq == 0) {
            size_t yi = (size_t)(b * SEQ + seg * SEGLEN + t) * DINNER + pofs + pl;
            g_yraw[yi] += scd[t] * p;
        }
    }
}

// ---------------- gate with silu(z) + RMSNorm -> fp16 ------------------------
__global__ void gate_rms_kernel(const float* __restrict__ rms_w)
{
    int m = blockIdx.x;
    int tid = threadIdx.x;
    float yg[2];
    float s2 = 0.f;
    #pragma unroll
    for (int e = 0; e < 2; e++) {
        int i = tid + e * 256;
        float z = g_zx[(size_t)m * DPROJ + i];
        float y = g_yraw[(size_t)m * DINNER + i];
        float g = y * siluf(z);
        yg[e] = g;
        s2 += g * g;
    }
    #pragma unroll
    for (int o = 16; o; o >>= 1) s2 += __shfl_xor_sync(0xffffffffu, s2, o);
    __shared__ float rs[8];
    int wid = tid >> 5, lid = tid & 31;
    if (lid == 0) rs[wid] = s2;
    __syncthreads();
    float tot = 0.f;
    #pragma unroll
    for (int i = 0; i < 8; i++) tot += rs[i];
    float r = rsqrtf(tot * (1.f / 512.f) + 1e-5f);
    #pragma unroll
    for (int e = 0; e < 2; e++) {
        int i = tid + e * 256;
        g_ynh[(size_t)m * DINNER + i] = __float2half(yg[e] * r * rms_w[i]);
    }
}

// ======== pipelined fp16 mma.sync GEMM: C = A * (Bh [+ Bl])^T ================
__device__ __forceinline__ uint32_t smem_u32(const void* p) {
    uint32_t a;
    asm("{ .reg .u64 t; cvta.to.shared.u64 t, %1; cvt.u32.u64 %0, t; }" : "=r"(a) : "l"(p));
    return a;
}

#define CP16(dst, src, sz) \
    asm volatile("cp.async.cg.shared.global [%0], [%1], 16, %2;" \
                 :: "r"(dst), "l"(src), "r"(sz))
#define CP_COMMIT() asm volatile("cp.async.commit_group;" ::: "memory")
#define CP_WAIT1()  asm volatile("cp.async.wait_group 1;" ::: "memory")

#define LDSM4(d0, d1, d2, d3, a) \
    asm volatile("ldmatrix.sync.aligned.m8n8.x4.shared.b16 {%0,%1,%2,%3}, [%4];" \
                 : "=r"(d0), "=r"(d1), "=r"(d2), "=r"(d3) : "r"(a))

__device__ __forceinline__ void mma_fp16(float* d, const uint32_t* a, const uint32_t* b) {
    asm volatile(
        "mma.sync.aligned.m16n8k16.row.col.f32.f16.f16.f32 "
        "{%0,%1,%2,%3}, {%4,%5,%6,%7}, {%8,%9}, {%0,%1,%2,%3};"
        : "+f"(d[0]), "+f"(d[1]), "+f"(d[2]), "+f"(d[3])
        : "r"(a[0]), "r"(a[1]), "r"(a[2]), "r"(a[3]), "r"(b[0]), "r"(b[1]));
}

#define ROWB     80
#define MATB     (128 * ROWB)        // 10240
#define NSTAGE   3

template <int MODE, int NPROD>
__global__ void __launch_bounds__(256, 2) gemm_mma(
    const __half* __restrict__ Ah,
    const __half* __restrict__ Bh, const __half* __restrict__ Bl,
    float* __restrict__ C, int N, int K,
    const float* __restrict__ e0, const float* __restrict__ e1)
{
    constexpr int STAGEB = (1 + NPROD) * MATB;
    extern __shared__ char smem[];
    uint32_t sb = smem_u32(smem);
    int tid  = threadIdx.x;
    int wid  = tid >> 5, lane = tid & 31;
    int wm   = wid >> 2, wn = wid & 3;
    int bm   = blockIdx.y * 128;
    int bn   = blockIdx.x * 128;
    int gq   = lane >> 2;
    int tq   = lane & 3;

    float acc[4][4][4];
    #pragma unroll
    for (int mi = 0; mi < 4; mi++)
        #pragma unroll
        for (int ni = 0; ni < 4; ni++)
            #pragma unroll
            for (int r = 0; r < 4; r++) acc[mi][ni][r] = 0.f;

    auto fill_stage = [&](int s, int k0) {
        uint32_t st = sb + s * STAGEB;
        #pragma unroll
        for (int j = 0; j < 2; j++) {
            int idx = j * 256 + tid;
            int row = idx >> 2, seg = idx & 3;
            const __half* sh;
            if (MODE == 2) {
                int gr = bm + row;
                int vv = gr >> 14;
                int base = gr & 16383;
                int kk = k0 + seg * 8;
                int usef1 = ((kk >= 256) ? 1 : 0) ^ vv;
                sh = g_sph + ((size_t)(base + (usef1 ? 16384 : 0))) * DMODEL + (kk & 255);
            } else {
                sh = Ah + (size_t)(bm + row) * K + k0 + seg * 8;
            }
            CP16(st + row * ROWB + seg * 16, sh, 16);
        }
        #pragma unroll
        for (int j = 0; j < 2; j++) {
            int idx = j * 256 + tid;
            int row = idx >> 2, seg = idx & 3;
            int gn = bn + row;
            int sz = (gn < N) ? 16 : 0;
            size_t off = (size_t)gn * K + k0 + seg * 8;
            uint32_t d = st + MATB + row * ROWB + seg * 16;
            CP16(d, Bh + off, sz);
            if (NPROD == 2) CP16(d + MATB, Bl + off, sz);
        }
    };

    auto compute_stage = [&](int s) {
        uint32_t stA = sb + s * STAGEB;
        uint32_t stB = stA + MATB;
        int q = lane >> 3, r = lane & 7;
        #pragma unroll
        for (int ks = 0; ks < 2; ks++) {
            int kc = ks * 16;
            uint32_t ah[4][4];
            #pragma unroll
            for (int mi = 0; mi < 4; mi++) {
                int arow = wm * 64 + mi * 16 + (q & 1) * 8 + r;
                int acol = kc + (q >> 1) * 8;
                LDSM4(ah[mi][0], ah[mi][1], ah[mi][2], ah[mi][3],
                      stA + arow * ROWB + acol * 2);
            }
            uint32_t bh[4][2], bl[4][2];
            #pragma unroll
            for (int nb = 0; nb < 2; nb++) {
                int brow = wn * 32 + nb * 16 + (q >> 1) * 8 + r;
                int bcol = kc + (q & 1) * 8;
                uint32_t bd = stB + brow * ROWB + bcol * 2;
                LDSM4(bh[2 * nb][0], bh[2 * nb][1], bh[2 * nb + 1][0], bh[2 * nb + 1][1], bd);
                if (NPROD == 2)
                    LDSM4(bl[2 * nb][0], bl[2 * nb][1], bl[2 * nb + 1][0], bl[2 * nb + 1][1], bd + MATB);
            }
            #pragma unroll
            for (int mi = 0; mi < 4; mi++)
                #pragma unroll
                for (int ni = 0; ni < 4; ni++) {
                    mma_fp16(acc[mi][ni], ah[mi], bh[ni]);
                    if (NPROD == 2) mma_fp16(acc[mi][ni], ah[mi], bl[ni]);
                }
        }
    };

    int nk = K >> 5;
    fill_stage(0, 0);  CP_COMMIT();
    fill_stage(1, 32); CP_COMMIT();

    for (int i = 0; i < nk; i++) {
        CP_WAIT1();
        __syncthreads();
        if (i + 2 < nk) fill_stage((i + 2) % NSTAGE, (i + 2) << 5);
        CP_COMMIT();
        compute_stage(i % NSTAGE);
    }

    // epilogue
    #pragma unroll
    for (int mi = 0; mi < 4; mi++) {
        int gr0 = bm + wm * 64 + mi * 16 + gq;
        int gr1 = gr0 + 8;
        const float *res0 = nullptr, *res1 = nullptr;
        if (MODE == 1) {
            int b0i = gr0 >> 12, t0 = gr0 & 4095;
            int b1i = gr1 >> 12, t1 = gr1 & 4095;
            res0 = (b0i < 4) ? (e0 + ((size_t)(b0i * SEQ + t0)) * DMODEL)
                             : (e1 + ((size_t)((b0i - 4) * SEQ + t0)) * DMODEL);
            res1 = (b1i < 4) ? (e0 + ((size_t)(b1i * SEQ + t1)) * DMODEL)
                             : (e1 + ((size_t)((b1i - 4) * SEQ + t1)) * DMODEL);
        }
        #pragma unroll
        for (int ni = 0; ni < 4; ni++) {
            int gc = bn + wn * 32 + ni * 8 + 2 * tq;
            if (gc >= N) continue;
            float v0 = acc[mi][ni][0], v1 = acc[mi][ni][1];
            float v2 = acc[mi][ni][2], v3 = acc[mi][ni][3];
            if (MODE == 0) {
                *(float2*)(C + (size_t)gr0 * N + gc) = make_float2(v0, v1);
                *(float2*)(C + (size_t)gr1 * N + gc) = make_float2(v2, v3);
            }
            if (MODE == 1) {
                v0 += res0[gc]; v1 += res0[gc + 1];
                v2 += res1[gc]; v3 += res1[gc + 1];
                *(float2*)(C + (size_t)gr0 * N + gc) = make_float2(v0, v1);
                *(float2*)(C + (size_t)gr1 * N + gc) = make_float2(v2, v3);
                *(__half2*)(g_sph + (size_t)gr0 * DMODEL + gc) = __floats2half2_rn(v0, v1);
                *(__half2*)(g_sph + (size_t)gr1 * DMODEL + gc) = __floats2half2_rn(v2, v3);
            }
            if (MODE == 2) {
                float bx = e0[gc], by = e0[gc + 1];
                v0 = siluf(v0 + bx); v1 = siluf(v1 + by);
                v2 = siluf(v2 + bx); v3 = siluf(v3 + by);
                *(__half2*)(g_hmh + (size_t)gr0 * DMODEL + gc) = __floats2half2_rn(v0, v1);
                *(__half2*)(g_hmh + (size_t)gr1 * DMODEL + gc) = __floats2half2_rn(v2, v3);
            }
            if (MODE == 3) {
                float bx = e0[gc], by = e0[gc + 1];
                const float* s0 = g_sp + (size_t)gr0 * DMODEL + gc;
                const float* s1 = g_sp + (size_t)gr1 * DMODEL + gc;
                v0 += bx + s0[0]; v1 += by + s0[1];
                v2 += bx + s1[0]; v3 += by + s1[1];
                *(float2*)(C + (size_t)gr0 * N + gc) = make_float2(v0, v1);
                *(float2*)(C + (size_t)gr1 * N + gc) = make_float2(v2, v3);
            }
        }
    }
}

// ---------------- launch ------------------------------------------------------
extern "C" void kernel_launch(void* const* d_in, const int* in_sizes, int n_in,
                              void* d_out, int out_size)
{
    const float* x0      = (const float*)d_in[0];
    const float* x1      = (const float*)d_in[1];
    const float* nsw     = (const float*)d_in[2];
    const float* nsb     = (const float*)d_in[3];
    const float* W_in    = (const float*)d_in[4];
    const float* conv_w  = (const float*)d_in[5];
    const float* conv_b  = (const float*)d_in[6];
    const float* dt_bias = (const float*)d_in[7];
    const float* A_log   = (const float*)d_in[8];
    const float* Dp      = (const float*)d_in[9];
    const float* rms_w   = (const float*)d_in[10];
    const float* W_out   = (const float*)d_in[11];
    const float* w1      = (const float*)d_in[12];
    const float* b1      = (const float*)d_in[13];
    const float* w2      = (const float*)d_in[14];
    const float* b2      = (const float*)d_in[15];
    const float* ntw     = (const float*)d_in[16];
    const float* ntb     = (const float*)d_in[17];
    float* out = (float*)d_out;

    float *p_zx, *p_sp, *p_u;
    cudaGetSymbolAddress((void**)&p_zx, g_zx);
    cudaGetSymbolAddress((void**)&p_sp, g_sp);
    cudaGetSymbolAddress((void**)&p_u,  g_u);
    __half *p_xnh, *p_ynh, *p_hmh;
    __half *p_Winh, *p_Winl, *p_Wouth, *p_w1h, *p_w2h;
    cudaGetSymbolAddress((void**)&p_xnh, g_xnh);
    cudaGetSymbolAddress((void**)&p_ynh, g_ynh);
    cudaGetSymbolAddress((void**)&p_hmh, g_hmh);
    cudaGetSymbolAddress((void**)&p_Winh,  g_Winh);
    cudaGetSymbolAddress((void**)&p_Winl,  g_Winl);
    cudaGetSymbolAddress((void**)&p_Wouth, g_Wouth);
    cudaGetSymbolAddress((void**)&p_w1h,   g_w1h);
    cudaGetSymbolAddress((void**)&p_w2h,   g_w2h);

    const int SM2 = NSTAGE * 3 * MATB;   // 92160 (NPROD=2)
    const int SM1 = NSTAGE * 2 * MATB;   // 61440 (NPROD=1)
    cudaFuncSetAttribute((const void*)gemm_mma<0, 2>, cudaFuncAttributeMaxDynamicSharedMemorySize, SM2);
    cudaFuncSetAttribute((const void*)gemm_mma<1, 1>, cudaFuncAttributeMaxDynamicSharedMemorySize, SM1);
    cudaFuncSetAttribute((const void*)gemm_mma<2, 1>, cudaFuncAttributeMaxDynamicSharedMemorySize, SM1);
    cudaFuncSetAttribute((const void*)gemm_mma<3, 1>, cudaFuncAttributeMaxDynamicSharedMemorySize, SM1);
    cudaFuncSetAttribute((const void*)scan_seg_kernel, cudaFuncAttributeMaxDynamicSharedMemorySize, SA_BYTES);
    cudaFuncSetAttribute((const void*)correct_kernel,  cudaFuncAttributeMaxDynamicSharedMemorySize, SC_BYTES);

    // #1: fused LayerNorm + weight convert
    pre_kernel<<<MTOT + 1160, 256>>>(x0, x1, nsw, nsb, W_in, W_out, w1, w2);

    // #2: in-proj GEMM (2-product): zxbcdt = xn @ W_in^T   (32768 x 1160 x 256)
    gemm_mma<0, 2><<<dim3((DPROJ + 127) / 128, MTOT / 128), 256, SM2>>>(
        p_xnh, p_Winh, p_Winl, p_zx, DPROJ, DMODEL, nullptr, nullptr);

    // #3: depthwise conv + SiLU
    conv_kernel<<<((MTOT / 4) * CONVDIM + 255) / 256, 256>>>(conv_w, conv_b);

    // #4: pass A — full-head segmented local scans, fp16 B/C  [ncu captures this]
    scan_seg_kernel<<<NSCANBLK, 256, SA_BYTES>>>(dt_bias, A_log, Dp);

    // #5: pass B — combine segment states
    combine_kernel<<<64, 256>>>();

    // #6: pass C — cross-segment correction
    correct_kernel<<<NSCANBLK, 256, SC_BYTES>>>();

    // #7: gate + RMSNorm -> fp16
    gate_rms_kernel<<<MTOT, 256>>>(rms_w);

    // #8: out-proj GEMM (1-product) + residual -> g_sp/g_sph
    gemm_mma<1, 1><<<dim3(2, MTOT / 128), 256, SM1>>>(
        p_ynh, p_Wouth, nullptr, p_sp, DMODEL, DINNER, x0, x1);

    // #9: MLP layer 1 (1-product, cross-concat gather) + SiLU -> g_hmh
    gemm_mma<2, 1><<<dim3(2, MTOT / 128), 256, SM1>>>(
        nullptr, p_w1h, nullptr, nullptr, DMODEL, DINNER, b1, nullptr);

    // #10: MLP layer 2 (1-product) + bias + g_sp residual -> g_u
    gemm_mma<3, 1><<<dim3(2, MTOT / 128), 256, SM1>>>(
        p_hmh, p_w2h, nullptr, p_u, DMODEL, DMODEL, b2, nullptr);

    // #11: final LayerNorm -> d_out
    ln_t_kernel<<<MTOT, 256>>>(ntw, ntb, out);

    (void)in_sizes; (void)n_in; (void)out_size;
}

// round 13
// speedup vs baseline: 2.7162x; 1.1610x over previous
#include <cuda_runtime.h>
#include <cuda_fp16.h>
#include <math.h>
#include <stdint.h>

#define SEQ      4096
#define DMODEL   256
#define DINNER   512
#define DSTATE   64
#define NHEADS   8
#define HEADDIM  64
#define CONVDIM  640
#define DPROJ    1160
#define MTOT     32768          // 8 * 4096 rows (concat of both batch stacks)
#define NSEG     32
#define SEGLEN   128            // SEQ / NSEG
#define NSCANBLK 2048           // 8b * 8h * 32seg (full head per block)

// ---------------- scratch (static device globals; no allocations allowed) ----
__device__ float g_zx   [(size_t)MTOT * DPROJ];
__device__ float g_xconv[(size_t)MTOT * CONVDIM];
__device__ float g_yraw [(size_t)MTOT * DINNER];
__device__ float g_sp   [(size_t)MTOT * DMODEL];
__device__ float g_u    [(size_t)MTOT * DMODEL];
__device__ float g_cda  [(size_t)MTOT * NHEADS];          // cumulative dA within segment
__device__ float g_hseg [(size_t)NSCANBLK * 4096];        // local end states per segment
__device__ float g_h0s  [(size_t)NSCANBLK * 4096];        // true start states per segment

// fp16 activations
__device__ __half g_xnh[(size_t)MTOT * DMODEL];
__device__ __half g_ynh[(size_t)MTOT * DINNER];
__device__ __half g_sph[(size_t)MTOT * DMODEL];
__device__ __half g_hmh[(size_t)MTOT * DMODEL];

// fp16 weights (in-proj keeps hi/lo split; others hi only)
__device__ __half g_Winh[DPROJ * DMODEL], g_Winl[DPROJ * DMODEL];
__device__ __half g_Wouth[DMODEL * DINNER];
__device__ __half g_w1h[DMODEL * DINNER];
__device__ __half g_w2h[DMODEL * DMODEL];

__device__ __forceinline__ float siluf(float x) {
    return x / (1.f + expf(-x));
}
__device__ __forceinline__ float2 h2f(uint32_t u) {
    __half2 h = *(__half2*)&u;
    return __half22float2(h);
}
__device__ __forceinline__ uint32_t smem_u32(const void* p) {
    uint32_t a;
    asm("{ .reg .u64 t; cvta.to.shared.u64 t, %1; cvt.u32.u64 %0, t; }" : "=r"(a) : "l"(p));
    return a;
}
#define LDSM4(d0, d1, d2, d3, a) \
    asm volatile("ldmatrix.sync.aligned.m8n8.x4.shared.b16 {%0,%1,%2,%3}, [%4];" \
                 : "=r"(d0), "=r"(d1), "=r"(d2), "=r"(d3) : "r"(a))
__device__ __forceinline__ void mma_fp16(float* d, const uint32_t* a, const uint32_t* b) {
    asm volatile(
        "mma.sync.aligned.m16n8k16.row.col.f32.f16.f16.f32 "
        "{%0,%1,%2,%3}, {%4,%5,%6,%7}, {%8,%9}, {%0,%1,%2,%3};"
        : "+f"(d[0]), "+f"(d[1]), "+f"(d[2]), "+f"(d[3])
        : "r"(a[0]), "r"(a[1]), "r"(a[2]), "r"(a[3]), "r"(b[0]), "r"(b[1]));
}

// ------ fused: LayerNorm(concat) -> fp16  PLUS weight conversion tail -------
__global__ void pre_kernel(const float* __restrict__ x0, const float* __restrict__ x1,
                           const float* __restrict__ w,  const float* __restrict__ bias,
                           const float* __restrict__ W_in, const float* __restrict__ W_out,
                           const float* __restrict__ w1,  const float* __restrict__ w2)
{
    int m = blockIdx.x;
    int n = threadIdx.x;
    if (m >= MTOT) {
        int i = (m - MTOT) * 256 + n;
        float v = W_in[i];
        __half h = __float2half(v);
        g_Winh[i] = h;
        g_Winl[i] = __float2half(v - __half2float(h));
        if (i < DMODEL * DINNER) {
            g_Wouth[i] = __float2half(W_out[i]);
            g_w1h[i]   = __float2half(w1[i]);
        }
        if (i < DMODEL * DMODEL) {
            g_w2h[i] = __float2half(w2[i]);
        }
        return;
    }
    int b = m >> 12;
    int t = m & 4095;
    const float* src = (b < 4) ? (x0 + ((size_t)(b * SEQ + t)) * DMODEL)
                               : (x1 + ((size_t)((b - 4) * SEQ + t)) * DMODEL);
    float v = src[n];
    float s = v, s2 = v * v;
    #pragma unroll
    for (int o = 16; o; o >>= 1) {
        s  += __shfl_xor_sync(0xffffffffu, s,  o);
        s2 += __shfl_xor_sync(0xffffffffu, s2, o);
    }
    __shared__ float rs[8], rs2[8];
    int wid = n >> 5, lid = n & 31;
    if (lid == 0) { rs[wid] = s; rs2[wid] = s2; }
    __syncthreads();
    float ts = 0.f, ts2 = 0.f;
    #pragma unroll
    for (int i = 0; i < 8; i++) { ts += rs[i]; ts2 += rs2[i]; }
    float mu  = ts  * (1.f / 256.f);
    float var = ts2 * (1.f / 256.f) - mu * mu;
    float r = rsqrtf(var + 1e-5f);
    float o = (v - mu) * r * w[n] + bias[n];
    g_xnh[(size_t)m * DMODEL + n] = __float2half(o);
}

// ---------------- final LayerNorm: g_u -> d_out ------------------------------
__global__ void ln_t_kernel(const float* __restrict__ w, const float* __restrict__ bias,
                            float* __restrict__ out)
{
    int m = blockIdx.x;
    int n = threadIdx.x;
    float v = g_u[(size_t)m * DMODEL + n];
    float s = v, s2 = v * v;
    #pragma unroll
    for (int o = 16; o; o >>= 1) {
        s  += __shfl_xor_sync(0xffffffffu, s,  o);
        s2 += __shfl_xor_sync(0xffffffffu, s2, o);
    }
    __shared__ float rs[8], rs2[8];
    int wid = n >> 5, lid = n & 31;
    if (lid == 0) { rs[wid] = s; rs2[wid] = s2; }
    __syncthreads();
    float ts = 0.f, ts2 = 0.f;
    #pragma unroll
    for (int i = 0; i < 8; i++) { ts += rs[i]; ts2 += rs2[i]; }
    float mu  = ts  * (1.f / 256.f);
    float var = ts2 * (1.f / 256.f) - mu * mu;
    float r = rsqrtf(var + 1e-5f);
    out[(size_t)m * DMODEL + n] = (v - mu) * r * w[n] + bias[n];
}

// ---------------- depthwise conv (k=4) + SiLU, 4 timesteps/thread -----------
__global__ void conv_kernel(const float* __restrict__ conv_w, const float* __restrict__ conv_b)
{
    int idx = blockIdx.x * blockDim.x + threadIdx.x;
    if (idx >= (MTOT / 4) * CONVDIM) return;
    int c  = idx % CONVDIM;
    int m4 = idx / CONVDIM;
    int b  = m4 >> 10;
    int t0 = (m4 & 1023) << 2;
    const float* base = g_zx + (size_t)(b * SEQ) * DPROJ + DINNER + c;
    float4 w4 = *(const float4*)(conv_w + c * 4);
    float bia = conv_b[c];
    float v[7];
    #pragma unroll
    for (int j = 0; j < 7; j++) {
        int tt = t0 - 3 + j;
        v[j] = (tt >= 0) ? base[(size_t)tt * DPROJ] : 0.f;
    }
    size_t obase = (size_t)(b * SEQ + t0) * CONVDIM + c;
    #pragma unroll
    for (int i = 0; i < 4; i++) {
        float acc = bia;
        acc = fmaf(v[i + 0], w4.x, acc);
        acc = fmaf(v[i + 1], w4.y, acc);
        acc = fmaf(v[i + 2], w4.z, acc);
        acc = fmaf(v[i + 3], w4.w, acc);
        g_xconv[obase + (size_t)i * CONVDIM] = siluf(acc);
    }
}

// ========== Pass A: segmented local scan, full head per block ================
// grid = 2048: blk = (b*8 + h)*32 + seg; block = 256: pl = tid>>2 in [0,64), nq = tid&3
#define SA_BYTES (16384 + 8192 + 8192 + 256 + 256)   // 33280
__global__ void __launch_bounds__(256) scan_seg_kernel(
    const float* __restrict__ dt_bias, const float* __restrict__ A_log,
    const float* __restrict__ D_param)
{
    extern __shared__ char smraw[];
    float*  sx  = (float*)smraw;                  // [64][64] fp32
    __half* sB  = (__half*)(smraw + 16384);       // [64][64] fp16
    __half* sC  = (__half*)(smraw + 24576);       // [64][64] fp16
    float*  sdt = (float*)(smraw + 32768);        // [64]
    float*  sdA = (float*)(smraw + 33024);        // [64]

    int blk = blockIdx.x;
    int seg = blk & 31;
    int h   = (blk >> 5) & 7;
    int b   = blk >> 8;
    int tid = threadIdx.x;
    int pl  = tid >> 2;
    int nq  = tid & 3;

    float hs[16];
    #pragma unroll
    for (int j = 0; j < 16; j++) hs[j] = 0.f;
    float cum = 1.f;

    float Dh  = D_param[h];
    float eA  = expf(A_log[h]);
    float dtb = dt_bias[h];
    const float* xbase = g_xconv + (size_t)b * SEQ * CONVDIM;
    int pofs = h * 64;
    int tseg = seg * SEGLEN;

    for (int c0 = tseg; c0 < tseg + SEGLEN; c0 += 64) {
        #pragma unroll
        for (int i = 0; i < 4; i++) {
            int idx = i * 256 + tid;            // 1024 = 64 t x 16 quads
            int t = idx >> 4, n4 = (idx & 15) * 4;
            const float* rowp = xbase + (size_t)(c0 + t) * CONVDIM;
            *(float4*)(sx + t * 64 + n4) = *(const float4*)(rowp + pofs + n4);
            float4 bv = *(const float4*)(rowp + 512 + n4);
            float4 cv = *(const float4*)(rowp + 576 + n4);
            __half2 b01 = __floats2half2_rn(bv.x, bv.y);
            __half2 b23 = __floats2half2_rn(bv.z, bv.w);
            __half2 c01 = __floats2half2_rn(cv.x, cv.y);
            __half2 c23 = __floats2half2_rn(cv.z, cv.w);
            *(uint2*)(sB + t * 64 + n4) = make_uint2(*(uint32_t*)&b01, *(uint32_t*)&b23);
            *(uint2*)(sC + t * 64 + n4) = make_uint2(*(uint32_t*)&c01, *(uint32_t*)&c23);
        }
        if (tid < 64) {
            float raw = g_zx[(size_t)(b * SEQ + c0 + tid) * DPROJ + (DPROJ - NHEADS) + h] + dtb;
            float dt = (raw > 20.f) ? raw : log1pf(expf(raw));
            sdt[tid] = dt;
            sdA[tid] = expf(-eA * dt);
        }
        __syncthreads();

        #pragma unroll 2
        for (int t = 0; t < 64; t++) {
            float dAv = sdA[t];
            float xv  = sx[t * 64 + pl];
            float dtx = sdt[t] * xv;
            const __half* bb = sB + t * 64 + nq * 16;
            const __half* cb = sC + t * 64 + nq * 16;
            uint4 bu0 = *(const uint4*)(bb);
            uint4 bu1 = *(const uint4*)(bb + 8);
            uint4 cu0 = *(const uint4*)(cb);
            uint4 cu1 = *(const uint4*)(cb + 8);
            float2 b0 = h2f(bu0.x), b1 = h2f(bu0.y), b2 = h2f(bu0.z), b3 = h2f(bu0.w);
            float2 b4 = h2f(bu1.x), b5 = h2f(bu1.y), b6 = h2f(bu1.z), b7 = h2f(bu1.w);
            float2 c0v = h2f(cu0.x), c1v = h2f(cu0.y), c2v = h2f(cu0.z), c3v = h2f(cu0.w);
            float2 c4v = h2f(cu1.x), c5v = h2f(cu1.y), c6v = h2f(cu1.z), c7v = h2f(cu1.w);
            hs[0]  = fmaf(dAv, hs[0],  dtx * b0.x);
            hs[1]  = fmaf(dAv, hs[1],  dtx * b0.y);
            hs[2]  = fmaf(dAv, hs[2],  dtx * b1.x);
            hs[3]  = fmaf(dAv, hs[3],  dtx * b1.y);
            hs[4]  = fmaf(dAv, hs[4],  dtx * b2.x);
            hs[5]  = fmaf(dAv, hs[5],  dtx * b2.y);
            hs[6]  = fmaf(dAv, hs[6],  dtx * b3.x);
            hs[7]  = fmaf(dAv, hs[7],  dtx * b3.y);
            hs[8]  = fmaf(dAv, hs[8],  dtx * b4.x);
            hs[9]  = fmaf(dAv, hs[9],  dtx * b4.y);
            hs[10] = fmaf(dAv, hs[10], dtx * b5.x);
            hs[11] = fmaf(dAv, hs[11], dtx * b5.y);
            hs[12] = fmaf(dAv, hs[12], dtx * b6.x);
            hs[13] = fmaf(dAv, hs[13], dtx * b6.y);
            hs[14] = fmaf(dAv, hs[14], dtx * b7.x);
            hs[15] = fmaf(dAv, hs[15], dtx * b7.y);
            float p0 = fmaf(hs[1],  c0v.y, hs[0]  * c0v.x);
            float p1 = fmaf(hs[3],  c1v.y, hs[2]  * c1v.x);
            float p2 = fmaf(hs[5],  c2v.y, hs[4]  * c2v.x);
            float p3 = fmaf(hs[7],  c3v.y, hs[6]  * c3v.x);
            float p4 = fmaf(hs[9],  c4v.y, hs[8]  * c4v.x);
            float p5 = fmaf(hs[11], c5v.y, hs[10] * c5v.x);
            float p6 = fmaf(hs[13], c6v.y, hs[12] * c6v.x);
            float p7 = fmaf(hs[15], c7v.y, hs[14] * c7v.x);
            float yp = ((p0 + p1) + (p2 + p3)) + ((p4 + p5) + (p6 + p7));
            yp += __shfl_xor_sync(0xffffffffu, yp, 1);
            yp += __shfl_xor_sync(0xffffffffu, yp, 2);
            cum *= dAv;
            if (nq == 0) {
                g_yraw[(size_t)(b * SEQ + c0 + t) * DINNER + pofs + pl] = fmaf(Dh, xv, yp);
            }
            if (tid == 0) {
                g_cda[(size_t)(b * SEQ + c0 + t) * NHEADS + h] = cum;
            }
        }
        __syncthreads();
    }

    size_t base = (size_t)blk * 4096 + pl * 64 + nq * 16;
    #pragma unroll
    for (int j = 0; j < 4; j++)
        *(float4*)(g_hseg + base + j * 4) = make_float4(hs[j*4], hs[j*4+1], hs[j*4+2], hs[j*4+3]);
}

// ========== Pass B: sequential combine across segments =======================
__global__ void __launch_bounds__(256) combine_kernel()
{
    int blk = blockIdx.x;
    int tid = threadIdx.x;
    int h = blk & 7;
    int b = blk >> 3;
    float hstart[16];
    #pragma unroll
    for (int j = 0; j < 16; j++) hstart[j] = 0.f;
    for (int s = 0; s < NSEG; s++) {
        size_t base = ((size_t)(blk * NSEG + s)) * 4096 + tid * 16;
        #pragma unroll
        for (int j = 0; j < 4; j++)
            *(float4*)(g_h0s + base + j * 4) =
                make_float4(hstart[j*4], hstart[j*4+1], hstart[j*4+2], hstart[j*4+3]);
        float P = g_cda[(size_t)(b * SEQ + s * SEGLEN + SEGLEN - 1) * NHEADS + h];
        #pragma unroll
        for (int j = 0; j < 4; j++) {
            float4 v = *(const float4*)(g_hseg + base + j * 4);
            hstart[j*4]   = fmaf(P, hstart[j*4],   v.x);
            hstart[j*4+1] = fmaf(P, hstart[j*4+1], v.y);
            hstart[j*4+2] = fmaf(P, hstart[j*4+2], v.z);
            hstart[j*4+3] = fmaf(P, hstart[j*4+3], v.w);
        }
    }
}

// ========== Pass C (tensor-core): y += cumdA_t * (C @ h0^T)[t,p] =============
// grid = 2048 (same decode as pass A); seg 0 exits. block = 256 (8 warps: 4t x 2p)
// SMEM: sCt half [128][72] | sH half [64][72] | scd [128]
#define SCROW 72
#define SC_BYTES (128 * SCROW * 2 + 64 * SCROW * 2 + 128 * 4)   // 18432+9216+512=28160
__global__ void __launch_bounds__(256) correct_kernel()
{
    int blk = blockIdx.x;
    int seg = blk & 31;
    if (seg == 0) return;
    extern __shared__ char smraw[];
    __half* sCt = (__half*)smraw;                      // [128][72]
    __half* sH  = (__half*)(smraw + 128 * SCROW * 2);  // [64][72]
    float*  scd = (float*)(smraw + 128 * SCROW * 2 + 64 * SCROW * 2);  // [128]

    int h   = (blk >> 5) & 7;
    int b   = blk >> 8;
    int tid = threadIdx.x;
    int wid = tid >> 5, lane = tid & 31;
    int wt  = wid >> 1, wp = wid & 1;     // 4 x 2 warp tiles (32t x 32p)
    int gq  = lane >> 2, tq = lane & 3;

    // stage C [128t x 64n] -> fp16
    {
        const float* Cb = g_xconv + ((size_t)(b * SEQ + seg * SEGLEN)) * CONVDIM + 576;
        #pragma unroll
        for (int i = 0; i < 8; i++) {
            int idx = i * 256 + tid;           // 2048 = 128 x 16 quads
            int t = idx >> 4, n4 = (idx & 15) * 4;
            float4 cv = *(const float4*)(Cb + (size_t)t * CONVDIM + n4);
            __half2 c01 = __floats2half2_rn(cv.x, cv.y);
            __half2 c23 = __floats2half2_rn(cv.z, cv.w);
            *(uint2*)(sCt + t * SCROW + n4) = make_uint2(*(uint32_t*)&c01, *(uint32_t*)&c23);
        }
    }
    // stage h0 [64p x 64n] -> fp16
    {
        const float* hb = g_h0s + (size_t)blk * 4096;
        #pragma unroll
        for (int i = 0; i < 4; i++) {
            int idx = i * 256 + tid;           // 1024 = 64 x 16 quads
            int p = idx >> 4, n4 = (idx & 15) * 4;
            float4 hv = *(const float4*)(hb + p * 64 + n4);
            __half2 h01 = __floats2half2_rn(hv.x, hv.y);
            __half2 h23 = __floats2half2_rn(hv.z, hv.w);
            *(uint2*)(sH + p * SCROW + n4) = make_uint2(*(uint32_t*)&h01, *(uint32_t*)&h23);
        }
    }
    if (tid < SEGLEN)
        scd[tid] = g_cda[(size_t)(b * SEQ + seg * SEGLEN + tid) * NHEADS + h];
    __syncthreads();

    float acc[2][4][4];
    #pragma unroll
    for (int mi = 0; mi < 2; mi++)
        #pragma unroll
        for (int ni = 0; ni < 4; ni++)
            #pragma unroll
            for (int r = 0; r < 4; r++) acc[mi][ni][r] = 0.f;

    uint32_t sc_base = smem_u32(sCt);
    uint32_t sh_base = smem_u32(sH);
    int q = lane >> 3, r = lane & 7;
    #pragma unroll
    for (int kc = 0; kc < 64; kc += 16) {
        uint32_t a[2][4];
        #pragma unroll
        for (int mi = 0; mi < 2; mi++) {
            int arow = wt * 32 + mi * 16 + (q & 1) * 8 + r;
            int acol = kc + (q >> 1) * 8;
            LDSM4(a[mi][0], a[mi][1], a[mi][2], a[mi][3],
                  sc_base + (arow * SCROW + acol) * 2);
        }
        uint32_t bf[4][2];
        #pragma unroll
        for (int nb = 0; nb < 2; nb++) {
            int brow = wp * 32 + nb * 16 + (q >> 1) * 8 + r;
            int bcol = kc + (q & 1) * 8;
            LDSM4(bf[2 * nb][0], bf[2 * nb][1], bf[2 * nb + 1][0], bf[2 * nb + 1][1],
                  sh_base + (brow * SCROW + bcol) * 2);
        }
        #pragma unroll
        for (int mi = 0; mi < 2; mi++)
            #pragma unroll
            for (int ni = 0; ni < 4; ni++)
                mma_fp16(acc[mi][ni], a[mi], bf[ni]);
    }

    int pofs = h * 64;
    #pragma unroll
    for (int mi = 0; mi < 2; mi++) {
        int t0 = wt * 32 + mi * 16 + gq;
        int t1 = t0 + 8;
        float s0 = scd[t0], s1 = scd[t1];
        float* y0 = g_yraw + (size_t)(b * SEQ + seg * SEGLEN + t0) * DINNER + pofs;
        float* y1 = g_yraw + (size_t)(b * SEQ + seg * SEGLEN + t1) * DINNER + pofs;
        #pragma unroll
        for (int ni = 0; ni < 4; ni++) {
            int p = wp * 32 + ni * 8 + 2 * tq;
            y0[p]     += s0 * acc[mi][ni][0];
            y0[p + 1] += s0 * acc[mi][ni][1];
            y1[p]     += s1 * acc[mi][ni][2];
            y1[p + 1] += s1 * acc[mi][ni][3];
        }
    }
}

// ---------------- gate with silu(z) + RMSNorm -> fp16 ------------------------
__global__ void gate_rms_kernel(const float* __restrict__ rms_w)
{
    int m = blockIdx.x;
    int tid = threadIdx.x;
    float yg[2];
    float s2 = 0.f;
    #pragma unroll
    for (int e = 0; e < 2; e++) {
        int i = tid + e * 256;
        float z = g_zx[(size_t)m * DPROJ + i];
        float y = g_yraw[(size_t)m * DINNER + i];
        float g = y * siluf(z);
        yg[e] = g;
        s2 += g * g;
    }
    #pragma unroll
    for (int o = 16; o; o >>= 1) s2 += __shfl_xor_sync(0xffffffffu, s2, o);
    __shared__ float rs[8];
    int wid = tid >> 5, lid = tid & 31;
    if (lid == 0) rs[wid] = s2;
    __syncthreads();
    float tot = 0.f;
    #pragma unroll
    for (int i = 0; i < 8; i++) tot += rs[i];
    float r = rsqrtf(tot * (1.f / 512.f) + 1e-5f);
    #pragma unroll
    for (int e = 0; e < 2; e++) {
        int i = tid + e * 256;
        g_ynh[(size_t)m * DINNER + i] = __float2half(yg[e] * r * rms_w[i]);
    }
}

// ======== pipelined fp16 mma.sync GEMM: C = A * (Bh [+ Bl])^T ================
#define CP16(dst, src, sz) \
    asm volatile("cp.async.cg.shared.global [%0], [%1], 16, %2;" \
                 :: "r"(dst), "l"(src), "r"(sz))
#define CP_COMMIT() asm volatile("cp.async.commit_group;" ::: "memory")
#define CP_WAIT1()  asm volatile("cp.async.wait_group 1;" ::: "memory")

#define ROWB     80
#define MATB     (128 * ROWB)        // 10240
#define NSTAGE   3

template <int MODE, int NPROD>
__global__ void __launch_bounds__(256, 2) gemm_mma(
    const __half* __restrict__ Ah,
    const __half* __restrict__ Bh, const __half* __restrict__ Bl,
    float* __restrict__ C, int N, int K,
    const float* __restrict__ e0, const float* __restrict__ e1)
{
    constexpr int STAGEB = (1 + NPROD) * MATB;
    extern __shared__ char smem[];
    uint32_t sb = smem_u32(smem);
    int tid  = threadIdx.x;
    int wid  = tid >> 5, lane = tid & 31;
    int wm   = wid >> 2, wn = wid & 3;
    int bm   = blockIdx.y * 128;
    int bn   = blockIdx.x * 128;
    int gq   = lane >> 2;
    int tq   = lane & 3;

    float acc[4][4][4];
    #pragma unroll
    for (int mi = 0; mi < 4; mi++)
        #pragma unroll
        for (int ni = 0; ni < 4; ni++)
            #pragma unroll
            for (int r = 0; r < 4; r++) acc[mi][ni][r] = 0.f;

    auto fill_stage = [&](int s, int k0) {
        uint32_t st = sb + s * STAGEB;
        #pragma unroll
        for (int j = 0; j < 2; j++) {
            int idx = j * 256 + tid;
            int row = idx >> 2, seg = idx & 3;
            const __half* sh;
            if (MODE == 2) {
                int gr = bm + row;
                int vv = gr >> 14;
                int base = gr & 16383;
                int kk = k0 + seg * 8;
                int usef1 = ((kk >= 256) ? 1 : 0) ^ vv;
                sh = g_sph + ((size_t)(base + (usef1 ? 16384 : 0))) * DMODEL + (kk & 255);
            } else {
                sh = Ah + (size_t)(bm + row) * K + k0 + seg * 8;
            }
            CP16(st + row * ROWB + seg * 16, sh, 16);
        }
        #pragma unroll
        for (int j = 0; j < 2; j++) {
            int idx = j * 256 + tid;
            int row = idx >> 2, seg = idx & 3;
            int gn = bn + row;
            int sz = (gn < N) ? 16 : 0;
            size_t off = (size_t)gn * K + k0 + seg * 8;
            uint32_t d = st + MATB + row * ROWB + seg * 16;
            CP16(d, Bh + off, sz);
            if (NPROD == 2) CP16(d + MATB, Bl + off, sz);
        }
    };

    auto compute_stage = [&](int s) {
        uint32_t stA = sb + s * STAGEB;
        uint32_t stB = stA + MATB;
        int q = lane >> 3, r = lane & 7;
        #pragma unroll
        for (int ks = 0; ks < 2; ks++) {
            int kc = ks * 16;
            uint32_t ah[4][4];
            #pragma unroll
            for (int mi = 0; mi < 4; mi++) {
                int arow = wm * 64 + mi * 16 + (q & 1) * 8 + r;
                int acol = kc + (q >> 1) * 8;
                LDSM4(ah[mi][0], ah[mi][1], ah[mi][2], ah[mi][3],
                      stA + arow * ROWB + acol * 2);
            }
            uint32_t bh[4][2], bl[4][2];
            #pragma unroll
            for (int nb = 0; nb < 2; nb++) {
                int brow = wn * 32 + nb * 16 + (q >> 1) * 8 + r;
                int bcol = kc + (q & 1) * 8;
                uint32_t bd = stB + brow * ROWB + bcol * 2;
                LDSM4(bh[2 * nb][0], bh[2 * nb][1], bh[2 * nb + 1][0], bh[2 * nb + 1][1], bd);
                if (NPROD == 2)
                    LDSM4(bl[2 * nb][0], bl[2 * nb][1], bl[2 * nb + 1][0], bl[2 * nb + 1][1], bd + MATB);
            }
            #pragma unroll
            for (int mi = 0; mi < 4; mi++)
                #pragma unroll
                for (int ni = 0; ni < 4; ni++) {
                    mma_fp16(acc[mi][ni], ah[mi], bh[ni]);
                    if (NPROD == 2) mma_fp16(acc[mi][ni], ah[mi], bl[ni]);
                }
        }
    };

    int nk = K >> 5;
    fill_stage(0, 0);  CP_COMMIT();
    fill_stage(1, 32); CP_COMMIT();

    for (int i = 0; i < nk; i++) {
        CP_WAIT1();
        __syncthreads();
        if (i + 2 < nk) fill_stage((i + 2) % NSTAGE, (i + 2) << 5);
        CP_COMMIT();
        compute_stage(i % NSTAGE);
    }

    // epilogue
    #pragma unroll
    for (int mi = 0; mi < 4; mi++) {
        int gr0 = bm + wm * 64 + mi * 16 + gq;
        int gr1 = gr0 + 8;
        const float *res0 = nullptr, *res1 = nullptr;
        if (MODE == 1) {
            int b0i = gr0 >> 12, t0 = gr0 & 4095;
            int b1i = gr1 >> 12, t1 = gr1 & 4095;
            res0 = (b0i < 4) ? (e0 + ((size_t)(b0i * SEQ + t0)) * DMODEL)
                             : (e1 + ((size_t)((b0i - 4) * SEQ + t0)) * DMODEL);
            res1 = (b1i < 4) ? (e0 + ((size_t)(b1i * SEQ + t1)) * DMODEL)
                             : (e1 + ((size_t)((b1i - 4) * SEQ + t1)) * DMODEL);
        }
        #pragma unroll
        for (int ni = 0; ni < 4; ni++) {
            int gc = bn + wn * 32 + ni * 8 + 2 * tq;
            if (gc >= N) continue;
            float v0 = acc[mi][ni][0], v1 = acc[mi][ni][1];
            float v2 = acc[mi][ni][2], v3 = acc[mi][ni][3];
            if (MODE == 0) {
                *(float2*)(C + (size_t)gr0 * N + gc) = make_float2(v0, v1);
                *(float2*)(C + (size_t)gr1 * N + gc) = make_float2(v2, v3);
            }
            if (MODE == 1) {
                v0 += res0[gc]; v1 += res0[gc + 1];
                v2 += res1[gc]; v3 += res1[gc + 1];
                *(float2*)(C + (size_t)gr0 * N + gc) = make_float2(v0, v1);
                *(float2*)(C + (size_t)gr1 * N + gc) = make_float2(v2, v3);
                *(__half2*)(g_sph + (size_t)gr0 * DMODEL + gc) = __floats2half2_rn(v0, v1);
                *(__half2*)(g_sph + (size_t)gr1 * DMODEL + gc) = __floats2half2_rn(v2, v3);
            }
            if (MODE == 2) {
                float bx = e0[gc], by = e0[gc + 1];
                v0 = siluf(v0 + bx); v1 = siluf(v1 + by);
                v2 = siluf(v2 + bx); v3 = siluf(v3 + by);
                *(__half2*)(g_hmh + (size_t)gr0 * DMODEL + gc) = __floats2half2_rn(v0, v1);
                *(__half2*)(g_hmh + (size_t)gr1 * DMODEL + gc) = __floats2half2_rn(v2, v3);
            }
            if (MODE == 3) {
                float bx = e0[gc], by = e0[gc + 1];
                const float* s0 = g_sp + (size_t)gr0 * DMODEL + gc;
                const float* s1 = g_sp + (size_t)gr1 * DMODEL + gc;
                v0 += bx + s0[0]; v1 += by + s0[1];
                v2 += bx + s1[0]; v3 += by + s1[1];
                *(float2*)(C + (size_t)gr0 * N + gc) = make_float2(v0, v1);
                *(float2*)(C + (size_t)gr1 * N + gc) = make_float2(v2, v3);
            }
        }
    }
}

// ---------------- launch ------------------------------------------------------
extern "C" void kernel_launch(void* const* d_in, const int* in_sizes, int n_in,
                              void* d_out, int out_size)
{
    const float* x0      = (const float*)d_in[0];
    const float* x1      = (const float*)d_in[1];
    const float* nsw     = (const float*)d_in[2];
    const float* nsb     = (const float*)d_in[3];
    const float* W_in    = (const float*)d_in[4];
    const float* conv_w  = (const float*)d_in[5];
    const float* conv_b  = (const float*)d_in[6];
    const float* dt_bias = (const float*)d_in[7];
    const float* A_log   = (const float*)d_in[8];
    const float* Dp      = (const float*)d_in[9];
    const float* rms_w   = (const float*)d_in[10];
    const float* W_out   = (const float*)d_in[11];
    const float* w1      = (const float*)d_in[12];
    const float* b1      = (const float*)d_in[13];
    const float* w2      = (const float*)d_in[14];
    const float* b2      = (const float*)d_in[15];
    const float* ntw     = (const float*)d_in[16];
    const float* ntb     = (const float*)d_in[17];
    float* out = (float*)d_out;

    float *p_zx, *p_sp, *p_u;
    cudaGetSymbolAddress((void**)&p_zx, g_zx);
    cudaGetSymbolAddress((void**)&p_sp, g_sp);
    cudaGetSymbolAddress((void**)&p_u,  g_u);
    __half *p_xnh, *p_ynh, *p_hmh;
    __half *p_Winh, *p_Winl, *p_Wouth, *p_w1h, *p_w2h;
    cudaGetSymbolAddress((void**)&p_xnh, g_xnh);
    cudaGetSymbolAddress((void**)&p_ynh, g_ynh);
    cudaGetSymbolAddress((void**)&p_hmh, g_hmh);
    cudaGetSymbolAddress((void**)&p_Winh,  g_Winh);
    cudaGetSymbolAddress((void**)&p_Winl,  g_Winl);
    cudaGetSymbolAddress((void**)&p_Wouth, g_Wouth);
    cudaGetSymbolAddress((void**)&p_w1h,   g_w1h);
    cudaGetSymbolAddress((void**)&p_w2h,   g_w2h);

    const int SM2 = NSTAGE * 3 * MATB;   // 92160 (NPROD=2)
    const int SM1 = NSTAGE * 2 * MATB;   // 61440 (NPROD=1)
    cudaFuncSetAttribute((const void*)gemm_mma<0, 2>, cudaFuncAttributeMaxDynamicSharedMemorySize, SM2);
    cudaFuncSetAttribute((const void*)gemm_mma<1, 1>, cudaFuncAttributeMaxDynamicSharedMemorySize, SM1);
    cudaFuncSetAttribute((const void*)gemm_mma<2, 1>, cudaFuncAttributeMaxDynamicSharedMemorySize, SM1);
    cudaFuncSetAttribute((const void*)gemm_mma<3, 1>, cudaFuncAttributeMaxDynamicSharedMemorySize, SM1);
    cudaFuncSetAttribute((const void*)scan_seg_kernel, cudaFuncAttributeMaxDynamicSharedMemorySize, SA_BYTES);
    cudaFuncSetAttribute((const void*)correct_kernel,  cudaFuncAttributeMaxDynamicSharedMemorySize, SC_BYTES);

    // #1: fused LayerNorm + weight convert
    pre_kernel<<<MTOT + 1160, 256>>>(x0, x1, nsw, nsb, W_in, W_out, w1, w2);

    // #2: in-proj GEMM (2-product): zxbcdt = xn @ W_in^T   (32768 x 1160 x 256)
    gemm_mma<0, 2><<<dim3((DPROJ + 127) / 128, MTOT / 128), 256, SM2>>>(
        p_xnh, p_Winh, p_Winl, p_zx, DPROJ, DMODEL, nullptr, nullptr);

    // #3: depthwise conv + SiLU
    conv_kernel<<<((MTOT / 4) * CONVDIM + 255) / 256, 256>>>(conv_w, conv_b);

    // #4: pass A — full-head segmented local scans, fp16 B/C  [ncu captures this]
    scan_seg_kernel<<<NSCANBLK, 256, SA_BYTES>>>(dt_bias, A_log, Dp);

    // #5: pass B — combine segment states
    combine_kernel<<<64, 256>>>();

    // #6: pass C — cross-segment correction via tensor cores
    correct_kernel<<<NSCANBLK, 256, SC_BYTES>>>();

    // #7: gate + RMSNorm -> fp16
    gate_rms_kernel<<<MTOT, 256>>>(rms_w);

    // #8: out-proj GEMM (1-product) + residual -> g_sp/g_sph
    gemm_mma<1, 1><<<dim3(2, MTOT / 128), 256, SM1>>>(
        p_ynh, p_Wouth, nullptr, p_sp, DMODEL, DINNER, x0, x1);

    // #9: MLP layer 1 (1-product, cross-concat gather) + SiLU -> g_hmh
    gemm_mma<2, 1><<<dim3(2, MTOT / 128), 256, SM1>>>(
        nullptr, p_w1h, nullptr, nullptr, DMODEL, DINNER, b1, nullptr);

    // #10: MLP layer 2 (1-product) + bias + g_sp residual -> g_u
    gemm_mma<3, 1><<<dim3(2, MTOT / 128), 256, SM1>>>(
        p_hmh, p_w2h, nullptr, p_u, DMODEL, DMODEL, b2, nullptr);

    // #11: final LayerNorm -> d_out
    ln_t_kernel<<<MTOT, 256>>>(ntw, ntb, out);

    (void)in_sizes; (void)n_in; (void)out_size;
}

// round 14
// speedup vs baseline: 2.7423x; 1.0096x over previous
#include <cuda_runtime.h>
#include <cuda_fp16.h>
#include <math.h>
#include <stdint.h>

#define SEQ      4096
#define DMODEL   256
#define DINNER   512
#define DSTATE   64
#define NHEADS   8
#define HEADDIM  64
#define CONVDIM  640
#define DPROJ    1160
#define MTOT     32768          // 8 * 4096 rows (concat of both batch stacks)
#define NSEG     32
#define SEGLEN   128            // SEQ / NSEG
#define NSCANBLK 2048           // 8b * 8h * 32seg (full head per block)

// ---------------- scratch (static device globals; no allocations allowed) ----
__device__ float  g_zx   [(size_t)MTOT * DPROJ];
__device__ __half g_xconv[(size_t)MTOT * CONVDIM];
__device__ float  g_yraw [(size_t)MTOT * DINNER];
__device__ float  g_sp   [(size_t)MTOT * DMODEL];
__device__ float  g_u    [(size_t)MTOT * DMODEL];
__device__ float  g_cda  [(size_t)MTOT * NHEADS];
__device__ float  g_hseg [(size_t)NSCANBLK * 4096];
__device__ float  g_h0s  [(size_t)NSCANBLK * 4096];

// fp16 activations
__device__ __half g_xnh[(size_t)MTOT * DMODEL];
__device__ __half g_ynh[(size_t)MTOT * DINNER];
__device__ __half g_sph[(size_t)MTOT * DMODEL];
__device__ __half g_hmh[(size_t)MTOT * DMODEL];

// fp16 weights (in-proj keeps hi/lo split; others hi only)
__device__ __half g_Winh[DPROJ * DMODEL], g_Winl[DPROJ * DMODEL];
__device__ __half g_Wouth[DMODEL * DINNER];
__device__ __half g_w1h[DMODEL * DINNER];
__device__ __half g_w2h[DMODEL * DMODEL];

__device__ __forceinline__ float siluf(float x) {
    return x / (1.f + expf(-x));
}
__device__ __forceinline__ float2 h2f(uint32_t u) {
    __half2 h = *(__half2*)&u;
    return __half22float2(h);
}
__device__ __forceinline__ uint32_t smem_u32(const void* p) {
    uint32_t a;
    asm("{ .reg .u64 t; cvta.to.shared.u64 t, %1; cvt.u32.u64 %0, t; }" : "=r"(a) : "l"(p));
    return a;
}
#define LDSM4(d0, d1, d2, d3, a) \
    asm volatile("ldmatrix.sync.aligned.m8n8.x4.shared.b16 {%0,%1,%2,%3}, [%4];" \
                 : "=r"(d0), "=r"(d1), "=r"(d2), "=r"(d3) : "r"(a))
__device__ __forceinline__ void mma_fp16(float* d, const uint32_t* a, const uint32_t* b) {
    asm volatile(
        "mma.sync.aligned.m16n8k16.row.col.f32.f16.f16.f32 "
        "{%0,%1,%2,%3}, {%4,%5,%6,%7}, {%8,%9}, {%0,%1,%2,%3};"
        : "+f"(d[0]), "+f"(d[1]), "+f"(d[2]), "+f"(d[3])
        : "r"(a[0]), "r"(a[1]), "r"(a[2]), "r"(a[3]), "r"(b[0]), "r"(b[1]));
}

// swizzle: logical n = nq*16 + s*4 + e  ->  phys = s*16 + nq*4 + e
__device__ __forceinline__ int bc_phys(int n) {
    return ((n >> 2) & 3) * 16 + (n >> 4) * 4 + (n & 3);
}

// ------ fused: LayerNorm(concat) -> fp16  PLUS weight conversion tail -------
__global__ void pre_kernel(const float* __restrict__ x0, const float* __restrict__ x1,
                           const float* __restrict__ w,  const float* __restrict__ bias,
                           const float* __restrict__ W_in, const float* __restrict__ W_out,
                           const float* __restrict__ w1,  const float* __restrict__ w2)
{
    int m = blockIdx.x;
    int n = threadIdx.x;
    if (m >= MTOT) {
        int i = (m - MTOT) * 256 + n;
        float v = W_in[i];
        __half h = __float2half(v);
        g_Winh[i] = h;
        g_Winl[i] = __float2half(v - __half2float(h));
        if (i < DMODEL * DINNER) {
            g_Wouth[i] = __float2half(W_out[i]);
            g_w1h[i]   = __float2half(w1[i]);
        }
        if (i < DMODEL * DMODEL) {
            g_w2h[i] = __float2half(w2[i]);
        }
        return;
    }
    int b = m >> 12;
    int t = m & 4095;
    const float* src = (b < 4) ? (x0 + ((size_t)(b * SEQ + t)) * DMODEL)
                               : (x1 + ((size_t)((b - 4) * SEQ + t)) * DMODEL);
    float v = src[n];
    float s = v, s2 = v * v;
    #pragma unroll
    for (int o = 16; o; o >>= 1) {
        s  += __shfl_xor_sync(0xffffffffu, s,  o);
        s2 += __shfl_xor_sync(0xffffffffu, s2, o);
    }
    __shared__ float rs[8], rs2[8];
    int wid = n >> 5, lid = n & 31;
    if (lid == 0) { rs[wid] = s; rs2[wid] = s2; }
    __syncthreads();
    float ts = 0.f, ts2 = 0.f;
    #pragma unroll
    for (int i = 0; i < 8; i++) { ts += rs[i]; ts2 += rs2[i]; }
    float mu  = ts  * (1.f / 256.f);
    float var = ts2 * (1.f / 256.f) - mu * mu;
    float r = rsqrtf(var + 1e-5f);
    float o = (v - mu) * r * w[n] + bias[n];
    g_xnh[(size_t)m * DMODEL + n] = __float2half(o);
}

// ---------------- final LayerNorm: g_u -> d_out ------------------------------
__global__ void ln_t_kernel(const float* __restrict__ w, const float* __restrict__ bias,
                            float* __restrict__ out)
{
    int m = blockIdx.x;
    int n = threadIdx.x;
    float v = g_u[(size_t)m * DMODEL + n];
    float s = v, s2 = v * v;
    #pragma unroll
    for (int o = 16; o; o >>= 1) {
        s  += __shfl_xor_sync(0xffffffffu, s,  o);
        s2 += __shfl_xor_sync(0xffffffffu, s2, o);
    }
    __shared__ float rs[8], rs2[8];
    int wid = n >> 5, lid = n & 31;
    if (lid == 0) { rs[wid] = s; rs2[wid] = s2; }
    __syncthreads();
    float ts = 0.f, ts2 = 0.f;
    #pragma unroll
    for (int i = 0; i < 8; i++) { ts += rs[i]; ts2 += rs2[i]; }
    float mu  = ts  * (1.f / 256.f);
    float var = ts2 * (1.f / 256.f) - mu * mu;
    float r = rsqrtf(var + 1e-5f);
    out[(size_t)m * DMODEL + n] = (v - mu) * r * w[n] + bias[n];
}

// ---------------- depthwise conv (k=4) + SiLU -> fp16, 4 timesteps/thread ---
__global__ void conv_kernel(const float* __restrict__ conv_w, const float* __restrict__ conv_b)
{
    int idx = blockIdx.x * blockDim.x + threadIdx.x;
    if (idx >= (MTOT / 4) * CONVDIM) return;
    int c  = idx % CONVDIM;
    int m4 = idx / CONVDIM;
    int b  = m4 >> 10;
    int t0 = (m4 & 1023) << 2;
    const float* base = g_zx + (size_t)(b * SEQ) * DPROJ + DINNER + c;
    float4 w4 = *(const float4*)(conv_w + c * 4);
    float bia = conv_b[c];
    float v[7];
    #pragma unroll
    for (int j = 0; j < 7; j++) {
        int tt = t0 - 3 + j;
        v[j] = (tt >= 0) ? base[(size_t)tt * DPROJ] : 0.f;
    }
    size_t obase = (size_t)(b * SEQ + t0) * CONVDIM + c;
    #pragma unroll
    for (int i = 0; i < 4; i++) {
        float acc = bia;
        acc = fmaf(v[i + 0], w4.x, acc);
        acc = fmaf(v[i + 1], w4.y, acc);
        acc = fmaf(v[i + 2], w4.z, acc);
        acc = fmaf(v[i + 3], w4.w, acc);
        g_xconv[obase + (size_t)i * CONVDIM] = __float2half(siluf(acc));
    }
}

// ========== Pass A: segmented local scan, full head per block ================
// grid = 2048: blk = (b*8 + h)*32 + seg; block = 256: pl = tid>>2, nq = tid&3
// SMEM: sx fp32 [64][64] | sB fp32 [64][64] swizzled | sC fp16 [64][64] | sdt, sdA
#define SA_BYTES (16384 + 16384 + 8192 + 256 + 256)   // 41472
__global__ void __launch_bounds__(256) scan_seg_kernel(
    const float* __restrict__ dt_bias, const float* __restrict__ A_log,
    const float* __restrict__ D_param)
{
    extern __shared__ char smraw[];
    float*  sx  = (float*)smraw;                  // [64][64] fp32
    float*  sB  = (float*)(smraw + 16384);        // [64][64] fp32 swizzled
    __half* sC  = (__half*)(smraw + 32768);       // [64][64] fp16
    float*  sdt = (float*)(smraw + 40960);        // [64]
    float*  sdA = (float*)(smraw + 41216);        // [64]

    int blk = blockIdx.x;
    int seg = blk & 31;
    int h   = (blk >> 5) & 7;
    int b   = blk >> 8;
    int tid = threadIdx.x;
    int pl  = tid >> 2;
    int nq  = tid & 3;

    float hs[16];
    #pragma unroll
    for (int j = 0; j < 16; j++) hs[j] = 0.f;
    float cum = 1.f;

    float Dh  = D_param[h];
    float eA  = expf(A_log[h]);
    float dtb = dt_bias[h];
    const __half* xbase = g_xconv + (size_t)b * SEQ * CONVDIM;
    int pofs = h * 64;
    int tseg = seg * SEGLEN;

    for (int c0 = tseg; c0 < tseg + SEGLEN; c0 += 64) {
        #pragma unroll
        for (int i = 0; i < 2; i++) {
            int idx = i * 256 + tid;            // 512 = 64 t x 8 groups of 8
            int t = idx >> 3, n8 = (idx & 7) * 8;
            const __half* rowp = xbase + (size_t)(c0 + t) * CONVDIM;
            uint4 xu = *(const uint4*)(rowp + pofs + n8);
            uint4 bu = *(const uint4*)(rowp + 512 + n8);
            uint4 cu = *(const uint4*)(rowp + 576 + n8);
            float2 x0v = h2f(xu.x), x1v = h2f(xu.y), x2v = h2f(xu.z), x3v = h2f(xu.w);
            *(float4*)(sx + t * 64 + n8)     = make_float4(x0v.x, x0v.y, x1v.x, x1v.y);
            *(float4*)(sx + t * 64 + n8 + 4) = make_float4(x2v.x, x2v.y, x3v.x, x3v.y);
            float2 b0v = h2f(bu.x), b1v = h2f(bu.y), b2v = h2f(bu.z), b3v = h2f(bu.w);
            *(float4*)(sB + t * 64 + bc_phys(n8))     = make_float4(b0v.x, b0v.y, b1v.x, b1v.y);
            *(float4*)(sB + t * 64 + bc_phys(n8 + 4)) = make_float4(b2v.x, b2v.y, b3v.x, b3v.y);
            *(uint4*)(sC + t * 64 + n8) = cu;
        }
        if (tid < 64) {
            float raw = g_zx[(size_t)(b * SEQ + c0 + tid) * DPROJ + (DPROJ - NHEADS) + h] + dtb;
            float dt = (raw > 20.f) ? raw : log1pf(expf(raw));
            sdt[tid] = dt;
            sdA[tid] = expf(-eA * dt);
        }
        __syncthreads();

        #pragma unroll 2
        for (int t = 0; t < 64; t++) {
            float dAv = sdA[t];
            float xv  = sx[t * 64 + pl];
            float dtx = sdt[t] * xv;
            const float* bp = sB + t * 64 + nq * 4;
            float4 B0 = *(const float4*)(bp);
            float4 B1 = *(const float4*)(bp + 16);
            float4 B2 = *(const float4*)(bp + 32);
            float4 B3 = *(const float4*)(bp + 48);
            const __half* cb = sC + t * 64 + nq * 16;
            uint4 cu0 = *(const uint4*)(cb);
            uint4 cu1 = *(const uint4*)(cb + 8);
            float2 c0v = h2f(cu0.x), c1v = h2f(cu0.y), c2v = h2f(cu0.z), c3v = h2f(cu0.w);
            float2 c4v = h2f(cu1.x), c5v = h2f(cu1.y), c6v = h2f(cu1.z), c7v = h2f(cu1.w);
            hs[0]  = fmaf(dAv, hs[0],  dtx * B0.x);
            hs[1]  = fmaf(dAv, hs[1],  dtx * B0.y);
            hs[2]  = fmaf(dAv, hs[2],  dtx * B0.z);
            hs[3]  = fmaf(dAv, hs[3],  dtx * B0.w);
            hs[4]  = fmaf(dAv, hs[4],  dtx * B1.x);
            hs[5]  = fmaf(dAv, hs[5],  dtx * B1.y);
            hs[6]  = fmaf(dAv, hs[6],  dtx * B1.z);
            hs[7]  = fmaf(dAv, hs[7],  dtx * B1.w);
            hs[8]  = fmaf(dAv, hs[8],  dtx * B2.x);
            hs[9]  = fmaf(dAv, hs[9],  dtx * B2.y);
            hs[10] = fmaf(dAv, hs[10], dtx * B2.z);
            hs[11] = fmaf(dAv, hs[11], dtx * B2.w);
            hs[12] = fmaf(dAv, hs[12], dtx * B3.x);
            hs[13] = fmaf(dAv, hs[13], dtx * B3.y);
            hs[14] = fmaf(dAv, hs[14], dtx * B3.z);
            hs[15] = fmaf(dAv, hs[15], dtx * B3.w);
            float p0 = fmaf(hs[1],  c0v.y, hs[0]  * c0v.x);
            float p1 = fmaf(hs[3],  c1v.y, hs[2]  * c1v.x);
            float p2 = fmaf(hs[5],  c2v.y, hs[4]  * c2v.x);
            float p3 = fmaf(hs[7],  c3v.y, hs[6]  * c3v.x);
            float p4 = fmaf(hs[9],  c4v.y, hs[8]  * c4v.x);
            float p5 = fmaf(hs[11], c5v.y, hs[10] * c5v.x);
            float p6 = fmaf(hs[13], c6v.y, hs[12] * c6v.x);
            float p7 = fmaf(hs[15], c7v.y, hs[14] * c7v.x);
            float yp = ((p0 + p1) + (p2 + p3)) + ((p4 + p5) + (p6 + p7));
            yp += __shfl_xor_sync(0xffffffffu, yp, 1);
            yp += __shfl_xor_sync(0xffffffffu, yp, 2);
            cum *= dAv;
            if (nq == 0) {
                g_yraw[(size_t)(b * SEQ + c0 + t) * DINNER + pofs + pl] = fmaf(Dh, xv, yp);
            }
            if (tid == 0) {
                g_cda[(size_t)(b * SEQ + c0 + t) * NHEADS + h] = cum;
            }
        }
        __syncthreads();
    }

    size_t base = (size_t)blk * 4096 + pl * 64 + nq * 16;
    #pragma unroll
    for (int j = 0; j < 4; j++)
        *(float4*)(g_hseg + base + j * 4) = make_float4(hs[j*4], hs[j*4+1], hs[j*4+2], hs[j*4+3]);
}

// ========== Pass B: sequential combine across segments =======================
__global__ void __launch_bounds__(256) combine_kernel()
{
    int blk = blockIdx.x;
    int tid = threadIdx.x;
    int h = blk & 7;
    int b = blk >> 3;
    float hstart[16];
    #pragma unroll
    for (int j = 0; j < 16; j++) hstart[j] = 0.f;
    for (int s = 0; s < NSEG; s++) {
        size_t base = ((size_t)(blk * NSEG + s)) * 4096 + tid * 16;
        #pragma unroll
        for (int j = 0; j < 4; j++)
            *(float4*)(g_h0s + base + j * 4) =
                make_float4(hstart[j*4], hstart[j*4+1], hstart[j*4+2], hstart[j*4+3]);
        float P = g_cda[(size_t)(b * SEQ + s * SEGLEN + SEGLEN - 1) * NHEADS + h];
        #pragma unroll
        for (int j = 0; j < 4; j++) {
            float4 v = *(const float4*)(g_hseg + base + j * 4);
            hstart[j*4]   = fmaf(P, hstart[j*4],   v.x);
            hstart[j*4+1] = fmaf(P, hstart[j*4+1], v.y);
            hstart[j*4+2] = fmaf(P, hstart[j*4+2], v.z);
            hstart[j*4+3] = fmaf(P, hstart[j*4+3], v.w);
        }
    }
}

// ========== Pass C (tensor-core): y += cumdA_t * (C @ h0^T)[t,p] =============
#define SCROW 72
#define SC_BYTES (128 * SCROW * 2 + 64 * SCROW * 2 + 128 * 4)   // 28160
__global__ void __launch_bounds__(256) correct_kernel()
{
    int blk = blockIdx.x;
    int seg = blk & 31;
    if (seg == 0) return;
    extern __shared__ char smraw[];
    __half* sCt = (__half*)smraw;                      // [128][72]
    __half* sH  = (__half*)(smraw + 128 * SCROW * 2);  // [64][72]
    float*  scd = (float*)(smraw + 128 * SCROW * 2 + 64 * SCROW * 2);  // [128]

    int h   = (blk >> 5) & 7;
    int b   = blk >> 8;
    int tid = threadIdx.x;
    int wid = tid >> 5, lane = tid & 31;
    int wt  = wid >> 1, wp = wid & 1;
    int gq  = lane >> 2, tq = lane & 3;

    // stage C [128t x 64n] (already fp16 — raw copy)
    {
        const __half* Cb = g_xconv + ((size_t)(b * SEQ + seg * SEGLEN)) * CONVDIM + 576;
        #pragma unroll
        for (int i = 0; i < 4; i++) {
            int idx = i * 256 + tid;           // 1024 = 128 x 8 groups
            int t = idx >> 3, n8 = (idx & 7) * 8;
            *(uint4*)(sCt + t * SCROW + n8) = *(const uint4*)(Cb + (size_t)t * CONVDIM + n8);
        }
    }
    // stage h0 [64p x 64n] -> fp16
    {
        const float* hb = g_h0s + (size_t)blk * 4096;
        #pragma unroll
        for (int i = 0; i < 4; i++) {
            int idx = i * 256 + tid;
            int p = idx >> 4, n4 = (idx & 15) * 4;
            float4 hv = *(const float4*)(hb + p * 64 + n4);
            __half2 h01 = __floats2half2_rn(hv.x, hv.y);
            __half2 h23 = __floats2half2_rn(hv.z, hv.w);
            *(uint2*)(sH + p * SCROW + n4) = make_uint2(*(uint32_t*)&h01, *(uint32_t*)&h23);
        }
    }
    if (tid < SEGLEN)
        scd[tid] = g_cda[(size_t)(b * SEQ + seg * SEGLEN + tid) * NHEADS + h];
    __syncthreads();

    float acc[2][4][4];
    #pragma unroll
    for (int mi = 0; mi < 2; mi++)
        #pragma unroll
        for (int ni = 0; ni < 4; ni++)
            #pragma unroll
            for (int r = 0; r < 4; r++) acc[mi][ni][r] = 0.f;

    uint32_t sc_base = smem_u32(sCt);
    uint32_t sh_base = smem_u32(sH);
    int q = lane >> 3, r = lane & 7;
    #pragma unroll
    for (int kc = 0; kc < 64; kc += 16) {
        uint32_t a[2][4];
        #pragma unroll
        for (int mi = 0; mi < 2; mi++) {
            int arow = wt * 32 + mi * 16 + (q & 1) * 8 + r;
            int acol = kc + (q >> 1) * 8;
            LDSM4(a[mi][0], a[mi][1], a[mi][2], a[mi][3],
                  sc_base + (arow * SCROW + acol) * 2);
        }
        uint32_t bf[4][2];
        #pragma unroll
        for (int nb = 0; nb < 2; nb++) {
            int brow = wp * 32 + nb * 16 + (q >> 1) * 8 + r;
            int bcol = kc + (q & 1) * 8;
            LDSM4(bf[2 * nb][0], bf[2 * nb][1], bf[2 * nb + 1][0], bf[2 * nb + 1][1],
                  sh_base + (brow * SCROW + bcol) * 2);
        }
        #pragma unroll
        for (int mi = 0; mi < 2; mi++)
            #pragma unroll
            for (int ni = 0; ni < 4; ni++)
                mma_fp16(acc[mi][ni], a[mi], bf[ni]);
    }

    int pofs = h * 64;
    #pragma unroll
    for (int mi = 0; mi < 2; mi++) {
        int t0 = wt * 32 + mi * 16 + gq;
        int t1 = t0 + 8;
        float s0 = scd[t0], s1 = scd[t1];
        float* y0 = g_yraw + (size_t)(b * SEQ + seg * SEGLEN + t0) * DINNER + pofs;
        float* y1 = g_yraw + (size_t)(b * SEQ + seg * SEGLEN + t1) * DINNER + pofs;
        #pragma unroll
        for (int ni = 0; ni < 4; ni++) {
            int p = wp * 32 + ni * 8 + 2 * tq;
            y0[p]     += s0 * acc[mi][ni][0];
            y0[p + 1] += s0 * acc[mi][ni][1];
            y1[p]     += s1 * acc[mi][ni][2];
            y1[p + 1] += s1 * acc[mi][ni][3];
        }
    }
}

// ---------------- gate with silu(z) + RMSNorm -> fp16 ------------------------
__global__ void gate_rms_kernel(const float* __restrict__ rms_w)
{
    int m = blockIdx.x;
    int tid = threadIdx.x;
    float yg[2];
    float s2 = 0.f;
    #pragma unroll
    for (int e = 0; e < 2; e++) {
        int i = tid + e * 256;
        float z = g_zx[(size_t)m * DPROJ + i];
        float y = g_yraw[(size_t)m * DINNER + i];
        float g = y * siluf(z);
        yg[e] = g;
        s2 += g * g;
    }
    #pragma unroll
    for (int o = 16; o; o >>= 1) s2 += __shfl_xor_sync(0xffffffffu, s2, o);
    __shared__ float rs[8];
    int wid = tid >> 5, lid = tid & 31;
    if (lid == 0) rs[wid] = s2;
    __syncthreads();
    float tot = 0.f;
    #pragma unroll
    for (int i = 0; i < 8; i++) tot += rs[i];
    float r = rsqrtf(tot * (1.f / 512.f) + 1e-5f);
    #pragma unroll
    for (int e = 0; e < 2; e++) {
        int i = tid + e * 256;
        g_ynh[(size_t)m * DINNER + i] = __float2half(yg[e] * r * rms_w[i]);
    }
}

// ======== pipelined fp16 mma.sync GEMM: C = A * (Bh [+ Bl])^T ================
#define CP16(dst, src, sz) \
    asm volatile("cp.async.cg.shared.global [%0], [%1], 16, %2;" \
                 :: "r"(dst), "l"(src), "r"(sz))
#define CP_COMMIT() asm volatile("cp.async.commit_group;" ::: "memory")
template <int N>
__device__ __forceinline__ void cp_wait() {
    asm volatile("cp.async.wait_group %0;" :: "n"(N) : "memory");
}

#define ROWB     80
#define MATB     (128 * ROWB)        // 10240

template <int MODE, int NPROD, int NST>
__global__ void __launch_bounds__(256, 2) gemm_mma(
    const __half* __restrict__ Ah,
    const __half* __restrict__ Bh, const __half* __restrict__ Bl,
    float* __restrict__ C, int N, int K,
    const float* __restrict__ e0, const float* __restrict__ e1)
{
    constexpr int STAGEB = (1 + NPROD) * MATB;
    extern __shared__ char smem[];
    uint32_t sb = smem_u32(smem);
    int tid  = threadIdx.x;
    int wid  = tid >> 5, lane = tid & 31;
    int wm   = wid >> 2, wn = wid & 3;
    int bm   = blockIdx.y * 128;
    int bn   = blockIdx.x * 128;
    int gq   = lane >> 2;
    int tq   = lane & 3;

    float acc[4][4][4];
    #pragma unroll
    for (int mi = 0; mi < 4; mi++)
        #pragma unroll
        for (int ni = 0; ni < 4; ni++)
            #pragma unroll
            for (int r = 0; r < 4; r++) acc[mi][ni][r] = 0.f;

    auto fill_stage = [&](int s, int k0) {
        uint32_t st = sb + s * STAGEB;
        #pragma unroll
        for (int j = 0; j < 2; j++) {
            int idx = j * 256 + tid;
            int row = idx >> 2, seg = idx & 3;
            const __half* sh;
            if (MODE == 2) {
                int gr = bm + row;
                int vv = gr >> 14;
                int base = gr & 16383;
                int kk = k0 + seg * 8;
                int usef1 = ((kk >= 256) ? 1 : 0) ^ vv;
                sh = g_sph + ((size_t)(base + (usef1 ? 16384 : 0))) * DMODEL + (kk & 255);
            } else {
                sh = Ah + (size_t)(bm + row) * K + k0 + seg * 8;
            }
            CP16(st + row * ROWB + seg * 16, sh, 16);
        }
        #pragma unroll
        for (int j = 0; j < 2; j++) {
            int idx = j * 256 + tid;
            int row = idx >> 2, seg = idx & 3;
            int gn = bn + row;
            int sz = (gn < N) ? 16 : 0;
            size_t off = (size_t)gn * K + k0 + seg * 8;
            uint32_t d = st + MATB + row * ROWB + seg * 16;
            CP16(d, Bh + off, sz);
            if (NPROD == 2) CP16(d + MATB, Bl + off, sz);
        }
    };

    auto compute_stage = [&](int s) {
        uint32_t stA = sb + s * STAGEB;
        uint32_t stB = stA + MATB;
        int q = lane >> 3, r = lane & 7;
        #pragma unroll
        for (int ks = 0; ks < 2; ks++) {
            int kc = ks * 16;
            uint32_t ah[4][4];
            #pragma unroll
            for (int mi = 0; mi < 4; mi++) {
                int arow = wm * 64 + mi * 16 + (q & 1) * 8 + r;
                int acol = kc + (q >> 1) * 8;
                LDSM4(ah[mi][0], ah[mi][1], ah[mi][2], ah[mi][3],
                      stA + arow * ROWB + acol * 2);
            }
            uint32_t bh[4][2], bl[4][2];
            #pragma unroll
            for (int nb = 0; nb < 2; nb++) {
                int brow = wn * 32 + nb * 16 + (q >> 1) * 8 + r;
                int bcol = kc + (q & 1) * 8;
                uint32_t bd = stB + brow * ROWB + bcol * 2;
                LDSM4(bh[2 * nb][0], bh[2 * nb][1], bh[2 * nb + 1][0], bh[2 * nb + 1][1], bd);
                if (NPROD == 2)
                    LDSM4(bl[2 * nb][0], bl[2 * nb][1], bl[2 * nb + 1][0], bl[2 * nb + 1][1], bd + MATB);
            }
            #pragma unroll
            for (int mi = 0; mi < 4; mi++)
                #pragma unroll
                for (int ni = 0; ni < 4; ni++) {
                    mma_fp16(acc[mi][ni], ah[mi], bh[ni]);
                    if (NPROD == 2) mma_fp16(acc[mi][ni], ah[mi], bl[ni]);
                }
        }
    };

    int nk = K >> 5;
    #pragma unroll
    for (int s = 0; s < NST - 1; s++) {
        if (s < nk) { fill_stage(s, s << 5); }
        CP_COMMIT();
    }
    for (int i = 0; i < nk; i++) {
        cp_wait<NST - 2>();
        __syncthreads();
        if (i + NST - 1 < nk) fill_stage((i + NST - 1) % NST, (i + NST - 1) << 5);
        CP_COMMIT();
        compute_stage(i % NST);
    }

    // epilogue
    #pragma unroll
    for (int mi = 0; mi < 4; mi++) {
        int gr0 = bm + wm * 64 + mi * 16 + gq;
        int gr1 = gr0 + 8;
        const float *res0 = nullptr, *res1 = nullptr;
        if (MODE == 1) {
            int b0i = gr0 >> 12, t0 = gr0 & 4095;
            int b1i = gr1 >> 12, t1 = gr1 & 4095;
            res0 = (b0i < 4) ? (e0 + ((size_t)(b0i * SEQ + t0)) * DMODEL)
                             : (e1 + ((size_t)((b0i - 4) * SEQ + t0)) * DMODEL);
            res1 = (b1i < 4) ? (e0 + ((size_t)(b1i * SEQ + t1)) * DMODEL)
                             : (e1 + ((size_t)((b1i - 4) * SEQ + t1)) * DMODEL);
        }
        #pragma unroll
        for (int ni = 0; ni < 4; ni++) {
            int gc = bn + wn * 32 + ni * 8 + 2 * tq;
            if (gc >= N) continue;
            float v0 = acc[mi][ni][0], v1 = acc[mi][ni][1];
            float v2 = acc[mi][ni][2], v3 = acc[mi][ni][3];
            if (MODE == 0) {
                *(float2*)(C + (size_t)gr0 * N + gc) = make_float2(v0, v1);
                *(float2*)(C + (size_t)gr1 * N + gc) = make_float2(v2, v3);
            }
            if (MODE == 1) {
                v0 += res0[gc]; v1 += res0[gc + 1];
                v2 += res1[gc]; v3 += res1[gc + 1];
                *(float2*)(C + (size_t)gr0 * N + gc) = make_float2(v0, v1);
                *(float2*)(C + (size_t)gr1 * N + gc) = make_float2(v2, v3);
                *(__half2*)(g_sph + (size_t)gr0 * DMODEL + gc) = __floats2half2_rn(v0, v1);
                *(__half2*)(g_sph + (size_t)gr1 * DMODEL + gc) = __floats2half2_rn(v2, v3);
            }
            if (MODE == 2) {
                float bx = e0[gc], by = e0[gc + 1];
                v0 = siluf(v0 + bx); v1 = siluf(v1 + by);
                v2 = siluf(v2 + bx); v3 = siluf(v3 + by);
                *(__half2*)(g_hmh + (size_t)gr0 * DMODEL + gc) = __floats2half2_rn(v0, v1);
                *(__half2*)(g_hmh + (size_t)gr1 * DMODEL + gc) = __floats2half2_rn(v2, v3);
            }
            if (MODE == 3) {
                float bx = e0[gc], by = e0[gc + 1];
                const float* s0 = g_sp + (size_t)gr0 * DMODEL + gc;
                const float* s1 = g_sp + (size_t)gr1 * DMODEL + gc;
                v0 += bx + s0[0]; v1 += by + s0[1];
                v2 += bx + s1[0]; v3 += by + s1[1];
                *(float2*)(C + (size_t)gr0 * N + gc) = make_float2(v0, v1);
                *(float2*)(C + (size_t)gr1 * N + gc) = make_float2(v2, v3);
            }
        }
    }
}

// ---------------- launch ------------------------------------------------------
extern "C" void kernel_launch(void* const* d_in, const int* in_sizes, int n_in,
                              void* d_out, int out_size)
{
    const float* x0      = (const float*)d_in[0];
    const float* x1      = (const float*)d_in[1];
    const float* nsw     = (const float*)d_in[2];
    const float* nsb     = (const float*)d_in[3];
    const float* W_in    = (const float*)d_in[4];
    const float* conv_w  = (const float*)d_in[5];
    const float* conv_b  = (const float*)d_in[6];
    const float* dt_bias = (const float*)d_in[7];
    const float* A_log   = (const float*)d_in[8];
    const float* Dp      = (const float*)d_in[9];
    const float* rms_w   = (const float*)d_in[10];
    const float* W_out   = (const float*)d_in[11];
    const float* w1      = (const float*)d_in[12];
    const float* b1      = (const float*)d_in[13];
    const float* w2      = (const float*)d_in[14];
    const float* b2      = (const float*)d_in[15];
    const float* ntw     = (const float*)d_in[16];
    const float* ntb     = (const float*)d_in[17];
    float* out = (float*)d_out;

    float *p_zx, *p_sp, *p_u;
    cudaGetSymbolAddress((void**)&p_zx, g_zx);
    cudaGetSymbolAddress((void**)&p_sp, g_sp);
    cudaGetSymbolAddress((void**)&p_u,  g_u);
    __half *p_xnh, *p_ynh, *p_hmh;
    __half *p_Winh, *p_Winl, *p_Wouth, *p_w1h, *p_w2h;
    cudaGetSymbolAddress((void**)&p_xnh, g_xnh);
    cudaGetSymbolAddress((void**)&p_ynh, g_ynh);
    cudaGetSymbolAddress((void**)&p_hmh, g_hmh);
    cudaGetSymbolAddress((void**)&p_Winh,  g_Winh);
    cudaGetSymbolAddress((void**)&p_Winl,  g_Winl);
    cudaGetSymbolAddress((void**)&p_Wouth, g_Wouth);
    cudaGetSymbolAddress((void**)&p_w1h,   g_w1h);
    cudaGetSymbolAddress((void**)&p_w2h,   g_w2h);

    const int SM22 = 2 * 3 * MATB;   // 61440 (NPROD=2, NST=2)
    const int SM13 = 3 * 2 * MATB;   // 61440 (NPROD=1, NST=3)
    cudaFuncSetAttribute((const void*)gemm_mma<0, 2, 2>, cudaFuncAttributeMaxDynamicSharedMemorySize, SM22);
    cudaFuncSetAttribute((const void*)gemm_mma<1, 1, 3>, cudaFuncAttributeMaxDynamicSharedMemorySize, SM13);
    cudaFuncSetAttribute((const void*)gemm_mma<2, 1, 3>, cudaFuncAttributeMaxDynamicSharedMemorySize, SM13);
    cudaFuncSetAttribute((const void*)gemm_mma<3, 1, 3>, cudaFuncAttributeMaxDynamicSharedMemorySize, SM13);
    cudaFuncSetAttribute((const void*)scan_seg_kernel, cudaFuncAttributeMaxDynamicSharedMemorySize, SA_BYTES);
    cudaFuncSetAttribute((const void*)correct_kernel,  cudaFuncAttributeMaxDynamicSharedMemorySize, SC_BYTES);

    // #1: fused LayerNorm + weight convert
    pre_kernel<<<MTOT + 1160, 256>>>(x0, x1, nsw, nsb, W_in, W_out, w1, w2);

    // #2: in-proj GEMM (2-product, 2-stage): zxbcdt = xn @ W_in^T
    gemm_mma<0, 2, 2><<<dim3((DPROJ + 127) / 128, MTOT / 128), 256, SM22>>>(
        p_xnh, p_Winh, p_Winl, p_zx, DPROJ, DMODEL, nullptr, nullptr);

    // #3: depthwise conv + SiLU -> fp16
    conv_kernel<<<((MTOT / 4) * CONVDIM + 255) / 256, 256>>>(conv_w, conv_b);

    // #4: pass A — full-head segmented local scans  [ncu captures this]
    scan_seg_kernel<<<NSCANBLK, 256, SA_BYTES>>>(dt_bias, A_log, Dp);

    // #5: pass B — combine segment states
    combine_kernel<<<64, 256>>>();

    // #6: pass C — cross-segment correction via tensor cores
    correct_kernel<<<NSCANBLK, 256, SC_BYTES>>>();

    // #7: gate + RMSNorm -> fp16
    gate_rms_kernel<<<MTOT, 256>>>(rms_w);

    // #8: out-proj GEMM (1-product) + residual -> g_sp/g_sph
    gemm_mma<1, 1, 3><<<dim3(2, MTOT / 128), 256, SM13>>>(
        p_ynh, p_Wouth, nullptr, p_sp, DMODEL, DINNER, x0, x1);

    // #9: MLP layer 1 (1-product, cross-concat gather) + SiLU -> g_hmh
    gemm_mma<2, 1, 3><<<dim3(2, MTOT / 128), 256, SM13>>>(
        nullptr, p_w1h, nullptr, nullptr, DMODEL, DINNER, b1, nullptr);

    // #10: MLP layer 2 (1-product) + bias + g_sp residual -> g_u
    gemm_mma<3, 1, 3><<<dim3(2, MTOT / 128), 256, SM13>>>(
        p_hmh, p_w2h, nullptr, p_u, DMODEL, DMODEL, b2, nullptr);

    // #11: final LayerNorm -> d_out
    ln_t_kernel<<<MTOT, 256>>>(ntw, ntb, out);

    (void)in_sizes; (void)n_in; (void)out_size;
}

// round 15
// speedup vs baseline: 3.1942x; 1.1648x over previous
#include <cuda_runtime.h>
#include <cuda_fp16.h>
#include <math.h>
#include <stdint.h>

#define SEQ      4096
#define DMODEL   256
#define DINNER   512
#define DSTATE   64
#define NHEADS   8
#define HEADDIM  64
#define CONVDIM  640
#define DPROJ    1160
#define MTOT     32768          // 8 * 4096 rows (concat of both batch stacks)
#define NSEG     32
#define SEGLEN   128            // SEQ / NSEG
#define NSCANBLK 2048           // 8b * 8h * 32seg (full head per block)

// ---------------- scratch (static device globals; no allocations allowed) ----
__device__ float  g_zx   [(size_t)MTOT * DPROJ];
__device__ __half g_xconv[(size_t)MTOT * CONVDIM];
__device__ float  g_yraw [(size_t)MTOT * DINNER];
__device__ float  g_sp   [(size_t)MTOT * DMODEL];
__device__ float  g_u    [(size_t)MTOT * DMODEL];
__device__ float  g_cda  [(size_t)MTOT * NHEADS];
__device__ float  g_hseg [(size_t)NSCANBLK * 4096];
__device__ float  g_h0s  [(size_t)NSCANBLK * 4096];

// fp16 activations
__device__ __half g_xnh[(size_t)MTOT * DMODEL];
__device__ __half g_ynh[(size_t)MTOT * DINNER];
__device__ __half g_sph[(size_t)MTOT * DMODEL];
__device__ __half g_hmh[(size_t)MTOT * DMODEL];

// fp16 weights (in-proj keeps hi/lo split; others hi only)
__device__ __half g_Winh[DPROJ * DMODEL], g_Winl[DPROJ * DMODEL];
__device__ __half g_Wouth[DMODEL * DINNER];
__device__ __half g_w1h[DMODEL * DINNER];
__device__ __half g_w2h[DMODEL * DMODEL];

__device__ __forceinline__ float siluf(float x) {
    return x / (1.f + expf(-x));
}
__device__ __forceinline__ float2 h2f(uint32_t u) {
    __half2 h = *(__half2*)&u;
    return __half22float2(h);
}
__device__ __forceinline__ uint32_t smem_u32(const void* p) {
    uint32_t a;
    asm("{ .reg .u64 t; cvta.to.shared.u64 t, %1; cvt.u32.u64 %0, t; }" : "=r"(a) : "l"(p));
    return a;
}
#define LDSM4(d0, d1, d2, d3, a) \
    asm volatile("ldmatrix.sync.aligned.m8n8.x4.shared.b16 {%0,%1,%2,%3}, [%4];" \
                 : "=r"(d0), "=r"(d1), "=r"(d2), "=r"(d3) : "r"(a))
__device__ __forceinline__ void mma_fp16(float* d, const uint32_t* a, const uint32_t* b) {
    asm volatile(
        "mma.sync.aligned.m16n8k16.row.col.f32.f16.f16.f32 "
        "{%0,%1,%2,%3}, {%4,%5,%6,%7}, {%8,%9}, {%0,%1,%2,%3};"
        : "+f"(d[0]), "+f"(d[1]), "+f"(d[2]), "+f"(d[3])
        : "r"(a[0]), "r"(a[1]), "r"(a[2]), "r"(a[3]), "r"(b[0]), "r"(b[1]));
}

// ------ fused: LayerNorm(concat) -> fp16  PLUS weight conversion tail -------
__global__ void pre_kernel(const float* __restrict__ x0, const float* __restrict__ x1,
                           const float* __restrict__ w,  const float* __restrict__ bias,
                           const float* __restrict__ W_in, const float* __restrict__ W_out,
                           const float* __restrict__ w1,  const float* __restrict__ w2)
{
    int m = blockIdx.x;
    int n = threadIdx.x;
    if (m >= MTOT) {
        int i = (m - MTOT) * 256 + n;
        float v = W_in[i];
        __half h = __float2half(v);
        g_Winh[i] = h;
        g_Winl[i] = __float2half(v - __half2float(h));
        if (i < DMODEL * DINNER) {
            g_Wouth[i] = __float2half(W_out[i]);
            g_w1h[i]   = __float2half(w1[i]);
        }
        if (i < DMODEL * DMODEL) {
            g_w2h[i] = __float2half(w2[i]);
        }
        return;
    }
    int b = m >> 12;
    int t = m & 4095;
    const float* src = (b < 4) ? (x0 + ((size_t)(b * SEQ + t)) * DMODEL)
                               : (x1 + ((size_t)((b - 4) * SEQ + t)) * DMODEL);
    float v = src[n];
    float s = v, s2 = v * v;
    #pragma unroll
    for (int o = 16; o; o >>= 1) {
        s  += __shfl_xor_sync(0xffffffffu, s,  o);
        s2 += __shfl_xor_sync(0xffffffffu, s2, o);
    }
    __shared__ float rs[8], rs2[8];
    int wid = n >> 5, lid = n & 31;
    if (lid == 0) { rs[wid] = s; rs2[wid] = s2; }
    __syncthreads();
    float ts = 0.f, ts2 = 0.f;
    #pragma unroll
    for (int i = 0; i < 8; i++) { ts += rs[i]; ts2 += rs2[i]; }
    float mu  = ts  * (1.f / 256.f);
    float var = ts2 * (1.f / 256.f) - mu * mu;
    float r = rsqrtf(var + 1e-5f);
    float o = (v - mu) * r * w[n] + bias[n];
    g_xnh[(size_t)m * DMODEL + n] = __float2half(o);
}

// ---------------- final LayerNorm: g_u -> d_out ------------------------------
__global__ void ln_t_kernel(const float* __restrict__ w, const float* __restrict__ bias,
                            float* __restrict__ out)
{
    int m = blockIdx.x;
    int n = threadIdx.x;
    float v = g_u[(size_t)m * DMODEL + n];
    float s = v, s2 = v * v;
    #pragma unroll
    for (int o = 16; o; o >>= 1) {
        s  += __shfl_xor_sync(0xffffffffu, s,  o);
        s2 += __shfl_xor_sync(0xffffffffu, s2, o);
    }
    __shared__ float rs[8], rs2[8];
    int wid = n >> 5, lid = n & 31;
    if (lid == 0) { rs[wid] = s; rs2[wid] = s2; }
    __syncthreads();
    float ts = 0.f, ts2 = 0.f;
    #pragma unroll
    for (int i = 0; i < 8; i++) { ts += rs[i]; ts2 += rs2[i]; }
    float mu  = ts  * (1.f / 256.f);
    float var = ts2 * (1.f / 256.f) - mu * mu;
    float r = rsqrtf(var + 1e-5f);
    out[(size_t)m * DMODEL + n] = (v - mu) * r * w[n] + bias[n];
}

// ---------------- depthwise conv (k=4) + SiLU -> fp16, 4 timesteps/thread ---
__global__ void conv_kernel(const float* __restrict__ conv_w, const float* __restrict__ conv_b)
{
    int idx = blockIdx.x * blockDim.x + threadIdx.x;
    if (idx >= (MTOT / 4) * CONVDIM) return;
    int c  = idx % CONVDIM;
    int m4 = idx / CONVDIM;
    int b  = m4 >> 10;
    int t0 = (m4 & 1023) << 2;
    const float* base = g_zx + (size_t)(b * SEQ) * DPROJ + DINNER + c;
    float4 w4 = *(const float4*)(conv_w + c * 4);
    float bia = conv_b[c];
    float v[7];
    #pragma unroll
    for (int j = 0; j < 7; j++) {
        int tt = t0 - 3 + j;
        v[j] = (tt >= 0) ? base[(size_t)tt * DPROJ] : 0.f;
    }
    size_t obase = (size_t)(b * SEQ + t0) * CONVDIM + c;
    #pragma unroll
    for (int i = 0; i < 4; i++) {
        float acc = bia;
        acc = fmaf(v[i + 0], w4.x, acc);
        acc = fmaf(v[i + 1], w4.y, acc);
        acc = fmaf(v[i + 2], w4.z, acc);
        acc = fmaf(v[i + 3], w4.w, acc);
        g_xconv[obase + (size_t)i * CONVDIM] = __float2half(siluf(acc));
    }
}

// ========== Pass A: chunked-SSD local scan (tensor cores), h0=0 per segment ==
// grid = 2048: blk = (b*8 + h)*32 + seg; block = 256 (8 warps: 4t x 2s / 4p x 2n)
// smem: sB[64][72]h  sC[64][72]h  sXT[64][136]h  sGa[64][136]h  sBv[64][72]h
//       sdt[64]f  sS[64]f  scda[64]f  svh[64]h
#define OFF_SB   0
#define OFF_SC   9216
#define OFF_SXT  18432
#define OFF_SGA  35840
#define OFF_SBV  53248
#define OFF_SDT  62464
#define OFF_SS   62720
#define OFF_SCDA 62976
#define OFF_SVH  63232
#define SA_BYTES 63360
__global__ void __launch_bounds__(256) scan_seg_kernel(
    const float* __restrict__ dt_bias, const float* __restrict__ A_log,
    const float* __restrict__ D_param)
{
    extern __shared__ char smraw[];
    __half* sB  = (__half*)(smraw + OFF_SB);
    __half* sC  = (__half*)(smraw + OFF_SC);
    __half* sXT = (__half*)(smraw + OFF_SXT);
    __half* sGa = (__half*)(smraw + OFF_SGA);
    __half* sBv = (__half*)(smraw + OFF_SBV);
    float*  sdt = (float*)(smraw + OFF_SDT);
    float*  sS  = (float*)(smraw + OFF_SS);
    float*  scda= (float*)(smraw + OFF_SCDA);
    __half* svh = (__half*)(smraw + OFF_SVH);

    int blk = blockIdx.x;
    int seg = blk & 31;
    int h   = (blk >> 5) & 7;
    int b   = blk >> 8;
    int tid = threadIdx.x;
    int wid = tid >> 5, lane = tid & 31;
    int wm  = wid >> 1, wn = wid & 1;   // 4 x 2 warp grid over 64x64
    int gq  = lane >> 2, tq = lane & 3;
    int q   = lane >> 3, r5 = lane & 7;

    float hfrag[4][4];
    #pragma unroll
    for (int ni = 0; ni < 4; ni++)
        #pragma unroll
        for (int r = 0; r < 4; r++) hfrag[ni][r] = 0.f;
    float prevcum = 1.f;

    float Dh  = D_param[h];
    float eA  = expf(A_log[h]);
    float dtb = dt_bias[h];
    const __half* xbase = g_xconv + (size_t)b * SEQ * CONVDIM;
    int pofs = h * 64;

    #pragma unroll 1
    for (int cc = 0; cc < 2; cc++) {
        int c0 = seg * SEGLEN + cc * 64;

        // --- A: stage x rows (temp in sGa), B, C; compute dt ---
        #pragma unroll
        for (int i = 0; i < 2; i++) {
            int idx = i * 256 + tid;
            int t = idx >> 3, n8 = (idx & 7) * 8;
            const __half* rowp = xbase + (size_t)(c0 + t) * CONVDIM;
            *(uint4*)(sGa + t * 136 + n8) = *(const uint4*)(rowp + pofs + n8);
            *(uint4*)(sB  + t * 72  + n8) = *(const uint4*)(rowp + 512 + n8);
            *(uint4*)(sC  + t * 72  + n8) = *(const uint4*)(rowp + 576 + n8);
        }
        if (tid < 64) {
            float raw = g_zx[(size_t)(b * SEQ + c0 + tid) * DPROJ + (DPROJ - NHEADS) + h] + dtb;
            sdt[tid] = (raw > 20.f) ? raw : log1pf(expf(raw));
        }
        __syncthreads();

        // --- B: prefix sum S (warp 0); cda/v; transpose x; stage h0 ---
        if (wid == 0) {
            float d0 = sdt[2 * lane], d1 = sdt[2 * lane + 1];
            float acc = d0 + d1;
            #pragma unroll
            for (int o = 1; o < 32; o <<= 1) {
                float vv = __shfl_up_sync(0xffffffffu, acc, o);
                if (lane >= o) acc += vv;
            }
            sS[2 * lane]     = acc - d1;
            sS[2 * lane + 1] = acc;
        }
        __syncthreads();
        if (tid < 64) {
            float cda = __expf(-eA * sS[tid]);
            scda[tid] = cda;
            g_cda[(size_t)(b * SEQ + c0 + tid) * NHEADS + h] = prevcum * cda;
            float Send = sS[63];
            svh[tid] = __float2half(__expf(eA * (sS[tid] - Send)) * sdt[tid]);
        }
        #pragma unroll
        for (int i = 0; i < 16; i++) {
            int idx = i * 256 + tid;         // p = idx>>6, t = idx&63
            int p = idx >> 6, t = idx & 63;
            sXT[p * 136 + t] = sGa[t * 136 + p];
        }
        if (cc == 0) {
            #pragma unroll
            for (int i = 0; i < 2; i++) {
                int idx = i * 256 + tid;
                int p = idx >> 3, n8 = (idx & 7) * 8;
                *(uint4*)(sXT + p * 136 + 64 + n8) = make_uint4(0, 0, 0, 0);
            }
        } else {
            #pragma unroll
            for (int ni = 0; ni < 4; ni++) {
                int n = wn * 32 + ni * 8 + 2 * tq;
                int p0 = wm * 16 + gq, p1 = p0 + 8;
                *(__half2*)(sXT + p0 * 136 + 64 + n) = __floats2half2_rn(hfrag[ni][0], hfrag[ni][1]);
                *(__half2*)(sXT + p1 * 136 + 64 + n) = __floats2half2_rn(hfrag[ni][2], hfrag[ni][3]);
            }
        }
        __syncthreads();

        // --- C: GEMM1 G = C @ B^T (M=t, N=s, K=n) ---
        float gacc[4][4];
        #pragma unroll
        for (int ni = 0; ni < 4; ni++)
            #pragma unroll
            for (int r = 0; r < 4; r++) gacc[ni][r] = 0.f;
        #pragma unroll
        for (int kc = 0; kc < 64; kc += 16) {
            uint32_t a[4];
            {
                int arow = wm * 16 + (q & 1) * 8 + r5;
                int acol = kc + (q >> 1) * 8;
                LDSM4(a[0], a[1], a[2], a[3], smem_u32(sC + arow * 72 + acol));
            }
            uint32_t bf[4][2];
            #pragma unroll
            for (int nb = 0; nb < 2; nb++) {
                int brow = wn * 32 + nb * 16 + (q >> 1) * 8 + r5;
                int bcol = kc + (q & 1) * 8;
                LDSM4(bf[2 * nb][0], bf[2 * nb][1], bf[2 * nb + 1][0], bf[2 * nb + 1][1],
                      smem_u32(sB + brow * 72 + bcol));
            }
            #pragma unroll
            for (int ni = 0; ni < 4; ni++) mma_fp16(gacc[ni], a, bf[ni]);
        }

        // --- D: mask G -> sGa[.,0:64]; aug cda*C -> sGa[.,64:128]; Bv ---
        #pragma unroll
        for (int ni = 0; ni < 4; ni++) {
            int s0 = wn * 32 + ni * 8 + 2 * tq;
            int t0 = wm * 16 + gq, t1 = t0 + 8;
            float St0 = sS[t0], St1 = sS[t1];
            float Ss0 = sS[s0], Ss1 = sS[s0 + 1];
            float d0 = sdt[s0], d1 = sdt[s0 + 1];
            float w00 = (s0     <= t0) ? __expf(eA * (Ss0 - St0)) * d0 : 0.f;
            float w01 = (s0 + 1 <= t0) ? __expf(eA * (Ss1 - St0)) * d1 : 0.f;
            float w10 = (s0     <= t1) ? __expf(eA * (Ss0 - St1)) * d0 : 0.f;
            float w11 = (s0 + 1 <= t1) ? __expf(eA * (Ss1 - St1)) * d1 : 0.f;
            *(__half2*)(sGa + t0 * 136 + s0) = __floats2half2_rn(gacc[ni][0] * w00, gacc[ni][1] * w01);
            *(__half2*)(sGa + t1 * 136 + s0) = __floats2half2_rn(gacc[ni][2] * w10, gacc[ni][3] * w11);
        }
        #pragma unroll
        for (int i = 0; i < 2; i++) {
            int idx = i * 256 + tid;
            int t = idx >> 3, n8 = (idx & 7) * 8;
            uint4 cu = *(uint4*)(sC + t * 72 + n8);
            __half2 sc = __float2half2_rn(scda[t]);
            __half2* cp = (__half2*)&cu;
            cp[0] = __hmul2(cp[0], sc); cp[1] = __hmul2(cp[1], sc);
            cp[2] = __hmul2(cp[2], sc); cp[3] = __hmul2(cp[3], sc);
            *(uint4*)(sGa + t * 136 + 64 + n8) = cu;
        }
        #pragma unroll
        for (int i = 0; i < 16; i++) {
            int idx = i * 256 + tid;         // n = idx>>6, s = idx&63
            int n = idx >> 6, s = idx & 63;
            sBv[n * 72 + s] = __hmul(sB[s * 72 + n], svh[s]);
        }
        __syncthreads();

        // --- E: GEMM2 Y = Ga @ [X;h0] (M=t, N=p, K=128) + epilogue ---
        float yacc[4][4];
        #pragma unroll
        for (int ni = 0; ni < 4; ni++)
            #pragma unroll
            for (int r = 0; r < 4; r++) yacc[ni][r] = 0.f;
        #pragma unroll
        for (int kc = 0; kc < 128; kc += 16) {
            uint32_t a[4];
            {
                int arow = wm * 16 + (q & 1) * 8 + r5;
                int acol = kc + (q >> 1) * 8;
                LDSM4(a[0], a[1], a[2], a[3], smem_u32(sGa + arow * 136 + acol));
            }
            uint32_t bf[4][2];
            #pragma unroll
            for (int nb = 0; nb < 2; nb++) {
                int brow = wn * 32 + nb * 16 + (q >> 1) * 8 + r5;
                int bcol = kc + (q & 1) * 8;
                LDSM4(bf[2 * nb][0], bf[2 * nb][1], bf[2 * nb + 1][0], bf[2 * nb + 1][1],
                      smem_u32(sXT + brow * 136 + bcol));
            }
            #pragma unroll
            for (int ni = 0; ni < 4; ni++) mma_fp16(yacc[ni], a, bf[ni]);
        }
        #pragma unroll
        for (int ni = 0; ni < 4; ni++) {
            int p0 = wn * 32 + ni * 8 + 2 * tq;
            int t0 = wm * 16 + gq, t1 = t0 + 8;
            float x00 = __half2float(sXT[p0 * 136 + t0]);
            float x01 = __half2float(sXT[(p0 + 1) * 136 + t0]);
            float x10 = __half2float(sXT[p0 * 136 + t1]);
            float x11 = __half2float(sXT[(p0 + 1) * 136 + t1]);
            float* y0 = g_yraw + (size_t)(b * SEQ + c0 + t0) * DINNER + pofs;
            float* y1 = g_yraw + (size_t)(b * SEQ + c0 + t1) * DINNER + pofs;
            *(float2*)(y0 + p0) = make_float2(fmaf(Dh, x00, yacc[ni][0]), fmaf(Dh, x01, yacc[ni][1]));
            *(float2*)(y1 + p0) = make_float2(fmaf(Dh, x10, yacc[ni][2]), fmaf(Dh, x11, yacc[ni][3]));
        }

        // --- F: h update: h = cda_end*h + X^T @ Bv^T (M=p, N=n, K=s) ---
        float cend = scda[63];
        #pragma unroll
        for (int ni = 0; ni < 4; ni++)
            #pragma unroll
            for (int r = 0; r < 4; r++) hfrag[ni][r] *= cend;
        #pragma unroll
        for (int kc = 0; kc < 64; kc += 16) {
            uint32_t a[4];
            {
                int arow = wm * 16 + (q & 1) * 8 + r5;
                int acol = kc + (q >> 1) * 8;
                LDSM4(a[0], a[1], a[2], a[3], smem_u32(sXT + arow * 136 + acol));
            }
            uint32_t bf[4][2];
            #pragma unroll
            for (int nb = 0; nb < 2; nb++) {
                int brow = wn * 32 + nb * 16 + (q >> 1) * 8 + r5;
                int bcol = kc + (q & 1) * 8;
                LDSM4(bf[2 * nb][0], bf[2 * nb][1], bf[2 * nb + 1][0], bf[2 * nb + 1][1],
                      smem_u32(sBv + brow * 72 + bcol));
            }
            #pragma unroll
            for (int ni = 0; ni < 4; ni++) mma_fp16(hfrag[ni], a, bf[ni]);
        }
        prevcum *= cend;
        __syncthreads();
    }

    // export local end state h[p][n]
    #pragma unroll
    for (int ni = 0; ni < 4; ni++) {
        int n = wn * 32 + ni * 8 + 2 * tq;
        int p0 = wm * 16 + gq, p1 = p0 + 8;
        *(float2*)(g_hseg + (size_t)blk * 4096 + p0 * 64 + n) = make_float2(hfrag[ni][0], hfrag[ni][1]);
        *(float2*)(g_hseg + (size_t)blk * 4096 + p1 * 64 + n) = make_float2(hfrag[ni][2], hfrag[ni][3]);
    }
}

// ========== Pass B: sequential combine across segments =======================
__global__ void __launch_bounds__(256) combine_kernel()
{
    int blk = blockIdx.x;
    int tid = threadIdx.x;
    int h = blk & 7;
    int b = blk >> 3;
    float hstart[16];
    #pragma unroll
    for (int j = 0; j < 16; j++) hstart[j] = 0.f;
    for (int s = 0; s < NSEG; s++) {
        size_t base = ((size_t)(blk * NSEG + s)) * 4096 + tid * 16;
        #pragma unroll
        for (int j = 0; j < 4; j++)
            *(float4*)(g_h0s + base + j * 4) =
                make_float4(hstart[j*4], hstart[j*4+1], hstart[j*4+2], hstart[j*4+3]);
        float P = g_cda[(size_t)(b * SEQ + s * SEGLEN + SEGLEN - 1) * NHEADS + h];
        #pragma unroll
        for (int j = 0; j < 4; j++) {
            float4 v = *(const float4*)(g_hseg + base + j * 4);
            hstart[j*4]   = fmaf(P, hstart[j*4],   v.x);
            hstart[j*4+1] = fmaf(P, hstart[j*4+1], v.y);
            hstart[j*4+2] = fmaf(P, hstart[j*4+2], v.z);
            hstart[j*4+3] = fmaf(P, hstart[j*4+3], v.w);
        }
    }
}

// ========== Pass C (tensor-core): y += cumdA_t * (C @ h0^T)[t,p] =============
#define SCROW 72
#define SC_BYTES (128 * SCROW * 2 + 64 * SCROW * 2 + 128 * 4)   // 28160
__global__ void __launch_bounds__(256) correct_kernel()
{
    int blk = blockIdx.x;
    int seg = blk & 31;
    if (seg == 0) return;
    extern __shared__ char smraw[];
    __half* sCt = (__half*)smraw;                      // [128][72]
    __half* sH  = (__half*)(smraw + 128 * SCROW * 2);  // [64][72]
    float*  scd = (float*)(smraw + 128 * SCROW * 2 + 64 * SCROW * 2);  // [128]

    int h   = (blk >> 5) & 7;
    int b   = blk >> 8;
    int tid = threadIdx.x;
    int wid = tid >> 5, lane = tid & 31;
    int wt  = wid >> 1, wp = wid & 1;
    int gq  = lane >> 2, tq = lane & 3;

    {
        const __half* Cb = g_xconv + ((size_t)(b * SEQ + seg * SEGLEN)) * CONVDIM + 576;
        #pragma unroll
        for (int i = 0; i < 4; i++) {
            int idx = i * 256 + tid;
            int t = idx >> 3, n8 = (idx & 7) * 8;
            *(uint4*)(sCt + t * SCROW + n8) = *(const uint4*)(Cb + (size_t)t * CONVDIM + n8);
        }
    }
    {
        const float* hb = g_h0s + (size_t)blk * 4096;
        #pragma unroll
        for (int i = 0; i < 4; i++) {
            int idx = i * 256 + tid;
            int p = idx >> 4, n4 = (idx & 15) * 4;
            float4 hv = *(const float4*)(hb + p * 64 + n4);
            __half2 h01 = __floats2half2_rn(hv.x, hv.y);
            __half2 h23 = __floats2half2_rn(hv.z, hv.w);
            *(uint2*)(sH + p * SCROW + n4) = make_uint2(*(uint32_t*)&h01, *(uint32_t*)&h23);
        }
    }
    if (tid < SEGLEN)
        scd[tid] = g_cda[(size_t)(b * SEQ + seg * SEGLEN + tid) * NHEADS + h];
    __syncthreads();

    float acc[2][4][4];
    #pragma unroll
    for (int mi = 0; mi < 2; mi++)
        #pragma unroll
        for (int ni = 0; ni < 4; ni++)
            #pragma unroll
            for (int r = 0; r < 4; r++) acc[mi][ni][r] = 0.f;

    uint32_t sc_base = smem_u32(sCt);
    uint32_t sh_base = smem_u32(sH);
    int q = lane >> 3, r = lane & 7;
    #pragma unroll
    for (int kc = 0; kc < 64; kc += 16) {
        uint32_t a[2][4];
        #pragma unroll
        for (int mi = 0; mi < 2; mi++) {
            int arow = wt * 32 + mi * 16 + (q & 1) * 8 + r;
            int acol = kc + (q >> 1) * 8;
            LDSM4(a[mi][0], a[mi][1], a[mi][2], a[mi][3],
                  sc_base + (arow * SCROW + acol) * 2);
        }
        uint32_t bf[4][2];
        #pragma unroll
        for (int nb = 0; nb < 2; nb++) {
            int brow = wp * 32 + nb * 16 + (q >> 1) * 8 + r;
            int bcol = kc + (q & 1) * 8;
            LDSM4(bf[2 * nb][0], bf[2 * nb][1], bf[2 * nb + 1][0], bf[2 * nb + 1][1],
                  sh_base + (brow * SCROW + bcol) * 2);
        }
        #pragma unroll
        for (int mi = 0; mi < 2; mi++)
            #pragma unroll
            for (int ni = 0; ni < 4; ni++)
                mma_fp16(acc[mi][ni], a[mi], bf[ni]);
    }

    int pofs = h * 64;
    #pragma unroll
    for (int mi = 0; mi < 2; mi++) {
        int t0 = wt * 32 + mi * 16 + gq;
        int t1 = t0 + 8;
        float s0 = scd[t0], s1 = scd[t1];
        float* y0 = g_yraw + (size_t)(b * SEQ + seg * SEGLEN + t0) * DINNER + pofs;
        float* y1 = g_yraw + (size_t)(b * SEQ + seg * SEGLEN + t1) * DINNER + pofs;
        #pragma unroll
        for (int ni = 0; ni < 4; ni++) {
            int p = wp * 32 + ni * 8 + 2 * tq;
            y0[p]     += s0 * acc[mi][ni][0];
            y0[p + 1] += s0 * acc[mi][ni][1];
            y1[p]     += s1 * acc[mi][ni][2];
            y1[p + 1] += s1 * acc[mi][ni][3];
        }
    }
}

// ---------------- gate with silu(z) + RMSNorm -> fp16 ------------------------
__global__ void gate_rms_kernel(const float* __restrict__ rms_w)
{
    int m = blockIdx.x;
    int tid = threadIdx.x;
    float yg[2];
    float s2 = 0.f;
    #pragma unroll
    for (int e = 0; e < 2; e++) {
        int i = tid + e * 256;
        float z = g_zx[(size_t)m * DPROJ + i];
        float y = g_yraw[(size_t)m * DINNER + i];
        float g = y * siluf(z);
        yg[e] = g;
        s2 += g * g;
    }
    #pragma unroll
    for (int o = 16; o; o >>= 1) s2 += __shfl_xor_sync(0xffffffffu, s2, o);
    __shared__ float rs[8];
    int wid = tid >> 5, lid = tid & 31;
    if (lid == 0) rs[wid] = s2;
    __syncthreads();
    float tot = 0.f;
    #pragma unroll
    for (int i = 0; i < 8; i++) tot += rs[i];
    float r = rsqrtf(tot * (1.f / 512.f) + 1e-5f);
    #pragma unroll
    for (int e = 0; e < 2; e++) {
        int i = tid + e * 256;
        g_ynh[(size_t)m * DINNER + i] = __float2half(yg[e] * r * rms_w[i]);
    }
}

// ======== pipelined fp16 mma.sync GEMM: C = A * (Bh [+ Bl])^T ================
#define CP16(dst, src, sz) \
    asm volatile("cp.async.cg.shared.global [%0], [%1], 16, %2;" \
                 :: "r"(dst), "l"(src), "r"(sz))
#define CP_COMMIT() asm volatile("cp.async.commit_group;" ::: "memory")
template <int N>
__device__ __forceinline__ void cp_wait() {
    asm volatile("cp.async.wait_group %0;" :: "n"(N) : "memory");
}

#define ROWB     80
#define MATB     (128 * ROWB)        // 10240

template <int MODE, int NPROD, int NST>
__global__ void __launch_bounds__(256, 2) gemm_mma(
    const __half* __restrict__ Ah,
    const __half* __restrict__ Bh, const __half* __restrict__ Bl,
    float* __restrict__ C, int N, int K,
    const float* __restrict__ e0, const float* __restrict__ e1)
{
    constexpr int STAGEB = (1 + NPROD) * MATB;
    extern __shared__ char smem[];
    uint32_t sb = smem_u32(smem);
    int tid  = threadIdx.x;
    int wid  = tid >> 5, lane = tid & 31;
    int wm   = wid >> 2, wn = wid & 3;
    int bm   = blockIdx.y * 128;
    int bn   = blockIdx.x * 128;
    int gq   = lane >> 2;
    int tq   = lane & 3;

    float acc[4][4][4];
    #pragma unroll
    for (int mi = 0; mi < 4; mi++)
        #pragma unroll
        for (int ni = 0; ni < 4; ni++)
            #pragma unroll
            for (int r = 0; r < 4; r++) acc[mi][ni][r] = 0.f;

    auto fill_stage = [&](int s, int k0) {
        uint32_t st = sb + s * STAGEB;
        #pragma unroll
        for (int j = 0; j < 2; j++) {
            int idx = j * 256 + tid;
            int row = idx >> 2, seg = idx & 3;
            const __half* sh;
            if (MODE == 2) {
                int gr = bm + row;
                int vv = gr >> 14;
                int base = gr & 16383;
                int kk = k0 + seg * 8;
                int usef1 = ((kk >= 256) ? 1 : 0) ^ vv;
                sh = g_sph + ((size_t)(base + (usef1 ? 16384 : 0))) * DMODEL + (kk & 255);
            } else {
                sh = Ah + (size_t)(bm + row) * K + k0 + seg * 8;
            }
            CP16(st + row * ROWB + seg * 16, sh, 16);
        }
        #pragma unroll
        for (int j = 0; j < 2; j++) {
            int idx = j * 256 + tid;
            int row = idx >> 2, seg = idx & 3;
            int gn = bn + row;
            int sz = (gn < N) ? 16 : 0;
            size_t off = (size_t)gn * K + k0 + seg * 8;
            uint32_t d = st + MATB + row * ROWB + seg * 16;
            CP16(d, Bh + off, sz);
            if (NPROD == 2) CP16(d + MATB, Bl + off, sz);
        }
    };

    auto compute_stage = [&](int s) {
        uint32_t stA = sb + s * STAGEB;
        uint32_t stB = stA + MATB;
        int q = lane >> 3, r = lane & 7;
        #pragma unroll
        for (int ks = 0; ks < 2; ks++) {
            int kc = ks * 16;
            uint32_t ah[4][4];
            #pragma unroll
            for (int mi = 0; mi < 4; mi++) {
                int arow = wm * 64 + mi * 16 + (q & 1) * 8 + r;
                int acol = kc + (q >> 1) * 8;
                LDSM4(ah[mi][0], ah[mi][1], ah[mi][2], ah[mi][3],
                      stA + arow * ROWB + acol * 2);
            }
            uint32_t bh[4][2], bl[4][2];
            #pragma unroll
            for (int nb = 0; nb < 2; nb++) {
                int brow = wn * 32 + nb * 16 + (q >> 1) * 8 + r;
                int bcol = kc + (q & 1) * 8;
                uint32_t bd = stB + brow * ROWB + bcol * 2;
                LDSM4(bh[2 * nb][0], bh[2 * nb][1], bh[2 * nb + 1][0], bh[2 * nb + 1][1], bd);
                if (NPROD == 2)
                    LDSM4(bl[2 * nb][0], bl[2 * nb][1], bl[2 * nb + 1][0], bl[2 * nb + 1][1], bd + MATB);
            }
            #pragma unroll
            for (int mi = 0; mi < 4; mi++)
                #pragma unroll
                for (int ni = 0; ni < 4; ni++) {
                    mma_fp16(acc[mi][ni], ah[mi], bh[ni]);
                    if (NPROD == 2) mma_fp16(acc[mi][ni], ah[mi], bl[ni]);
                }
        }
    };

    int nk = K >> 5;
    #pragma unroll
    for (int s = 0; s < NST - 1; s++) {
        if (s < nk) { fill_stage(s, s << 5); }
        CP_COMMIT();
    }
    for (int i = 0; i < nk; i++) {
        cp_wait<NST - 2>();
        __syncthreads();
        if (i + NST - 1 < nk) fill_stage((i + NST - 1) % NST, (i + NST - 1) << 5);
        CP_COMMIT();
        compute_stage(i % NST);
    }

    // epilogue
    #pragma unroll
    for (int mi = 0; mi < 4; mi++) {
        int gr0 = bm + wm * 64 + mi * 16 + gq;
        int gr1 = gr0 + 8;
        const float *res0 = nullptr, *res1 = nullptr;
        if (MODE == 1) {
            int b0i = gr0 >> 12, t0 = gr0 & 4095;
            int b1i = gr1 >> 12, t1 = gr1 & 4095;
            res0 = (b0i < 4) ? (e0 + ((size_t)(b0i * SEQ + t0)) * DMODEL)
                             : (e1 + ((size_t)((b0i - 4) * SEQ + t0)) * DMODEL);
            res1 = (b1i < 4) ? (e0 + ((size_t)(b1i * SEQ + t1)) * DMODEL)
                             : (e1 + ((size_t)((b1i - 4) * SEQ + t1)) * DMODEL);
        }
        #pragma unroll
        for (int ni = 0; ni < 4; ni++) {
            int gc = bn + wn * 32 + ni * 8 + 2 * tq;
            if (gc >= N) continue;
            float v0 = acc[mi][ni][0], v1 = acc[mi][ni][1];
            float v2 = acc[mi][ni][2], v3 = acc[mi][ni][3];
            if (MODE == 0) {
                *(float2*)(C + (size_t)gr0 * N + gc) = make_float2(v0, v1);
                *(float2*)(C + (size_t)gr1 * N + gc) = make_float2(v2, v3);
            }
            if (MODE == 1) {
                v0 += res0[gc]; v1 += res0[gc + 1];
                v2 += res1[gc]; v3 += res1[gc + 1];
                *(float2*)(C + (size_t)gr0 * N + gc) = make_float2(v0, v1);
                *(float2*)(C + (size_t)gr1 * N + gc) = make_float2(v2, v3);
                *(__half2*)(g_sph + (size_t)gr0 * DMODEL + gc) = __floats2half2_rn(v0, v1);
                *(__half2*)(g_sph + (size_t)gr1 * DMODEL + gc) = __floats2half2_rn(v2, v3);
            }
            if (MODE == 2) {
                float bx = e0[gc], by = e0[gc + 1];
                v0 = siluf(v0 + bx); v1 = siluf(v1 + by);
                v2 = siluf(v2 + bx); v3 = siluf(v3 + by);
                *(__half2*)(g_hmh + (size_t)gr0 * DMODEL + gc) = __floats2half2_rn(v0, v1);
                *(__half2*)(g_hmh + (size_t)gr1 * DMODEL + gc) = __floats2half2_rn(v2, v3);
            }
            if (MODE == 3) {
                float bx = e0[gc], by = e0[gc + 1];
                const float* s0 = g_sp + (size_t)gr0 * DMODEL + gc;
                const float* s1 = g_sp + (size_t)gr1 * DMODEL + gc;
                v0 += bx + s0[0]; v1 += by + s0[1];
                v2 += bx + s1[0]; v3 += by + s1[1];
                *(float2*)(C + (size_t)gr0 * N + gc) = make_float2(v0, v1);
                *(float2*)(C + (size_t)gr1 * N + gc) = make_float2(v2, v3);
            }
        }
    }
}

// ---------------- launch ------------------------------------------------------
extern "C" void kernel_launch(void* const* d_in, const int* in_sizes, int n_in,
                              void* d_out, int out_size)
{
    const float* x0      = (const float*)d_in[0];
    const float* x1      = (const float*)d_in[1];
    const float* nsw     = (const float*)d_in[2];
    const float* nsb     = (const float*)d_in[3];
    const float* W_in    = (const float*)d_in[4];
    const float* conv_w  = (const float*)d_in[5];
    const float* conv_b  = (const float*)d_in[6];
    const float* dt_bias = (const float*)d_in[7];
    const float* A_log   = (const float*)d_in[8];
    const float* Dp      = (const float*)d_in[9];
    const float* rms_w   = (const float*)d_in[10];
    const float* W_out   = (const float*)d_in[11];
    const float* w1      = (const float*)d_in[12];
    const float* b1      = (const float*)d_in[13];
    const float* w2      = (const float*)d_in[14];
    const float* b2      = (const float*)d_in[15];
    const float* ntw     = (const float*)d_in[16];
    const float* ntb     = (const float*)d_in[17];
    float* out = (float*)d_out;

    float *p_zx, *p_sp, *p_u;
    cudaGetSymbolAddress((void**)&p_zx, g_zx);
    cudaGetSymbolAddress((void**)&p_sp, g_sp);
    cudaGetSymbolAddress((void**)&p_u,  g_u);
    __half *p_xnh, *p_ynh, *p_hmh;
    __half *p_Winh, *p_Winl, *p_Wouth, *p_w1h, *p_w2h;
    cudaGetSymbolAddress((void**)&p_xnh, g_xnh);
    cudaGetSymbolAddress((void**)&p_ynh, g_ynh);
    cudaGetSymbolAddress((void**)&p_hmh, g_hmh);
    cudaGetSymbolAddress((void**)&p_Winh,  g_Winh);
    cudaGetSymbolAddress((void**)&p_Winl,  g_Winl);
    cudaGetSymbolAddress((void**)&p_Wouth, g_Wouth);
    cudaGetSymbolAddress((void**)&p_w1h,   g_w1h);
    cudaGetSymbolAddress((void**)&p_w2h,   g_w2h);

    const int SM22 = 2 * 3 * MATB;   // 61440 (NPROD=2, NST=2)
    const int SM13 = 3 * 2 * MATB;   // 61440 (NPROD=1, NST=3)
    cudaFuncSetAttribute((const void*)gemm_mma<0, 2, 2>, cudaFuncAttributeMaxDynamicSharedMemorySize, SM22);
    cudaFuncSetAttribute((const void*)gemm_mma<1, 1, 3>, cudaFuncAttributeMaxDynamicSharedMemorySize, SM13);
    cudaFuncSetAttribute((const void*)gemm_mma<2, 1, 3>, cudaFuncAttributeMaxDynamicSharedMemorySize, SM13);
    cudaFuncSetAttribute((const void*)gemm_mma<3, 1, 3>, cudaFuncAttributeMaxDynamicSharedMemorySize, SM13);
    cudaFuncSetAttribute((const void*)scan_seg_kernel, cudaFuncAttributeMaxDynamicSharedMemorySize, SA_BYTES);
    cudaFuncSetAttribute((const void*)correct_kernel,  cudaFuncAttributeMaxDynamicSharedMemorySize, SC_BYTES);

    // #1: fused LayerNorm + weight convert
    pre_kernel<<<MTOT + 1160, 256>>>(x0, x1, nsw, nsb, W_in, W_out, w1, w2);

    // #2: in-proj GEMM (2-product, 2-stage): zxbcdt = xn @ W_in^T
    gemm_mma<0, 2, 2><<<dim3((DPROJ + 127) / 128, MTOT / 128), 256, SM22>>>(
        p_xnh, p_Winh, p_Winl, p_zx, DPROJ, DMODEL, nullptr, nullptr);

    // #3: depthwise conv + SiLU -> fp16
    conv_kernel<<<((MTOT / 4) * CONVDIM + 255) / 256, 256>>>(conv_w, conv_b);

    // #4: pass A — chunked-SSD segmented scans on tensor cores  [ncu captures this]
    scan_seg_kernel<<<NSCANBLK, 256, SA_BYTES>>>(dt_bias, A_log, Dp);

    // #5: pass B — combine segment states
    combine_kernel<<<64, 256>>>();

    // #6: pass C — cross-segment correction via tensor cores
    correct_kernel<<<NSCANBLK, 256, SC_BYTES>>>();

    // #7: gate + RMSNorm -> fp16
    gate_rms_kernel<<<MTOT, 256>>>(rms_w);

    // #8: out-proj GEMM (1-product) + residual -> g_sp/g_sph
    gemm_mma<1, 1, 3><<<dim3(2, MTOT / 128), 256, SM13>>>(
        p_ynh, p_Wouth, nullptr, p_sp, DMODEL, DINNER, x0, x1);

    // #9: MLP layer 1 (1-product, cross-concat gather) + SiLU -> g_hmh
    gemm_mma<2, 1, 3><<<dim3(2, MTOT / 128), 256, SM13>>>(
        nullptr, p_w1h, nullptr, nullptr, DMODEL, DINNER, b1, nullptr);

    // #10: MLP layer 2 (1-product) + bias + g_sp residual -> g_u
    gemm_mma<3, 1, 3><<<dim3(2, MTOT / 128), 256, SM13>>>(
        p_hmh, p_w2h, nullptr, p_u, DMODEL, DMODEL, b2, nullptr);

    // #11: final LayerNorm -> d_out
    ln_t_kernel<<<MTOT, 256>>>(ntw, ntb, out);

    (void)in_sizes; (void)n_in; (void)out_size;
}

// round 16
// speedup vs baseline: 3.8158x; 1.1946x over previous
#include <cuda_runtime.h>
#include <cuda_fp16.h>
#include <math.h>
#include <stdint.h>

#define SEQ      4096
#define DMODEL   256
#define DINNER   512
#define DSTATE   64
#define NHEADS   8
#define HEADDIM  64
#define CONVDIM  640
#define DPROJ    1160
#define MTOT     32768          // 8 * 4096 rows (concat of both batch stacks)
#define NSEG     32
#define SEGLEN   128            // SEQ / NSEG
#define NSCANBLK 2048           // 8b * 8h * 32seg (full head per block)

// ---------------- scratch (static device globals; no allocations allowed) ----
__device__ float  g_zx   [(size_t)MTOT * DPROJ];
__device__ __half g_xconv[(size_t)MTOT * CONVDIM];
__device__ float  g_yraw [(size_t)MTOT * DINNER];
__device__ float  g_sp   [(size_t)MTOT * DMODEL];
__device__ float  g_u    [(size_t)MTOT * DMODEL];
__device__ float  g_cda  [(size_t)MTOT * NHEADS];
__device__ float  g_hseg [(size_t)NSCANBLK * 4096];
__device__ float  g_h0s  [(size_t)NSCANBLK * 4096];

// fp16 activations
__device__ __half g_xnh[(size_t)MTOT * DMODEL];
__device__ __half g_ynh[(size_t)MTOT * DINNER];
__device__ __half g_sph[(size_t)MTOT * DMODEL];
__device__ __half g_hmh[(size_t)MTOT * DMODEL];

// fp16 weights (in-proj keeps hi/lo split; others hi only)
__device__ __half g_Winh[DPROJ * DMODEL], g_Winl[DPROJ * DMODEL];
__device__ __half g_Wouth[DMODEL * DINNER];
__device__ __half g_w1h[DMODEL * DINNER];
__device__ __half g_w2h[DMODEL * DMODEL];

__device__ __forceinline__ float siluf(float x) {
    return x / (1.f + expf(-x));
}
__device__ __forceinline__ float2 h2f(uint32_t u) {
    __half2 h = *(__half2*)&u;
    return __half22float2(h);
}
__device__ __forceinline__ uint32_t smem_u32(const void* p) {
    uint32_t a;
    asm("{ .reg .u64 t; cvta.to.shared.u64 t, %1; cvt.u32.u64 %0, t; }" : "=r"(a) : "l"(p));
    return a;
}
#define LDSM4(d0, d1, d2, d3, a) \
    asm volatile("ldmatrix.sync.aligned.m8n8.x4.shared.b16 {%0,%1,%2,%3}, [%4];" \
                 : "=r"(d0), "=r"(d1), "=r"(d2), "=r"(d3) : "r"(a))
__device__ __forceinline__ void mma_fp16(float* d, const uint32_t* a, const uint32_t* b) {
    asm volatile(
        "mma.sync.aligned.m16n8k16.row.col.f32.f16.f16.f32 "
        "{%0,%1,%2,%3}, {%4,%5,%6,%7}, {%8,%9}, {%0,%1,%2,%3};"
        : "+f"(d[0]), "+f"(d[1]), "+f"(d[2]), "+f"(d[3])
        : "r"(a[0]), "r"(a[1]), "r"(a[2]), "r"(a[3]), "r"(b[0]), "r"(b[1]));
}

// ------ fused: LayerNorm(concat) -> fp16 (warp per row) + weight tail -------
#define PRE_LN_BLKS (MTOT / 8)       // 4096
#define PRE_W_BLKS  145              // 145 * 2048 = 296960 = DPROJ*DMODEL
__global__ void __launch_bounds__(256) pre_kernel(
    const float* __restrict__ x0, const float* __restrict__ x1,
    const float* __restrict__ w,  const float* __restrict__ bias,
    const float* __restrict__ W_in, const float* __restrict__ W_out,
    const float* __restrict__ w1,  const float* __restrict__ w2)
{
    int blk = blockIdx.x;
    int tid = threadIdx.x;
    if (blk >= PRE_LN_BLKS) {
        int i0 = (blk - PRE_LN_BLKS) * 2048 + tid * 8;
        #pragma unroll
        for (int j = 0; j < 8; j += 4) {
            int i = i0 + j;
            float4 v = *(const float4*)(W_in + i);
            __half h0 = __float2half(v.x), h1 = __float2half(v.y);
            __half h2 = __float2half(v.z), h3 = __float2half(v.w);
            __half2 hh0; hh0.x = h0; hh0.y = h1;
            __half2 hh1; hh1.x = h2; hh1.y = h3;
            *(uint2*)(g_Winh + i) = make_uint2(*(uint32_t*)&hh0, *(uint32_t*)&hh1);
            __half2 ll0 = __floats2half2_rn(v.x - __half2float(h0), v.y - __half2float(h1));
            __half2 ll1 = __floats2half2_rn(v.z - __half2float(h2), v.w - __half2float(h3));
            *(uint2*)(g_Winl + i) = make_uint2(*(uint32_t*)&ll0, *(uint32_t*)&ll1);
            if (i < DMODEL * DINNER) {
                float4 a = *(const float4*)(W_out + i);
                float4 c = *(const float4*)(w1 + i);
                __half2 a01 = __floats2half2_rn(a.x, a.y), a23 = __floats2half2_rn(a.z, a.w);
                __half2 c01 = __floats2half2_rn(c.x, c.y), c23 = __floats2half2_rn(c.z, c.w);
                *(uint2*)(g_Wouth + i) = make_uint2(*(uint32_t*)&a01, *(uint32_t*)&a23);
                *(uint2*)(g_w1h + i)   = make_uint2(*(uint32_t*)&c01, *(uint32_t*)&c23);
            }
            if (i < DMODEL * DMODEL) {
                float4 c = *(const float4*)(w2 + i);
                __half2 c01 = __floats2half2_rn(c.x, c.y), c23 = __floats2half2_rn(c.z, c.w);
                *(uint2*)(g_w2h + i) = make_uint2(*(uint32_t*)&c01, *(uint32_t*)&c23);
            }
        }
        return;
    }
    int wd = tid >> 5, lid = tid & 31;
    int m = blk * 8 + wd;
    int b = m >> 12;
    int t = m & 4095;
    const float* src = (b < 4) ? (x0 + ((size_t)(b * SEQ + t)) * DMODEL)
                               : (x1 + ((size_t)((b - 4) * SEQ + t)) * DMODEL);
    int c0 = lid * 8;
    float4 v0 = *(const float4*)(src + c0);
    float4 v1 = *(const float4*)(src + c0 + 4);
    float s  = (v0.x + v0.y + v0.z + v0.w) + (v1.x + v1.y + v1.z + v1.w);
    float s2 = (v0.x*v0.x + v0.y*v0.y + v0.z*v0.z + v0.w*v0.w)
             + (v1.x*v1.x + v1.y*v1.y + v1.z*v1.z + v1.w*v1.w);
    #pragma unroll
    for (int o = 16; o; o >>= 1) {
        s  += __shfl_xor_sync(0xffffffffu, s,  o);
        s2 += __shfl_xor_sync(0xffffffffu, s2, o);
    }
    float mu  = s  * (1.f / 256.f);
    float var = s2 * (1.f / 256.f) - mu * mu;
    float r = rsqrtf(var + 1e-5f);
    float4 w0 = *(const float4*)(w + c0);
    float4 w1v = *(const float4*)(w + c0 + 4);
    float4 b0 = *(const float4*)(bias + c0);
    float4 b1 = *(const float4*)(bias + c0 + 4);
    __half2 o0 = __floats2half2_rn((v0.x - mu) * r * w0.x + b0.x, (v0.y - mu) * r * w0.y + b0.y);
    __half2 o1 = __floats2half2_rn((v0.z - mu) * r * w0.z + b0.z, (v0.w - mu) * r * w0.w + b0.w);
    __half2 o2 = __floats2half2_rn((v1.x - mu) * r * w1v.x + b1.x, (v1.y - mu) * r * w1v.y + b1.y);
    __half2 o3 = __floats2half2_rn((v1.z - mu) * r * w1v.z + b1.z, (v1.w - mu) * r * w1v.w + b1.w);
    *(uint4*)(g_xnh + (size_t)m * DMODEL + c0) =
        make_uint4(*(uint32_t*)&o0, *(uint32_t*)&o1, *(uint32_t*)&o2, *(uint32_t*)&o3);
}

// ---------------- final LayerNorm (warp per row): g_u -> d_out ---------------
__global__ void __launch_bounds__(256) ln_t_kernel(
    const float* __restrict__ w, const float* __restrict__ bias,
    float* __restrict__ out)
{
    int wd = threadIdx.x >> 5, lid = threadIdx.x & 31;
    int m = blockIdx.x * 8 + wd;
    int c0 = lid * 8;
    const float* src = g_u + (size_t)m * DMODEL;
    float4 v0 = *(const float4*)(src + c0);
    float4 v1 = *(const float4*)(src + c0 + 4);
    float s  = (v0.x + v0.y + v0.z + v0.w) + (v1.x + v1.y + v1.z + v1.w);
    float s2 = (v0.x*v0.x + v0.y*v0.y + v0.z*v0.z + v0.w*v0.w)
             + (v1.x*v1.x + v1.y*v1.y + v1.z*v1.z + v1.w*v1.w);
    #pragma unroll
    for (int o = 16; o; o >>= 1) {
        s  += __shfl_xor_sync(0xffffffffu, s,  o);
        s2 += __shfl_xor_sync(0xffffffffu, s2, o);
    }
    float mu  = s  * (1.f / 256.f);
    float var = s2 * (1.f / 256.f) - mu * mu;
    float r = rsqrtf(var + 1e-5f);
    float4 w0 = *(const float4*)(w + c0);
    float4 w1v = *(const float4*)(w + c0 + 4);
    float4 b0 = *(const float4*)(bias + c0);
    float4 b1 = *(const float4*)(bias + c0 + 4);
    float* dst = out + (size_t)m * DMODEL + c0;
    *(float4*)dst = make_float4((v0.x - mu) * r * w0.x + b0.x, (v0.y - mu) * r * w0.y + b0.y,
                                (v0.z - mu) * r * w0.z + b0.z, (v0.w - mu) * r * w0.w + b0.w);
    *(float4*)(dst + 4) = make_float4((v1.x - mu) * r * w1v.x + b1.x, (v1.y - mu) * r * w1v.y + b1.y,
                                      (v1.z - mu) * r * w1v.z + b1.z, (v1.w - mu) * r * w1v.w + b1.w);
}

// ---------------- depthwise conv (k=4) + SiLU -> fp16, 4 timesteps/thread ---
__global__ void conv_kernel(const float* __restrict__ conv_w, const float* __restrict__ conv_b)
{
    int idx = blockIdx.x * blockDim.x + threadIdx.x;
    if (idx >= (MTOT / 4) * CONVDIM) return;
    int c  = idx % CONVDIM;
    int m4 = idx / CONVDIM;
    int b  = m4 >> 10;
    int t0 = (m4 & 1023) << 2;
    const float* base = g_zx + (size_t)(b * SEQ) * DPROJ + DINNER + c;
    float4 w4 = *(const float4*)(conv_w + c * 4);
    float bia = conv_b[c];
    float v[7];
    #pragma unroll
    for (int j = 0; j < 7; j++) {
        int tt = t0 - 3 + j;
        v[j] = (tt >= 0) ? base[(size_t)tt * DPROJ] : 0.f;
    }
    size_t obase = (size_t)(b * SEQ + t0) * CONVDIM + c;
    #pragma unroll
    for (int i = 0; i < 4; i++) {
        float acc = bia;
        acc = fmaf(v[i + 0], w4.x, acc);
        acc = fmaf(v[i + 1], w4.y, acc);
        acc = fmaf(v[i + 2], w4.z, acc);
        acc = fmaf(v[i + 3], w4.w, acc);
        g_xconv[obase + (size_t)i * CONVDIM] = __float2half(siluf(acc));
    }
}

// ========== Pass A: chunked-SSD local scan (tensor cores), h0=0 per segment ==
#define OFF_SB   0
#define OFF_SC   9216
#define OFF_SXT  18432
#define OFF_SGA  35840
#define OFF_SBV  53248
#define OFF_SDT  62464
#define OFF_SS   62720
#define OFF_SCDA 62976
#define OFF_SVH  63232
#define SA_BYTES 63360
__global__ void __launch_bounds__(256, 2) scan_seg_kernel(
    const float* __restrict__ dt_bias, const float* __restrict__ A_log,
    const float* __restrict__ D_param)
{
    extern __shared__ char smraw[];
    __half* sB  = (__half*)(smraw + OFF_SB);
    __half* sC  = (__half*)(smraw + OFF_SC);
    __half* sXT = (__half*)(smraw + OFF_SXT);
    __half* sGa = (__half*)(smraw + OFF_SGA);
    __half* sBv = (__half*)(smraw + OFF_SBV);
    float*  sdt = (float*)(smraw + OFF_SDT);
    float*  sS  = (float*)(smraw + OFF_SS);
    float*  scda= (float*)(smraw + OFF_SCDA);
    __half* svh = (__half*)(smraw + OFF_SVH);

    int blk = blockIdx.x;
    int seg = blk & 31;
    int h   = (blk >> 5) & 7;
    int b   = blk >> 8;
    int tid = threadIdx.x;
    int wid = tid >> 5, lane = tid & 31;
    int wm  = wid >> 1, wn = wid & 1;   // 4 x 2 warp grid over 64x64
    int gq  = lane >> 2, tq = lane & 3;
    int q   = lane >> 3, r5 = lane & 7;

    float hfrag[4][4];
    #pragma unroll
    for (int ni = 0; ni < 4; ni++)
        #pragma unroll
        for (int r = 0; r < 4; r++) hfrag[ni][r] = 0.f;
    float prevcum = 1.f;

    float Dh  = D_param[h];
    float eA  = expf(A_log[h]);
    float dtb = dt_bias[h];
    const __half* xbase = g_xconv + (size_t)b * SEQ * CONVDIM;
    int pofs = h * 64;

    #pragma unroll 1
    for (int cc = 0; cc < 2; cc++) {
        int c0 = seg * SEGLEN + cc * 64;

        // --- A: stage x rows (temp in sGa), B, C; compute dt ---
        #pragma unroll
        for (int i = 0; i < 2; i++) {
            int idx = i * 256 + tid;
            int t = idx >> 3, n8 = (idx & 7) * 8;
            const __half* rowp = xbase + (size_t)(c0 + t) * CONVDIM;
            *(uint4*)(sGa + t * 136 + n8) = *(const uint4*)(rowp + pofs + n8);
            *(uint4*)(sB  + t * 72  + n8) = *(const uint4*)(rowp + 512 + n8);
            *(uint4*)(sC  + t * 72  + n8) = *(const uint4*)(rowp + 576 + n8);
        }
        if (tid < 64) {
            float raw = g_zx[(size_t)(b * SEQ + c0 + tid) * DPROJ + (DPROJ - NHEADS) + h] + dtb;
            sdt[tid] = (raw > 20.f) ? raw : log1pf(expf(raw));
        }
        __syncthreads();

        // --- B: prefix sum S (warp 0); cda/v; transpose x; stage h0 ---
        if (wid == 0) {
            float d0 = sdt[2 * lane], d1 = sdt[2 * lane + 1];
            float acc = d0 + d1;
            #pragma unroll
            for (int o = 1; o < 32; o <<= 1) {
                float vv = __shfl_up_sync(0xffffffffu, acc, o);
                if (lane >= o) acc += vv;
            }
            sS[2 * lane]     = acc - d1;
            sS[2 * lane + 1] = acc;
        }
        __syncthreads();
        if (tid < 64) {
            float cda = __expf(-eA * sS[tid]);
            scda[tid] = cda;
            g_cda[(size_t)(b * SEQ + c0 + tid) * NHEADS + h] = prevcum * cda;
            float Send = sS[63];
            svh[tid] = __float2half(__expf(eA * (sS[tid] - Send)) * sdt[tid]);
        }
        #pragma unroll
        for (int i = 0; i < 16; i++) {
            int idx = i * 256 + tid;
            int p = idx >> 6, t = idx & 63;
            sXT[p * 136 + t] = sGa[t * 136 + p];
        }
        if (cc == 0) {
            #pragma unroll
            for (int i = 0; i < 2; i++) {
                int idx = i * 256 + tid;
                int p = idx >> 3, n8 = (idx & 7) * 8;
                *(uint4*)(sXT + p * 136 + 64 + n8) = make_uint4(0, 0, 0, 0);
            }
        } else {
            #pragma unroll
            for (int ni = 0; ni < 4; ni++) {
                int n = wn * 32 + ni * 8 + 2 * tq;
                int p0 = wm * 16 + gq, p1 = p0 + 8;
                *(__half2*)(sXT + p0 * 136 + 64 + n) = __floats2half2_rn(hfrag[ni][0], hfrag[ni][1]);
                *(__half2*)(sXT + p1 * 136 + 64 + n) = __floats2half2_rn(hfrag[ni][2], hfrag[ni][3]);
            }
        }
        __syncthreads();

        // --- C: GEMM1 G = C @ B^T ---
        float gacc[4][4];
        #pragma unroll
        for (int ni = 0; ni < 4; ni++)
            #pragma unroll
            for (int r = 0; r < 4; r++) gacc[ni][r] = 0.f;
        #pragma unroll
        for (int kc = 0; kc < 64; kc += 16) {
            uint32_t a[4];
            {
                int arow = wm * 16 + (q & 1) * 8 + r5;
                int acol = kc + (q >> 1) * 8;
                LDSM4(a[0], a[1], a[2], a[3], smem_u32(sC + arow * 72 + acol));
            }
            uint32_t bf[4][2];
            #pragma unroll
            for (int nb = 0; nb < 2; nb++) {
                int brow = wn * 32 + nb * 16 + (q >> 1) * 8 + r5;
                int bcol = kc + (q & 1) * 8;
                LDSM4(bf[2 * nb][0], bf[2 * nb][1], bf[2 * nb + 1][0], bf[2 * nb + 1][1],
                      smem_u32(sB + brow * 72 + bcol));
            }
            #pragma unroll
            for (int ni = 0; ni < 4; ni++) mma_fp16(gacc[ni], a, bf[ni]);
        }

        // --- D: mask G -> sGa[.,0:64]; aug cda*C -> sGa[.,64:128]; Bv ---
        #pragma unroll
        for (int ni = 0; ni < 4; ni++) {
            int s0 = wn * 32 + ni * 8 + 2 * tq;
            int t0 = wm * 16 + gq, t1 = t0 + 8;
            float St0 = sS[t0], St1 = sS[t1];
            float Ss0 = sS[s0], Ss1 = sS[s0 + 1];
            float d0 = sdt[s0], d1 = sdt[s0 + 1];
            float w00 = (s0     <= t0) ? __expf(eA * (Ss0 - St0)) * d0 : 0.f;
            float w01 = (s0 + 1 <= t0) ? __expf(eA * (Ss1 - St0)) * d1 : 0.f;
            float w10 = (s0     <= t1) ? __expf(eA * (Ss0 - St1)) * d0 : 0.f;
            float w11 = (s0 + 1 <= t1) ? __expf(eA * (Ss1 - St1)) * d1 : 0.f;
            *(__half2*)(sGa + t0 * 136 + s0) = __floats2half2_rn(gacc[ni][0] * w00, gacc[ni][1] * w01);
            *(__half2*)(sGa + t1 * 136 + s0) = __floats2half2_rn(gacc[ni][2] * w10, gacc[ni][3] * w11);
        }
        #pragma unroll
        for (int i = 0; i < 2; i++) {
            int idx = i * 256 + tid;
            int t = idx >> 3, n8 = (idx & 7) * 8;
            uint4 cu = *(uint4*)(sC + t * 72 + n8);
            __half2 sc = __float2half2_rn(scda[t]);
            __half2* cp = (__half2*)&cu;
            cp[0] = __hmul2(cp[0], sc); cp[1] = __hmul2(cp[1], sc);
            cp[2] = __hmul2(cp[2], sc); cp[3] = __hmul2(cp[3], sc);
            *(uint4*)(sGa + t * 136 + 64 + n8) = cu;
        }
        #pragma unroll
        for (int i = 0; i < 16; i++) {
            int idx = i * 256 + tid;
            int n = idx >> 6, s = idx & 63;
            sBv[n * 72 + s] = __hmul(sB[s * 72 + n], svh[s]);
        }
        __syncthreads();

        // --- E: GEMM2 Y = Ga @ [X;h0] + epilogue ---
        float yacc[4][4];
        #pragma unroll
        for (int ni = 0; ni < 4; ni++)
            #pragma unroll
            for (int r = 0; r < 4; r++) yacc[ni][r] = 0.f;
        #pragma unroll
        for (int kc = 0; kc < 128; kc += 16) {
            uint32_t a[4];
            {
                int arow = wm * 16 + (q & 1) * 8 + r5;
                int acol = kc + (q >> 1) * 8;
                LDSM4(a[0], a[1], a[2], a[3], smem_u32(sGa + arow * 136 + acol));
            }
            uint32_t bf[4][2];
            #pragma unroll
            for (int nb = 0; nb < 2; nb++) {
                int brow = wn * 32 + nb * 16 + (q >> 1) * 8 + r5;
                int bcol = kc + (q & 1) * 8;
                LDSM4(bf[2 * nb][0], bf[2 * nb][1], bf[2 * nb + 1][0], bf[2 * nb + 1][1],
                      smem_u32(sXT + brow * 136 + bcol));
            }
            #pragma unroll
            for (int ni = 0; ni < 4; ni++) mma_fp16(yacc[ni], a, bf[ni]);
        }
        #pragma unroll
        for (int ni = 0; ni < 4; ni++) {
            int p0 = wn * 32 + ni * 8 + 2 * tq;
            int t0 = wm * 16 + gq, t1 = t0 + 8;
            float x00 = __half2float(sXT[p0 * 136 + t0]);
            float x01 = __half2float(sXT[(p0 + 1) * 136 + t0]);
            float x10 = __half2float(sXT[p0 * 136 + t1]);
            float x11 = __half2float(sXT[(p0 + 1) * 136 + t1]);
            float* y0 = g_yraw + (size_t)(b * SEQ + c0 + t0) * DINNER + pofs;
            float* y1 = g_yraw + (size_t)(b * SEQ + c0 + t1) * DINNER + pofs;
            *(float2*)(y0 + p0) = make_float2(fmaf(Dh, x00, yacc[ni][0]), fmaf(Dh, x01, yacc[ni][1]));
            *(float2*)(y1 + p0) = make_float2(fmaf(Dh, x10, yacc[ni][2]), fmaf(Dh, x11, yacc[ni][3]));
        }

        // --- F: h update ---
        float cend = scda[63];
        #pragma unroll
        for (int ni = 0; ni < 4; ni++)
            #pragma unroll
            for (int r = 0; r < 4; r++) hfrag[ni][r] *= cend;
        #pragma unroll
        for (int kc = 0; kc < 64; kc += 16) {
            uint32_t a[4];
            {
                int arow = wm * 16 + (q & 1) * 8 + r5;
                int acol = kc + (q >> 1) * 8;
                LDSM4(a[0], a[1], a[2], a[3], smem_u32(sXT + arow * 136 + acol));
            }
            uint32_t bf[4][2];
            #pragma unroll
            for (int nb = 0; nb < 2; nb++) {
                int brow = wn * 32 + nb * 16 + (q >> 1) * 8 + r5;
                int bcol = kc + (q & 1) * 8;
                LDSM4(bf[2 * nb][0], bf[2 * nb][1], bf[2 * nb + 1][0], bf[2 * nb + 1][1],
                      smem_u32(sBv + brow * 72 + bcol));
            }
            #pragma unroll
            for (int ni = 0; ni < 4; ni++) mma_fp16(hfrag[ni], a, bf[ni]);
        }
        prevcum *= cend;
        __syncthreads();
    }

    // export local end state h[p][n]
    #pragma unroll
    for (int ni = 0; ni < 4; ni++) {
        int n = wn * 32 + ni * 8 + 2 * tq;
        int p0 = wm * 16 + gq, p1 = p0 + 8;
        *(float2*)(g_hseg + (size_t)blk * 4096 + p0 * 64 + n) = make_float2(hfrag[ni][0], hfrag[ni][1]);
        *(float2*)(g_hseg + (size_t)blk * 4096 + p1 * 64 + n) = make_float2(hfrag[ni][2], hfrag[ni][3]);
    }
}

// ========== Pass B: sequential combine across segments =======================
__global__ void __launch_bounds__(256) combine_kernel()
{
    int blk = blockIdx.x;
    int tid = threadIdx.x;
    int h = blk & 7;
    int b = blk >> 3;
    float hstart[16];
    #pragma unroll
    for (int j = 0; j < 16; j++) hstart[j] = 0.f;
    for (int s = 0; s < NSEG; s++) {
        size_t base = ((size_t)(blk * NSEG + s)) * 4096 + tid * 16;
        #pragma unroll
        for (int j = 0; j < 4; j++)
            *(float4*)(g_h0s + base + j * 4) =
                make_float4(hstart[j*4], hstart[j*4+1], hstart[j*4+2], hstart[j*4+3]);
        float P = g_cda[(size_t)(b * SEQ + s * SEGLEN + SEGLEN - 1) * NHEADS + h];
        #pragma unroll
        for (int j = 0; j < 4; j++) {
            float4 v = *(const float4*)(g_hseg + base + j * 4);
            hstart[j*4]   = fmaf(P, hstart[j*4],   v.x);
            hstart[j*4+1] = fmaf(P, hstart[j*4+1], v.y);
            hstart[j*4+2] = fmaf(P, hstart[j*4+2], v.z);
            hstart[j*4+3] = fmaf(P, hstart[j*4+3], v.w);
        }
    }
}

// ========== Pass C (tensor-core): y += cumdA_t * (C @ h0^T)[t,p] =============
#define SCROW 72
#define SC_BYTES (128 * SCROW * 2 + 64 * SCROW * 2 + 128 * 4)   // 28160
__global__ void __launch_bounds__(256) correct_kernel()
{
    int blk = blockIdx.x;
    int seg = blk & 31;
    if (seg == 0) return;
    extern __shared__ char smraw[];
    __half* sCt = (__half*)smraw;                      // [128][72]
    __half* sH  = (__half*)(smraw + 128 * SCROW * 2);  // [64][72]
    float*  scd = (float*)(smraw + 128 * SCROW * 2 + 64 * SCROW * 2);  // [128]

    int h   = (blk >> 5) & 7;
    int b   = blk >> 8;
    int tid = threadIdx.x;
    int wid = tid >> 5, lane = tid & 31;
    int wt  = wid >> 1, wp = wid & 1;
    int gq  = lane >> 2, tq = lane & 3;

    {
        const __half* Cb = g_xconv + ((size_t)(b * SEQ + seg * SEGLEN)) * CONVDIM + 576;
        #pragma unroll
        for (int i = 0; i < 4; i++) {
            int idx = i * 256 + tid;
            int t = idx >> 3, n8 = (idx & 7) * 8;
            *(uint4*)(sCt + t * SCROW + n8) = *(const uint4*)(Cb + (size_t)t * CONVDIM + n8);
        }
    }
    {
        const float* hb = g_h0s + (size_t)blk * 4096;
        #pragma unroll
        for (int i = 0; i < 4; i++) {
            int idx = i * 256 + tid;
            int p = idx >> 4, n4 = (idx & 15) * 4;
            float4 hv = *(const float4*)(hb + p * 64 + n4);
            __half2 h01 = __floats2half2_rn(hv.x, hv.y);
            __half2 h23 = __floats2half2_rn(hv.z, hv.w);
            *(uint2*)(sH + p * SCROW + n4) = make_uint2(*(uint32_t*)&h01, *(uint32_t*)&h23);
        }
    }
    if (tid < SEGLEN)
        scd[tid] = g_cda[(size_t)(b * SEQ + seg * SEGLEN + tid) * NHEADS + h];
    __syncthreads();

    float acc[2][4][4];
    #pragma unroll
    for (int mi = 0; mi < 2; mi++)
        #pragma unroll
        for (int ni = 0; ni < 4; ni++)
            #pragma unroll
            for (int r = 0; r < 4; r++) acc[mi][ni][r] = 0.f;

    uint32_t sc_base = smem_u32(sCt);
    uint32_t sh_base = smem_u32(sH);
    int q = lane >> 3, r = lane & 7;
    #pragma unroll
    for (int kc = 0; kc < 64; kc += 16) {
        uint32_t a[2][4];
        #pragma unroll
        for (int mi = 0; mi < 2; mi++) {
            int arow = wt * 32 + mi * 16 + (q & 1) * 8 + r;
            int acol = kc + (q >> 1) * 8;
            LDSM4(a[mi][0], a[mi][1], a[mi][2], a[mi][3],
                  sc_base + (arow * SCROW + acol) * 2);
        }
        uint32_t bf[4][2];
        #pragma unroll
        for (int nb = 0; nb < 2; nb++) {
            int brow = wp * 32 + nb * 16 + (q >> 1) * 8 + r;
            int bcol = kc + (q & 1) * 8;
            LDSM4(bf[2 * nb][0], bf[2 * nb][1], bf[2 * nb + 1][0], bf[2 * nb + 1][1],
                  sh_base + (brow * SCROW + bcol) * 2);
        }
        #pragma unroll
        for (int mi = 0; mi < 2; mi++)
            #pragma unroll
            for (int ni = 0; ni < 4; ni++)
                mma_fp16(acc[mi][ni], a[mi], bf[ni]);
    }

    int pofs = h * 64;
    #pragma unroll
    for (int mi = 0; mi < 2; mi++) {
        int t0 = wt * 32 + mi * 16 + gq;
        int t1 = t0 + 8;
        float s0 = scd[t0], s1 = scd[t1];
        float* y0 = g_yraw + (size_t)(b * SEQ + seg * SEGLEN + t0) * DINNER + pofs;
        float* y1 = g_yraw + (size_t)(b * SEQ + seg * SEGLEN + t1) * DINNER + pofs;
        #pragma unroll
        for (int ni = 0; ni < 4; ni++) {
            int p = wp * 32 + ni * 8 + 2 * tq;
            y0[p]     += s0 * acc[mi][ni][0];
            y0[p + 1] += s0 * acc[mi][ni][1];
            y1[p]     += s1 * acc[mi][ni][2];
            y1[p + 1] += s1 * acc[mi][ni][3];
        }
    }
}

// ---------------- gate with silu(z) + RMSNorm -> fp16 (warp per row) ---------
__global__ void __launch_bounds__(256) gate_rms_kernel(const float* __restrict__ rms_w)
{
    int wd = threadIdx.x >> 5, lid = threadIdx.x & 31;
    int m = blockIdx.x * 8 + wd;
    int c0 = lid * 16;
    const float* zp = g_zx + (size_t)m * DPROJ + c0;
    const float* yp = g_yraw + (size_t)m * DINNER + c0;
    float g[16];
    float s2 = 0.f;
    #pragma unroll
    for (int j = 0; j < 16; j += 4) {
        float4 z = *(const float4*)(zp + j);
        float4 y = *(const float4*)(yp + j);
        g[j]     = y.x * siluf(z.x);
        g[j + 1] = y.y * siluf(z.y);
        g[j + 2] = y.z * siluf(z.z);
        g[j + 3] = y.w * siluf(z.w);
        s2 += g[j]*g[j] + g[j+1]*g[j+1] + g[j+2]*g[j+2] + g[j+3]*g[j+3];
    }
    #pragma unroll
    for (int o = 16; o; o >>= 1) s2 += __shfl_xor_sync(0xffffffffu, s2, o);
    float r = rsqrtf(s2 * (1.f / 512.f) + 1e-5f);
    __half out8[16];
    #pragma unroll
    for (int j = 0; j < 16; j += 4) {
        float4 w4 = *(const float4*)(rms_w + c0 + j);
        out8[j]     = __float2half(g[j]     * r * w4.x);
        out8[j + 1] = __float2half(g[j + 1] * r * w4.y);
        out8[j + 2] = __float2half(g[j + 2] * r * w4.z);
        out8[j + 3] = __float2half(g[j + 3] * r * w4.w);
    }
    *(uint4*)(g_ynh + (size_t)m * DINNER + c0)     = *(uint4*)(out8);
    *(uint4*)(g_ynh + (size_t)m * DINNER + c0 + 8) = *(uint4*)(out8 + 8);
}

// ======== pipelined fp16 mma.sync GEMM: C = A * (Bh [+ Bl])^T ================
#define CP16(dst, src, sz) \
    asm volatile("cp.async.cg.shared.global [%0], [%1], 16, %2;" \
                 :: "r"(dst), "l"(src), "r"(sz))
#define CP_COMMIT() asm volatile("cp.async.commit_group;" ::: "memory")
template <int N>
__device__ __forceinline__ void cp_wait() {
    asm volatile("cp.async.wait_group %0;" :: "n"(N) : "memory");
}

#define ROWB     80
#define MATB     (128 * ROWB)        // 10240

template <int MODE, int NPROD, int NST>
__global__ void __launch_bounds__(256, 2) gemm_mma(
    const __half* __restrict__ Ah,
    const __half* __restrict__ Bh, const __half* __restrict__ Bl,
    float* __restrict__ C, int N, int K,
    const float* __restrict__ e0, const float* __restrict__ e1)
{
    constexpr int STAGEB = (1 + NPROD) * MATB;
    extern __shared__ char smem[];
    uint32_t sb = smem_u32(smem);
    int tid  = threadIdx.x;
    int wid  = tid >> 5, lane = tid & 31;
    int wm   = wid >> 2, wn = wid & 3;
    int bm   = blockIdx.y * 128;
    int bn   = blockIdx.x * 128;
    int gq   = lane >> 2;
    int tq   = lane & 3;

    float acc[4][4][4];
    #pragma unroll
    for (int mi = 0; mi < 4; mi++)
        #pragma unroll
        for (int ni = 0; ni < 4; ni++)
            #pragma unroll
            for (int r = 0; r < 4; r++) acc[mi][ni][r] = 0.f;

    auto fill_stage = [&](int s, int k0) {
        uint32_t st = sb + s * STAGEB;
        #pragma unroll
        for (int j = 0; j < 2; j++) {
            int idx = j * 256 + tid;
            int row = idx >> 2, seg = idx & 3;
            const __half* sh;
            if (MODE == 2) {
                int gr = bm + row;
                int vv = gr >> 14;
                int base = gr & 16383;
                int kk = k0 + seg * 8;
                int usef1 = ((kk >= 256) ? 1 : 0) ^ vv;
                sh = g_sph + ((size_t)(base + (usef1 ? 16384 : 0))) * DMODEL + (kk & 255);
            } else {
                sh = Ah + (size_t)(bm + row) * K + k0 + seg * 8;
            }
            CP16(st + row * ROWB + seg * 16, sh, 16);
        }
        #pragma unroll
        for (int j = 0; j < 2; j++) {
            int idx = j * 256 + tid;
            int row = idx >> 2, seg = idx & 3;
            int gn = bn + row;
            int sz = (gn < N) ? 16 : 0;
            size_t off = (size_t)gn * K + k0 + seg * 8;
            uint32_t d = st + MATB + row * ROWB + seg * 16;
            CP16(d, Bh + off, sz);
            if (NPROD == 2) CP16(d + MATB, Bl + off, sz);
        }
    };

    auto compute_stage = [&](int s) {
        uint32_t stA = sb + s * STAGEB;
        uint32_t stB = stA + MATB;
        int q = lane >> 3, r = lane & 7;
        #pragma unroll
        for (int ks = 0; ks < 2; ks++) {
            int kc = ks * 16;
            uint32_t ah[4][4];
            #pragma unroll
            for (int mi = 0; mi < 4; mi++) {
                int arow = wm * 64 + mi * 16 + (q & 1) * 8 + r;
                int acol = kc + (q >> 1) * 8;
                LDSM4(ah[mi][0], ah[mi][1], ah[mi][2], ah[mi][3],
                      stA + arow * ROWB + acol * 2);
            }
            uint32_t bh[4][2], bl[4][2];
            #pragma unroll
            for (int nb = 0; nb < 2; nb++) {
                int brow = wn * 32 + nb * 16 + (q >> 1) * 8 + r;
                int bcol = kc + (q & 1) * 8;
                uint32_t bd = stB + brow * ROWB + bcol * 2;
                LDSM4(bh[2 * nb][0], bh[2 * nb][1], bh[2 * nb + 1][0], bh[2 * nb + 1][1], bd);
                if (NPROD == 2)
                    LDSM4(bl[2 * nb][0], bl[2 * nb][1], bl[2 * nb + 1][0], bl[2 * nb + 1][1], bd + MATB);
            }
            #pragma unroll
            for (int mi = 0; mi < 4; mi++)
                #pragma unroll
                for (int ni = 0; ni < 4; ni++) {
                    mma_fp16(acc[mi][ni], ah[mi], bh[ni]);
                    if (NPROD == 2) mma_fp16(acc[mi][ni], ah[mi], bl[ni]);
                }
        }
    };

    int nk = K >> 5;
    #pragma unroll
    for (int s = 0; s < NST - 1; s++) {
        if (s < nk) { fill_stage(s, s << 5); }
        CP_COMMIT();
    }
    for (int i = 0; i < nk; i++) {
        cp_wait<NST - 2>();
        __syncthreads();
        if (i + NST - 1 < nk) fill_stage((i + NST - 1) % NST, (i + NST - 1) << 5);
        CP_COMMIT();
        compute_stage(i % NST);
    }

    // epilogue
    #pragma unroll
    for (int mi = 0; mi < 4; mi++) {
        int gr0 = bm + wm * 64 + mi * 16 + gq;
        int gr1 = gr0 + 8;
        const float *res0 = nullptr, *res1 = nullptr;
        if (MODE == 1) {
            int b0i = gr0 >> 12, t0 = gr0 & 4095;
            int b1i = gr1 >> 12, t1 = gr1 & 4095;
            res0 = (b0i < 4) ? (e0 + ((size_t)(b0i * SEQ + t0)) * DMODEL)
                             : (e1 + ((size_t)((b0i - 4) * SEQ + t0)) * DMODEL);
            res1 = (b1i < 4) ? (e0 + ((size_t)(b1i * SEQ + t1)) * DMODEL)
                             : (e1 + ((size_t)((b1i - 4) * SEQ + t1)) * DMODEL);
        }
        #pragma unroll
        for (int ni = 0; ni < 4; ni++) {
            int gc = bn + wn * 32 + ni * 8 + 2 * tq;
            if (gc >= N) continue;
            float v0 = acc[mi][ni][0], v1 = acc[mi][ni][1];
            float v2 = acc[mi][ni][2], v3 = acc[mi][ni][3];
            if (MODE == 0) {
                *(float2*)(C + (size_t)gr0 * N + gc) = make_float2(v0, v1);
                *(float2*)(C + (size_t)gr1 * N + gc) = make_float2(v2, v3);
            }
            if (MODE == 1) {
                v0 += res0[gc]; v1 += res0[gc + 1];
                v2 += res1[gc]; v3 += res1[gc + 1];
                *(float2*)(C + (size_t)gr0 * N + gc) = make_float2(v0, v1);
                *(float2*)(C + (size_t)gr1 * N + gc) = make_float2(v2, v3);
                *(__half2*)(g_sph + (size_t)gr0 * DMODEL + gc) = __floats2half2_rn(v0, v1);
                *(__half2*)(g_sph + (size_t)gr1 * DMODEL + gc) = __floats2half2_rn(v2, v3);
            }
            if (MODE == 2) {
                float bx = e0[gc], by = e0[gc + 1];
                v0 = siluf(v0 + bx); v1 = siluf(v1 + by);
                v2 = siluf(v2 + bx); v3 = siluf(v3 + by);
                *(__half2*)(g_hmh + (size_t)gr0 * DMODEL + gc) = __floats2half2_rn(v0, v1);
                *(__half2*)(g_hmh + (size_t)gr1 * DMODEL + gc) = __floats2half2_rn(v2, v3);
            }
            if (MODE == 3) {
                float bx = e0[gc], by = e0[gc + 1];
                const float* s0 = g_sp + (size_t)gr0 * DMODEL + gc;
                const float* s1 = g_sp + (size_t)gr1 * DMODEL + gc;
                v0 += bx + s0[0]; v1 += by + s0[1];
                v2 += bx + s1[0]; v3 += by + s1[1];
                *(float2*)(C + (size_t)gr0 * N + gc) = make_float2(v0, v1);
                *(float2*)(C + (size_t)gr1 * N + gc) = make_float2(v2, v3);
            }
        }
    }
}

// ---------------- launch ------------------------------------------------------
extern "C" void kernel_launch(void* const* d_in, const int* in_sizes, int n_in,
                              void* d_out, int out_size)
{
    const float* x0      = (const float*)d_in[0];
    const float* x1      = (const float*)d_in[1];
    const float* nsw     = (const float*)d_in[2];
    const float* nsb     = (const float*)d_in[3];
    const float* W_in    = (const float*)d_in[4];
    const float* conv_w  = (const float*)d_in[5];
    const float* conv_b  = (const float*)d_in[6];
    const float* dt_bias = (const float*)d_in[7];
    const float* A_log   = (const float*)d_in[8];
    const float* Dp      = (const float*)d_in[9];
    const float* rms_w   = (const float*)d_in[10];
    const float* W_out   = (const float*)d_in[11];
    const float* w1      = (const float*)d_in[12];
    const float* b1      = (const float*)d_in[13];
    const float* w2      = (const float*)d_in[14];
    const float* b2      = (const float*)d_in[15];
    const float* ntw     = (const float*)d_in[16];
    const float* ntb     = (const float*)d_in[17];
    float* out = (float*)d_out;

    float *p_zx, *p_sp, *p_u;
    cudaGetSymbolAddress((void**)&p_zx, g_zx);
    cudaGetSymbolAddress((void**)&p_sp, g_sp);
    cudaGetSymbolAddress((void**)&p_u,  g_u);
    __half *p_xnh, *p_ynh, *p_hmh;
    __half *p_Winh, *p_Winl, *p_Wouth, *p_w1h, *p_w2h;
    cudaGetSymbolAddress((void**)&p_xnh, g_xnh);
    cudaGetSymbolAddress((void**)&p_ynh, g_ynh);
    cudaGetSymbolAddress((void**)&p_hmh, g_hmh);
    cudaGetSymbolAddress((void**)&p_Winh,  g_Winh);
    cudaGetSymbolAddress((void**)&p_Winl,  g_Winl);
    cudaGetSymbolAddress((void**)&p_Wouth, g_Wouth);
    cudaGetSymbolAddress((void**)&p_w1h,   g_w1h);
    cudaGetSymbolAddress((void**)&p_w2h,   g_w2h);

    const int SM22 = 2 * 3 * MATB;   // 61440 (NPROD=2, NST=2)
    const int SM13 = 3 * 2 * MATB;   // 61440 (NPROD=1, NST=3)
    cudaFuncSetAttribute((const void*)gemm_mma<0, 2, 2>, cudaFuncAttributeMaxDynamicSharedMemorySize, SM22);
    cudaFuncSetAttribute((const void*)gemm_mma<1, 1, 3>, cudaFuncAttributeMaxDynamicSharedMemorySize, SM13);
    cudaFuncSetAttribute((const void*)gemm_mma<2, 1, 3>, cudaFuncAttributeMaxDynamicSharedMemorySize, SM13);
    cudaFuncSetAttribute((const void*)gemm_mma<3, 1, 3>, cudaFuncAttributeMaxDynamicSharedMemorySize, SM13);
    cudaFuncSetAttribute((const void*)scan_seg_kernel, cudaFuncAttributeMaxDynamicSharedMemorySize, SA_BYTES);
    cudaFuncSetAttribute((const void*)correct_kernel,  cudaFuncAttributeMaxDynamicSharedMemorySize, SC_BYTES);

    // #1: fused LayerNorm (warp/row) + weight convert
    pre_kernel<<<PRE_LN_BLKS + PRE_W_BLKS, 256>>>(x0, x1, nsw, nsb, W_in, W_out, w1, w2);

    // #2: in-proj GEMM (2-product, 2-stage): zxbcdt = xn @ W_in^T
    gemm_mma<0, 2, 2><<<dim3((DPROJ + 127) / 128, MTOT / 128), 256, SM22>>>(
        p_xnh, p_Winh, p_Winl, p_zx, DPROJ, DMODEL, nullptr, nullptr);

    // #3: depthwise conv + SiLU -> fp16
    conv_kernel<<<((MTOT / 4) * CONVDIM + 255) / 256, 256>>>(conv_w, conv_b);

    // #4: pass A — chunked-SSD segmented scans, 2 CTAs/SM  [ncu captures this]
    scan_seg_kernel<<<NSCANBLK, 256, SA_BYTES>>>(dt_bias, A_log, Dp);

    // #5: pass B — combine segment states
    combine_kernel<<<64, 256>>>();

    // #6: pass C — cross-segment correction via tensor cores
    correct_kernel<<<NSCANBLK, 256, SC_BYTES>>>();

    // #7: gate + RMSNorm (warp/row) -> fp16
    gate_rms_kernel<<<MTOT / 8, 256>>>(rms_w);

    // #8: out-proj GEMM (1-product) + residual -> g_sp/g_sph
    gemm_mma<1, 1, 3><<<dim3(2, MTOT / 128), 256, SM13>>>(
        p_ynh, p_Wouth, nullptr, p_sp, DMODEL, DINNER, x0, x1);

    // #9: MLP layer 1 (1-product, cross-concat gather) + SiLU -> g_hmh
    gemm_mma<2, 1, 3><<<dim3(2, MTOT / 128), 256, SM13>>>(
        nullptr, p_w1h, nullptr, nullptr, DMODEL, DINNER, b1, nullptr);

    // #10: MLP layer 2 (1-product) + bias + g_sp residual -> g_u
    gemm_mma<3, 1, 3><<<dim3(2, MTOT / 128), 256, SM13>>>(
        p_hmh, p_w2h, nullptr, p_u, DMODEL, DMODEL, b2, nullptr);

    // #11: final LayerNorm (warp/row) -> d_out
    ln_t_kernel<<<MTOT / 8, 256>>>(ntw, ntb, out);

    (void)in_sizes; (void)n_in; (void)out_size;
}